// round 2
// baseline (speedup 1.0000x reference)
#include <cuda_runtime.h>
#include <math.h>

#define BATCH   2
#define TSEQ    2048
#define DMODEL  1024
#define NHEADS  16
#define HDIM    64
#define BT      (BATCH*TSEQ)   /* 4096 */

// ---------------- scratch (static device arrays; no allocation) ----------------
__device__ float g_rope[TSEQ*HDIM];
__device__ float g_M[HDIM*HDIM];
__device__ float g_Wvp[DMODEL*DMODEL];
__device__ float g_q[BATCH*NHEADS*TSEQ*HDIM];
__device__ float g_k[BATCH*NHEADS*TSEQ*HDIM];
__device__ float g_v[BATCH*NHEADS*TSEQ*HDIM];
__device__ float g_attn[(size_t)BT*DMODEL];

// ---------------- rope: rope[s,d] = cos/sin(s * invf) ----------------
__global__ void rope_kernel() {
    int s = blockIdx.x;
    int d = threadIdx.x;           // 0..63
    int j = d & 31;
    double invf = exp(-log(10000.0) * (double)j / 32.0);
    double ang  = (double)s * invf;
    float v = (d < 32) ? (float)cos(ang) : (float)sin(ang);
    g_rope[s*HDIM + d] = v;
}

// ---------------- M = rope^T @ rope  (64x64) ----------------
__global__ void gram_kernel() {
    int d = blockIdx.x;
    int e = threadIdx.x;
    double acc = 0.0;
    for (int s = 0; s < TSEQ; s++)
        acc += (double)g_rope[s*HDIM + d] * (double)g_rope[s*HDIM + e];
    g_M[d*HDIM + e] = (float)acc;
}

// ---------------- Wvp = Wv @ blockdiag(M) ----------------
__global__ __launch_bounds__(256) void fold_kernel(const float* __restrict__ Wv) {
    __shared__ float Ms[HDIM*HDIM];
    __shared__ float wrow[DMODEL];
    int i = blockIdx.x;
    for (int t = threadIdx.x; t < HDIM*HDIM; t += blockDim.x) Ms[t] = g_M[t];
    for (int t = threadIdx.x; t < DMODEL;    t += blockDim.x) wrow[t] = Wv[(size_t)i*DMODEL + t];
    __syncthreads();
    for (int c = threadIdx.x; c < DMODEL; c += blockDim.x) {
        int h = c >> 6, e = c & 63;
        float acc = 0.f;
        #pragma unroll 8
        for (int d = 0; d < HDIM; d++)
            acc = fmaf(wrow[h*64 + d], Ms[d*64 + e], acc);
        g_Wvp[(size_t)i*DMODEL + c] = acc;
    }
}

// ---------------- SGEMM: C(4096x1024) = A(4096x1024) @ B(1024x1024) ----------------
// MODE 0: write into split-head layout (B,H,T,hd), no bias.
// MODE 1: plain row-major + bias.
template<int MODE>
__global__ __launch_bounds__(256) void sgemm_kernel(const float* __restrict__ A,
                                                    const float* __restrict__ B,
                                                    const float* __restrict__ bias,
                                                    float* __restrict__ OUT)
{
    const int K = DMODEL, N = DMODEL;
    __shared__ float As[2][8][128];   // [k][m] transposed
    __shared__ float Bs[2][8][128];   // [k][n]

    int tid = threadIdx.x;
    int br = blockIdx.y, bc = blockIdx.x;
    int tr = tid >> 4, tc = tid & 15;

    const float* Ab = A + (size_t)br*128*K;
    const float* Bb = B + (size_t)bc*128;

    int arow = tid >> 1;            // 0..127
    int akc  = (tid & 1) * 4;       // 0 or 4
    int brow = tid >> 5;            // 0..7
    int bcol = (tid & 31) * 4;      // 0..124

    float4 ra = *(const float4*)(Ab + (size_t)arow*K + akc);
    float4 rb = *(const float4*)(Bb + (size_t)brow*N + bcol);
    As[0][akc+0][arow] = ra.x; As[0][akc+1][arow] = ra.y;
    As[0][akc+2][arow] = ra.z; As[0][akc+3][arow] = ra.w;
    *(float4*)&Bs[0][brow][bcol] = rb;
    __syncthreads();

    float acc[8][8];
    #pragma unroll
    for (int i = 0; i < 8; i++)
        #pragma unroll
        for (int j = 0; j < 8; j++) acc[i][j] = 0.f;

    const int KT = K / 8;
    for (int kt = 0; kt < KT; kt++) {
        int cur = kt & 1;
        if (kt + 1 < KT) {
            ra = *(const float4*)(Ab + (size_t)arow*K + (kt+1)*8 + akc);
            rb = *(const float4*)(Bb + (size_t)((kt+1)*8 + brow)*N + bcol);
        }
        #pragma unroll
        for (int kk = 0; kk < 8; kk++) {
            float a[8], b[8];
            *(float4*)&a[0] = *(const float4*)&As[cur][kk][tr*4];
            *(float4*)&a[4] = *(const float4*)&As[cur][kk][64 + tr*4];
            *(float4*)&b[0] = *(const float4*)&Bs[cur][kk][tc*4];
            *(float4*)&b[4] = *(const float4*)&Bs[cur][kk][64 + tc*4];
            #pragma unroll
            for (int i = 0; i < 8; i++)
                #pragma unroll
                for (int j = 0; j < 8; j++)
                    acc[i][j] = fmaf(a[i], b[j], acc[i][j]);
        }
        if (kt + 1 < KT) {
            int nxt = cur ^ 1;
            As[nxt][akc+0][arow] = ra.x; As[nxt][akc+1][arow] = ra.y;
            As[nxt][akc+2][arow] = ra.z; As[nxt][akc+3][arow] = ra.w;
            *(float4*)&Bs[nxt][brow][bcol] = rb;
        }
        __syncthreads();
    }

    #pragma unroll
    for (int i = 0; i < 8; i++) {
        int row = br*128 + ((i < 4) ? tr*4 + i : 64 + tr*4 + (i - 4));
        #pragma unroll
        for (int jg = 0; jg < 2; jg++) {
            int col0 = bc*128 + (jg == 0 ? tc*4 : 64 + tc*4);
            float4 v;
            v.x = acc[i][jg*4+0]; v.y = acc[i][jg*4+1];
            v.z = acc[i][jg*4+2]; v.w = acc[i][jg*4+3];
            if (MODE == 1) {
                float4 bb = *(const float4*)&bias[col0];
                v.x += bb.x; v.y += bb.y; v.z += bb.z; v.w += bb.w;
                *(float4*)&OUT[(size_t)row*N + col0] = v;
            } else {
                int b = row >> 11, t = row & 2047;
                int h = col0 >> 6, d = col0 & 63;
                size_t o = (((size_t)(b*NHEADS + h))*TSEQ + t)*HDIM + d;
                *(float4*)&OUT[o] = v;
            }
        }
    }
}

// ---------------- flash attention (fp32, 64x64 tiles, online softmax) ----------------
__global__ __launch_bounds__(256) void flash_kernel(const float* __restrict__ q,
                                                    const float* __restrict__ k,
                                                    const float* __restrict__ v,
                                                    float* __restrict__ out)
{
    extern __shared__ float sm[];
    float* Qt = sm;                 // [d][row]  64x68, pre-scaled by 0.125
    float* Kt = Qt + 64*68;         // [d][key]  64x68
    float* Vs = Kt + 64*68;         // [key][d]  64x68
    float* Ps = Vs + 64*68;         // [row][key] 64x68

    const int bh = blockIdx.y;                 // b*NHEADS + h
    const int q0 = blockIdx.x * 64;
    const float* qb = q + ((size_t)bh*TSEQ + q0)*HDIM;
    const float* kb = k + (size_t)bh*TSEQ*HDIM;
    const float* vb = v + (size_t)bh*TSEQ*HDIM;

    int tid = threadIdx.x;
    int ty = tid >> 4, tx = tid & 15;

    // load Q transposed + scaled
    {
        int r  = tid >> 2;          // 0..63
        int c0 = (tid & 3) * 16;    // 0,16,32,48
        #pragma unroll
        for (int u = 0; u < 4; u++) {
            float4 t = *(const float4*)(qb + (size_t)r*HDIM + c0 + u*4);
            Qt[(c0+u*4+0)*68 + r] = t.x * 0.125f;
            Qt[(c0+u*4+1)*68 + r] = t.y * 0.125f;
            Qt[(c0+u*4+2)*68 + r] = t.z * 0.125f;
            Qt[(c0+u*4+3)*68 + r] = t.w * 0.125f;
        }
    }

    float O[4][4];
    #pragma unroll
    for (int i = 0; i < 4; i++)
        #pragma unroll
        for (int j = 0; j < 4; j++) O[i][j] = 0.f;
    float mrow[4] = {-INFINITY, -INFINITY, -INFINITY, -INFINITY};
    float lrow[4] = {0.f, 0.f, 0.f, 0.f};

    __syncthreads();

    for (int kblk = 0; kblk < TSEQ/64; kblk++) {
        // load K (transposed) and V tiles
        {
            int r  = tid >> 2;
            int c0 = (tid & 3) * 16;
            const float* kp = kb + (size_t)(kblk*64 + r)*HDIM;
            const float* vp = vb + (size_t)(kblk*64 + r)*HDIM;
            #pragma unroll
            for (int u = 0; u < 4; u++) {
                float4 tk = *(const float4*)(kp + c0 + u*4);
                Kt[(c0+u*4+0)*68 + r] = tk.x;
                Kt[(c0+u*4+1)*68 + r] = tk.y;
                Kt[(c0+u*4+2)*68 + r] = tk.z;
                Kt[(c0+u*4+3)*68 + r] = tk.w;
                float4 tv = *(const float4*)(vp + c0 + u*4);
                *(float4*)&Vs[r*68 + c0 + u*4] = tv;
            }
        }
        __syncthreads();

        // S = (Q*scale) @ K^T
        float S[4][4];
        #pragma unroll
        for (int i = 0; i < 4; i++)
            #pragma unroll
            for (int j = 0; j < 4; j++) S[i][j] = 0.f;
        #pragma unroll 8
        for (int d = 0; d < 64; d++) {
            float4 a = *(const float4*)&Qt[d*68 + ty*4];
            float4 b = *(const float4*)&Kt[d*68 + tx*4];
            S[0][0] = fmaf(a.x, b.x, S[0][0]); S[0][1] = fmaf(a.x, b.y, S[0][1]);
            S[0][2] = fmaf(a.x, b.z, S[0][2]); S[0][3] = fmaf(a.x, b.w, S[0][3]);
            S[1][0] = fmaf(a.y, b.x, S[1][0]); S[1][1] = fmaf(a.y, b.y, S[1][1]);
            S[1][2] = fmaf(a.y, b.z, S[1][2]); S[1][3] = fmaf(a.y, b.w, S[1][3]);
            S[2][0] = fmaf(a.z, b.x, S[2][0]); S[2][1] = fmaf(a.z, b.y, S[2][1]);
            S[2][2] = fmaf(a.z, b.z, S[2][2]); S[2][3] = fmaf(a.z, b.w, S[2][3]);
            S[3][0] = fmaf(a.w, b.x, S[3][0]); S[3][1] = fmaf(a.w, b.y, S[3][1]);
            S[3][2] = fmaf(a.w, b.z, S[3][2]); S[3][3] = fmaf(a.w, b.w, S[3][3]);
        }

        // online softmax update
        #pragma unroll
        for (int i = 0; i < 4; i++) {
            float rm = fmaxf(fmaxf(S[i][0], S[i][1]), fmaxf(S[i][2], S[i][3]));
            #pragma unroll
            for (int w = 1; w < 16; w <<= 1)
                rm = fmaxf(rm, __shfl_xor_sync(0xffffffffu, rm, w));
            float mn   = fmaxf(mrow[i], rm);
            float corr = __expf(mrow[i] - mn);
            mrow[i] = mn;
            lrow[i] *= corr;
            #pragma unroll
            for (int j = 0; j < 4; j++) O[i][j] *= corr;
            float4 p;
            p.x = __expf(S[i][0] - mn); p.y = __expf(S[i][1] - mn);
            p.z = __expf(S[i][2] - mn); p.w = __expf(S[i][3] - mn);
            float rs = p.x + p.y + p.z + p.w;
            *(float4*)&Ps[(ty*4+i)*68 + tx*4] = p;
            #pragma unroll
            for (int w = 1; w < 16; w <<= 1)
                rs += __shfl_xor_sync(0xffffffffu, rs, w);
            lrow[i] += rs;
        }
        __syncthreads();

        // O += P @ V
        #pragma unroll 8
        for (int kk = 0; kk < 64; kk++) {
            float4 vv = *(const float4*)&Vs[kk*68 + tx*4];
            #pragma unroll
            for (int i = 0; i < 4; i++) {
                float p = Ps[(ty*4+i)*68 + kk];
                O[i][0] = fmaf(p, vv.x, O[i][0]);
                O[i][1] = fmaf(p, vv.y, O[i][1]);
                O[i][2] = fmaf(p, vv.z, O[i][2]);
                O[i][3] = fmaf(p, vv.w, O[i][3]);
            }
        }
        __syncthreads();
    }

    // normalize + write (B,T,D) layout for the final projection GEMM
    int b = bh >> 4, h = bh & 15;
    #pragma unroll
    for (int i = 0; i < 4; i++) {
        int t = q0 + ty*4 + i;
        float inv = 1.f / lrow[i];
        float4 r;
        r.x = O[i][0]*inv; r.y = O[i][1]*inv; r.z = O[i][2]*inv; r.w = O[i][3]*inv;
        *(float4*)&g_attn[((size_t)(b*TSEQ + t))*DMODEL + h*64 + tx*4] = r;
    }
    (void)out;
}

// ---------------- launch ----------------
extern "C" void kernel_launch(void* const* d_in, const int* in_sizes, int n_in,
                              void* d_out, int out_size)
{
    const float* x  = (const float*)d_in[0];
    const float* Wq = (const float*)d_in[1];
    const float* Wk = (const float*)d_in[2];
    const float* Wv = (const float*)d_in[3];
    const float* Wo = (const float*)d_in[4];
    const float* bo = (const float*)d_in[5];
    float* out = (float*)d_out;

    float *q, *k, *v, *attn, *wvp;
    cudaGetSymbolAddress((void**)&q,    g_q);
    cudaGetSymbolAddress((void**)&k,    g_k);
    cudaGetSymbolAddress((void**)&v,    g_v);
    cudaGetSymbolAddress((void**)&attn, g_attn);
    cudaGetSymbolAddress((void**)&wvp,  g_Wvp);

    rope_kernel<<<TSEQ, HDIM>>>();
    gram_kernel<<<HDIM, HDIM>>>();
    fold_kernel<<<DMODEL, 256>>>(Wv);

    dim3 gg(DMODEL/128, BT/128), bb(256);
    sgemm_kernel<0><<<gg, bb>>>(x, Wq,  nullptr, q);
    sgemm_kernel<0><<<gg, bb>>>(x, Wk,  nullptr, k);
    sgemm_kernel<0><<<gg, bb>>>(x, wvp, nullptr, v);

    cudaFuncSetAttribute(flash_kernel, cudaFuncAttributeMaxDynamicSharedMemorySize, 4*64*68*4);
    flash_kernel<<<dim3(TSEQ/64, BATCH*NHEADS), 256, 4*64*68*4>>>(q, k, v, attn);

    sgemm_kernel<1><<<gg, bb>>>(attn, Wo, bo, out);

    (void)in_sizes; (void)n_in; (void)out_size;
}

// round 4
// speedup vs baseline: 1.2045x; 1.2045x over previous
#include <cuda_runtime.h>
#include <cuda_bf16.h>
#include <math.h>
#include <stdint.h>

#define BATCH   2
#define TSEQ    2048
#define DMODEL  1024
#define NHEADS  16
#define HDIM    64
#define BT      (BATCH*TSEQ)   /* 4096 */

// ---------------- scratch (static device arrays; no allocation) ----------------
__device__ float g_rope[TSEQ*HDIM];
__device__ float g_M[HDIM*HDIM];
__device__ float g_Wvp[DMODEL*DMODEL];
__device__ float g_q[BATCH*NHEADS*TSEQ*HDIM];
__device__ float g_k[BATCH*NHEADS*TSEQ*HDIM];
__device__ float g_v[BATCH*NHEADS*TSEQ*HDIM];
__device__ float g_attn[(size_t)BT*DMODEL];
__device__ __nv_bfloat16 g_xhi[(size_t)BT*DMODEL];
__device__ __nv_bfloat16 g_xlo[(size_t)BT*DMODEL];
__device__ __nv_bfloat16 g_whi[4*(size_t)DMODEL*DMODEL];   // transposed weights [N][K]
__device__ __nv_bfloat16 g_wlo[4*(size_t)DMODEL*DMODEL];
__device__ __nv_bfloat16 g_ahi[(size_t)BT*DMODEL];
__device__ __nv_bfloat16 g_alo[(size_t)BT*DMODEL];

// ---------------- PTX helpers (base ISA only: cp.async / ldmatrix / mma.sync) ---
__device__ __forceinline__ uint32_t smem_u32(const void* p) {
    uint32_t a;
    asm("{ .reg .u64 t; cvta.to.shared.u64 t, %1; cvt.u32.u64 %0, t; }" : "=r"(a) : "l"(p));
    return a;
}
#define CP16(dst, src) asm volatile("cp.async.cg.shared.global [%0], [%1], 16;" :: "r"(dst), "l"(src))
#define CP_COMMIT()    asm volatile("cp.async.commit_group;" ::: "memory")
#define CP_WAIT1()     asm volatile("cp.async.wait_group 1;" ::: "memory")
#define CP_WAIT0()     asm volatile("cp.async.wait_group 0;" ::: "memory")
#define LDSM4(r, a) \
    asm volatile("ldmatrix.sync.aligned.m8n8.x4.shared.b16 {%0,%1,%2,%3}, [%4];" \
        : "=r"((r)[0]), "=r"((r)[1]), "=r"((r)[2]), "=r"((r)[3]) : "r"(a))
__device__ __forceinline__ void mma_bf16(float* c, const uint32_t* a, uint32_t b0, uint32_t b1) {
    asm volatile("mma.sync.aligned.m16n8k16.row.col.f32.bf16.bf16.f32 "
                 "{%0,%1,%2,%3}, {%4,%5,%6,%7}, {%8,%9}, {%0,%1,%2,%3};"
                 : "+f"(c[0]), "+f"(c[1]), "+f"(c[2]), "+f"(c[3])
                 : "r"(a[0]), "r"(a[1]), "r"(a[2]), "r"(a[3]), "r"(b0), "r"(b1));
}

// ---------------- rope / gram / fold ----------------
__global__ void rope_kernel() {
    int s = blockIdx.x, d = threadIdx.x;
    int j = d & 31;
    double invf = exp(-log(10000.0) * (double)j / 32.0);
    double ang  = (double)s * invf;
    g_rope[s*HDIM + d] = (d < 32) ? (float)cos(ang) : (float)sin(ang);
}
__global__ void gram_kernel() {
    int d = blockIdx.x, e = threadIdx.x;
    double acc = 0.0;
    for (int s = 0; s < TSEQ; s++)
        acc += (double)g_rope[s*HDIM + d] * (double)g_rope[s*HDIM + e];
    g_M[d*HDIM + e] = (float)acc;
}
__global__ __launch_bounds__(256) void fold_kernel(const float* __restrict__ Wv) {
    __shared__ float Ms[HDIM*HDIM];
    __shared__ float wrow[DMODEL];
    int i = blockIdx.x;
    for (int t = threadIdx.x; t < HDIM*HDIM; t += blockDim.x) Ms[t] = g_M[t];
    for (int t = threadIdx.x; t < DMODEL;    t += blockDim.x) wrow[t] = Wv[(size_t)i*DMODEL + t];
    __syncthreads();
    for (int c = threadIdx.x; c < DMODEL; c += blockDim.x) {
        int h = c >> 6, e = c & 63;
        float acc = 0.f;
        #pragma unroll 8
        for (int d = 0; d < HDIM; d++) acc = fmaf(wrow[h*64 + d], Ms[d*64 + e], acc);
        g_Wvp[(size_t)i*DMODEL + c] = acc;
    }
}

// ---------------- hi/lo bf16 split (elementwise) ----------------
__global__ __launch_bounds__(256) void split_kernel(const float* __restrict__ src,
                                                    __nv_bfloat16* __restrict__ hi,
                                                    __nv_bfloat16* __restrict__ lo, int n4) {
    int i = blockIdx.x*blockDim.x + threadIdx.x;
    if (i >= n4) return;
    float4 v = ((const float4*)src)[i];
    __nv_bfloat16 h0 = __float2bfloat16(v.x), h1 = __float2bfloat16(v.y);
    __nv_bfloat16 h2 = __float2bfloat16(v.z), h3 = __float2bfloat16(v.w);
    __nv_bfloat16 l0 = __float2bfloat16(v.x - __bfloat162float(h0));
    __nv_bfloat16 l1 = __float2bfloat16(v.y - __bfloat162float(h1));
    __nv_bfloat16 l2 = __float2bfloat16(v.z - __bfloat162float(h2));
    __nv_bfloat16 l3 = __float2bfloat16(v.w - __bfloat162float(h3));
    uint2 H, L;
    H.x = ((uint32_t)__bfloat16_as_ushort(h1) << 16) | __bfloat16_as_ushort(h0);
    H.y = ((uint32_t)__bfloat16_as_ushort(h3) << 16) | __bfloat16_as_ushort(h2);
    L.x = ((uint32_t)__bfloat16_as_ushort(l1) << 16) | __bfloat16_as_ushort(l0);
    L.y = ((uint32_t)__bfloat16_as_ushort(l3) << 16) | __bfloat16_as_ushort(l2);
    ((uint2*)hi)[i] = H;
    ((uint2*)lo)[i] = L;
}

// ---------------- transpose + split: W[K][N] -> T[N][K] hi/lo bf16 ----------------
__global__ void tsplit_kernel(const float* __restrict__ W,
                              __nv_bfloat16* __restrict__ hi,
                              __nv_bfloat16* __restrict__ lo) {
    __shared__ float t[32][33];
    int x0 = blockIdx.x*32, y0 = blockIdx.y*32;
    int tx = threadIdx.x, ty = threadIdx.y;
    #pragma unroll
    for (int j = 0; j < 32; j += 8)
        t[ty+j][tx] = W[(size_t)(y0+ty+j)*DMODEL + x0+tx];
    __syncthreads();
    #pragma unroll
    for (int j = 0; j < 32; j += 8) {
        float v = t[tx][ty+j];
        __nv_bfloat16 h = __float2bfloat16(v);
        size_t o = (size_t)(x0+ty+j)*DMODEL + y0+tx;
        hi[o] = h;
        lo[o] = __float2bfloat16(v - __bfloat162float(h));
    }
}

// ---------------- HMMA GEMM: C(4096x1024) = A @ W^T, bf16 hi/lo x3, fp32 accum ----
// A: [4096][1024] bf16 hi/lo (K-major rows). B: [1024(N)][1024(K)] bf16 hi/lo.
// Smem per stage: 4 tiles of 128 rows x 32 bf16, rows padded to 80B.
// MODE 0: write split-head (B,H,T,hd). MODE 1: row-major + bias.
#define ROWB     80
#define TILEB    (128*ROWB)      /* 10240 */
#define STAGEB   (4*TILEB)       /* 40960 */
#define SMEMB    (2*STAGEB)      /* 81920 */

template<int MODE>
__global__ __launch_bounds__(256) void hgemm_tc(const __nv_bfloat16* __restrict__ Ahi,
                                                const __nv_bfloat16* __restrict__ Alo,
                                                const __nv_bfloat16* __restrict__ Bhi,
                                                const __nv_bfloat16* __restrict__ Blo,
                                                const float* __restrict__ bias,
                                                float* __restrict__ OUT)
{
    extern __shared__ char smem[];
    const uint32_t smem_base = smem_u32(smem);
    const int tid  = threadIdx.x;
    const int lane = tid & 31;
    const int wid  = tid >> 5;
    const int wm   = wid & 3;         // 4 m-warps
    const int wn   = wid >> 2;        // 2 n-warps
    const int br   = blockIdx.y, bc = blockIdx.x;

    // global load mapping: thread -> (row, chunk), coalesced 64B per 4 lanes
    const int lrow  = tid >> 2;       // 0..63
    const int chunk = tid & 3;        // 0..3 (16B chunks of a 64B row)

    const __nv_bfloat16* A0h = Ahi + (size_t)(br*128 + lrow)*DMODEL + chunk*8;
    const __nv_bfloat16* A0l = Alo + (size_t)(br*128 + lrow)*DMODEL + chunk*8;
    const __nv_bfloat16* B0h = Bhi + (size_t)(bc*128 + lrow)*DMODEL + chunk*8;
    const __nv_bfloat16* B0l = Blo + (size_t)(bc*128 + lrow)*DMODEL + chunk*8;
    const size_t rstep = (size_t)64*DMODEL;   // +64 rows

#define ISSUE(s_, buf_) do { \
    uint32_t sb = smem_base + (buf_)*STAGEB; \
    uint32_t d0 = sb + lrow*ROWB + chunk*16; \
    size_t  go = (size_t)(s_)*32; \
    CP16(d0,                    A0h + go); \
    CP16(d0 + TILEB,            A0l + go); \
    CP16(d0 + 2*TILEB,          B0h + go); \
    CP16(d0 + 3*TILEB,          B0l + go); \
    uint32_t d1 = d0 + 64*ROWB; \
    CP16(d1,                    A0h + go + rstep); \
    CP16(d1 + TILEB,            A0l + go + rstep); \
    CP16(d1 + 2*TILEB,          B0h + go + rstep); \
    CP16(d1 + 3*TILEB,          B0l + go + rstep); \
} while (0)

    float acc[2][8][4];
    #pragma unroll
    for (int i = 0; i < 2; i++)
        #pragma unroll
        for (int j = 0; j < 8; j++)
            #pragma unroll
            for (int e = 0; e < 4; e++) acc[i][j][e] = 0.f;

    const int m0 = wm*32, n0 = wn*64;
    const int lr = lane & 15, lh = lane >> 4;

    ISSUE(0, 0); CP_COMMIT();

    for (int s = 0; s < 32; s++) {
        if (s + 1 < 32) { ISSUE(s + 1, (s + 1) & 1); CP_COMMIT(); CP_WAIT1(); }
        else            { CP_WAIT0(); }
        __syncthreads();

        const uint32_t As = smem_base + (s & 1)*STAGEB;
        const uint32_t Bs = As + 2*TILEB;
        #pragma unroll
        for (int k = 0; k < 2; k++) {
            const uint32_t koff = k*32 + lh*16;
            uint32_t ahi[2][4], axx[2][4], bq[4][4];
            #pragma unroll
            for (int mi = 0; mi < 2; mi++)
                LDSM4(ahi[mi], As + (m0 + mi*16 + lr)*ROWB + koff);
            #pragma unroll
            for (int jg = 0; jg < 4; jg++)
                LDSM4(bq[jg], Bs + (n0 + jg*16 + lr)*ROWB + koff);
            // hi * hi
            #pragma unroll
            for (int mi = 0; mi < 2; mi++)
                #pragma unroll
                for (int j = 0; j < 8; j++)
                    mma_bf16(acc[mi][j], ahi[mi], bq[j>>1][j&1], bq[j>>1][(j&1)+2]);
            // lo * hi
            #pragma unroll
            for (int mi = 0; mi < 2; mi++)
                LDSM4(axx[mi], As + TILEB + (m0 + mi*16 + lr)*ROWB + koff);
            #pragma unroll
            for (int mi = 0; mi < 2; mi++)
                #pragma unroll
                for (int j = 0; j < 8; j++)
                    mma_bf16(acc[mi][j], axx[mi], bq[j>>1][j&1], bq[j>>1][(j&1)+2]);
            // hi * lo
            #pragma unroll
            for (int jg = 0; jg < 4; jg++)
                LDSM4(bq[jg], Bs + TILEB + (n0 + jg*16 + lr)*ROWB + koff);
            #pragma unroll
            for (int mi = 0; mi < 2; mi++)
                #pragma unroll
                for (int j = 0; j < 8; j++)
                    mma_bf16(acc[mi][j], ahi[mi], bq[j>>1][j&1], bq[j>>1][(j&1)+2]);
        }
        __syncthreads();
    }
#undef ISSUE

    // epilogue: fragment (g, t) owns rows (g, g+8), cols t*2, t*2+1 per n-frag
    const int g = lane >> 2, t = lane & 3;
    #pragma unroll
    for (int mi = 0; mi < 2; mi++) {
        #pragma unroll
        for (int rr = 0; rr < 2; rr++) {
            const int row = br*128 + m0 + mi*16 + rr*8 + g;
            #pragma unroll
            for (int j = 0; j < 8; j++) {
                const int col = bc*128 + n0 + j*8 + t*2;
                float2 v;
                v.x = acc[mi][j][rr*2 + 0];
                v.y = acc[mi][j][rr*2 + 1];
                if (MODE == 1) {
                    v.x += bias[col]; v.y += bias[col + 1];
                    *(float2*)&OUT[(size_t)row*DMODEL + col] = v;
                } else {
                    int bi = row >> 11, tt = row & 2047;
                    int h = col >> 6, dd = col & 63;
                    *(float2*)&OUT[(((size_t)(bi*NHEADS + h))*TSEQ + tt)*HDIM + dd] = v;
                }
            }
        }
    }
}

// ---------------- flash attention (fp32, 64x64 tiles, online softmax) ----------------
__global__ __launch_bounds__(256) void flash_kernel(const float* __restrict__ q,
                                                    const float* __restrict__ k,
                                                    const float* __restrict__ v,
                                                    float* __restrict__ out)
{
    extern __shared__ float sm[];
    float* Qt = sm;                 // [d][row]  64x68
    float* Kt = Qt + 64*68;         // [d][key]  64x68
    float* Vs = Kt + 64*68;         // [key][d]  64x68
    float* Ps = Vs + 64*68;         // [row][key] 64x68

    const int bh = blockIdx.y;
    const int q0 = blockIdx.x * 64;
    const float* qb = q + ((size_t)bh*TSEQ + q0)*HDIM;
    const float* kb = k + (size_t)bh*TSEQ*HDIM;
    const float* vb = v + (size_t)bh*TSEQ*HDIM;

    int tid = threadIdx.x;
    int ty = tid >> 4, tx = tid & 15;

    {
        int r  = tid >> 2;
        int c0 = (tid & 3) * 16;
        #pragma unroll
        for (int u = 0; u < 4; u++) {
            float4 t = *(const float4*)(qb + (size_t)r*HDIM + c0 + u*4);
            Qt[(c0+u*4+0)*68 + r] = t.x * 0.125f;
            Qt[(c0+u*4+1)*68 + r] = t.y * 0.125f;
            Qt[(c0+u*4+2)*68 + r] = t.z * 0.125f;
            Qt[(c0+u*4+3)*68 + r] = t.w * 0.125f;
        }
    }

    float O[4][4];
    #pragma unroll
    for (int i = 0; i < 4; i++)
        #pragma unroll
        for (int j = 0; j < 4; j++) O[i][j] = 0.f;
    float mrow[4] = {-INFINITY, -INFINITY, -INFINITY, -INFINITY};
    float lrow[4] = {0.f, 0.f, 0.f, 0.f};

    __syncthreads();

    for (int kblk = 0; kblk < TSEQ/64; kblk++) {
        {
            int r  = tid >> 2;
            int c0 = (tid & 3) * 16;
            const float* kp = kb + (size_t)(kblk*64 + r)*HDIM;
            const float* vp = vb + (size_t)(kblk*64 + r)*HDIM;
            #pragma unroll
            for (int u = 0; u < 4; u++) {
                float4 tk = *(const float4*)(kp + c0 + u*4);
                Kt[(c0+u*4+0)*68 + r] = tk.x;
                Kt[(c0+u*4+1)*68 + r] = tk.y;
                Kt[(c0+u*4+2)*68 + r] = tk.z;
                Kt[(c0+u*4+3)*68 + r] = tk.w;
                float4 tv = *(const float4*)(vp + c0 + u*4);
                *(float4*)&Vs[r*68 + c0 + u*4] = tv;
            }
        }
        __syncthreads();

        float S[4][4];
        #pragma unroll
        for (int i = 0; i < 4; i++)
            #pragma unroll
            for (int j = 0; j < 4; j++) S[i][j] = 0.f;
        #pragma unroll 8
        for (int d = 0; d < 64; d++) {
            float4 a = *(const float4*)&Qt[d*68 + ty*4];
            float4 b = *(const float4*)&Kt[d*68 + tx*4];
            S[0][0] = fmaf(a.x, b.x, S[0][0]); S[0][1] = fmaf(a.x, b.y, S[0][1]);
            S[0][2] = fmaf(a.x, b.z, S[0][2]); S[0][3] = fmaf(a.x, b.w, S[0][3]);
            S[1][0] = fmaf(a.y, b.x, S[1][0]); S[1][1] = fmaf(a.y, b.y, S[1][1]);
            S[1][2] = fmaf(a.y, b.z, S[1][2]); S[1][3] = fmaf(a.y, b.w, S[1][3]);
            S[2][0] = fmaf(a.z, b.x, S[2][0]); S[2][1] = fmaf(a.z, b.y, S[2][1]);
            S[2][2] = fmaf(a.z, b.z, S[2][2]); S[2][3] = fmaf(a.z, b.w, S[2][3]);
            S[3][0] = fmaf(a.w, b.x, S[3][0]); S[3][1] = fmaf(a.w, b.y, S[3][1]);
            S[3][2] = fmaf(a.w, b.z, S[3][2]); S[3][3] = fmaf(a.w, b.w, S[3][3]);
        }

        #pragma unroll
        for (int i = 0; i < 4; i++) {
            float rm = fmaxf(fmaxf(S[i][0], S[i][1]), fmaxf(S[i][2], S[i][3]));
            #pragma unroll
            for (int w = 1; w < 16; w <<= 1)
                rm = fmaxf(rm, __shfl_xor_sync(0xffffffffu, rm, w));
            float mn   = fmaxf(mrow[i], rm);
            float corr = __expf(mrow[i] - mn);
            mrow[i] = mn;
            lrow[i] *= corr;
            #pragma unroll
            for (int j = 0; j < 4; j++) O[i][j] *= corr;
            float4 p;
            p.x = __expf(S[i][0] - mn); p.y = __expf(S[i][1] - mn);
            p.z = __expf(S[i][2] - mn); p.w = __expf(S[i][3] - mn);
            float rs = p.x + p.y + p.z + p.w;
            *(float4*)&Ps[(ty*4+i)*68 + tx*4] = p;
            #pragma unroll
            for (int w = 1; w < 16; w <<= 1)
                rs += __shfl_xor_sync(0xffffffffu, rs, w);
            lrow[i] += rs;
        }
        __syncthreads();

        #pragma unroll 8
        for (int kk = 0; kk < 64; kk++) {
            float4 vv = *(const float4*)&Vs[kk*68 + tx*4];
            #pragma unroll
            for (int i = 0; i < 4; i++) {
                float p = Ps[(ty*4+i)*68 + kk];
                O[i][0] = fmaf(p, vv.x, O[i][0]);
                O[i][1] = fmaf(p, vv.y, O[i][1]);
                O[i][2] = fmaf(p, vv.z, O[i][2]);
                O[i][3] = fmaf(p, vv.w, O[i][3]);
            }
        }
        __syncthreads();
    }

    int b = bh >> 4, h = bh & 15;
    #pragma unroll
    for (int i = 0; i < 4; i++) {
        int t = q0 + ty*4 + i;
        float inv = 1.f / lrow[i];
        float4 r;
        r.x = O[i][0]*inv; r.y = O[i][1]*inv; r.z = O[i][2]*inv; r.w = O[i][3]*inv;
        *(float4*)&g_attn[((size_t)(b*TSEQ + t))*DMODEL + h*64 + tx*4] = r;
    }
    (void)out;
}

// ---------------- launch ----------------
extern "C" void kernel_launch(void* const* d_in, const int* in_sizes, int n_in,
                              void* d_out, int out_size)
{
    const float* x  = (const float*)d_in[0];
    const float* Wq = (const float*)d_in[1];
    const float* Wk = (const float*)d_in[2];
    const float* Wv = (const float*)d_in[3];
    const float* Wo = (const float*)d_in[4];
    const float* bo = (const float*)d_in[5];
    float* out = (float*)d_out;

    float *q, *k, *v, *attn, *wvp;
    cudaGetSymbolAddress((void**)&q,    g_q);
    cudaGetSymbolAddress((void**)&k,    g_k);
    cudaGetSymbolAddress((void**)&v,    g_v);
    cudaGetSymbolAddress((void**)&attn, g_attn);
    cudaGetSymbolAddress((void**)&wvp,  g_Wvp);
    __nv_bfloat16 *xhi, *xlo, *whi, *wlo, *ahi, *alo;
    cudaGetSymbolAddress((void**)&xhi, g_xhi);
    cudaGetSymbolAddress((void**)&xlo, g_xlo);
    cudaGetSymbolAddress((void**)&whi, g_whi);
    cudaGetSymbolAddress((void**)&wlo, g_wlo);
    cudaGetSymbolAddress((void**)&ahi, g_ahi);
    cudaGetSymbolAddress((void**)&alo, g_alo);

    const size_t WSZ = (size_t)DMODEL*DMODEL;

    rope_kernel<<<TSEQ, HDIM>>>();
    gram_kernel<<<HDIM, HDIM>>>();
    fold_kernel<<<DMODEL, 256>>>(Wv);

    split_kernel<<<(BT*DMODEL/4 + 255)/256, 256>>>(x, xhi, xlo, BT*DMODEL/4);
    dim3 tg(DMODEL/32, DMODEL/32), tb(32, 8);
    tsplit_kernel<<<tg, tb>>>(Wq,  whi + 0*WSZ, wlo + 0*WSZ);
    tsplit_kernel<<<tg, tb>>>(Wk,  whi + 1*WSZ, wlo + 1*WSZ);
    tsplit_kernel<<<tg, tb>>>(wvp, whi + 2*WSZ, wlo + 2*WSZ);
    tsplit_kernel<<<tg, tb>>>(Wo,  whi + 3*WSZ, wlo + 3*WSZ);

    cudaFuncSetAttribute(hgemm_tc<0>, cudaFuncAttributeMaxDynamicSharedMemorySize, SMEMB);
    cudaFuncSetAttribute(hgemm_tc<1>, cudaFuncAttributeMaxDynamicSharedMemorySize, SMEMB);

    dim3 gg(DMODEL/128, BT/128);   // (8, 32)
    hgemm_tc<0><<<gg, 256, SMEMB>>>(xhi, xlo, whi + 0*WSZ, wlo + 0*WSZ, nullptr, q);
    hgemm_tc<0><<<gg, 256, SMEMB>>>(xhi, xlo, whi + 1*WSZ, wlo + 1*WSZ, nullptr, k);
    hgemm_tc<0><<<gg, 256, SMEMB>>>(xhi, xlo, whi + 2*WSZ, wlo + 2*WSZ, nullptr, v);

    cudaFuncSetAttribute(flash_kernel, cudaFuncAttributeMaxDynamicSharedMemorySize, 4*64*68*4);
    flash_kernel<<<dim3(TSEQ/64, BATCH*NHEADS), 256, 4*64*68*4>>>(q, k, v, attn);

    split_kernel<<<(BT*DMODEL/4 + 255)/256, 256>>>(attn, ahi, alo, BT*DMODEL/4);
    hgemm_tc<1><<<gg, 256, SMEMB>>>(ahi, alo, whi + 3*WSZ, wlo + 3*WSZ, bo, out);

    (void)in_sizes; (void)n_in; (void)out_size;
}

// round 5
// speedup vs baseline: 2.0252x; 1.6814x over previous
#include <cuda_runtime.h>
#include <cuda_bf16.h>
#include <math.h>
#include <stdint.h>

#define BATCH   2
#define TSEQ    2048
#define DMODEL  1024
#define NHEADS  16
#define HDIM    64
#define BT      (BATCH*TSEQ)   /* 4096 */

// ---------------- scratch (static device arrays; no allocation) ----------------
__device__ float g_rope[TSEQ*HDIM];
__device__ float g_M[HDIM*HDIM];
__device__ float g_Wvp[DMODEL*DMODEL];
__device__ __nv_bfloat16 g_xhi[(size_t)BT*DMODEL];
__device__ __nv_bfloat16 g_xlo[(size_t)BT*DMODEL];
__device__ __nv_bfloat16 g_whi[4*(size_t)DMODEL*DMODEL];   // transposed weights [N][K]
__device__ __nv_bfloat16 g_wlo[4*(size_t)DMODEL*DMODEL];
__device__ __nv_bfloat16 g_qhi[BATCH*NHEADS*TSEQ*HDIM];
__device__ __nv_bfloat16 g_qlo[BATCH*NHEADS*TSEQ*HDIM];
__device__ __nv_bfloat16 g_khi[BATCH*NHEADS*TSEQ*HDIM];
__device__ __nv_bfloat16 g_klo[BATCH*NHEADS*TSEQ*HDIM];
__device__ __nv_bfloat16 g_vhi[BATCH*NHEADS*TSEQ*HDIM];
__device__ __nv_bfloat16 g_vlo[BATCH*NHEADS*TSEQ*HDIM];
__device__ __nv_bfloat16 g_ahi[(size_t)BT*DMODEL];
__device__ __nv_bfloat16 g_alo[(size_t)BT*DMODEL];

// ---------------- PTX helpers (base ISA: cp.async / ldmatrix / mma.sync) --------
__device__ __forceinline__ uint32_t smem_u32(const void* p) {
    uint32_t a;
    asm("{ .reg .u64 t; cvta.to.shared.u64 t, %1; cvt.u32.u64 %0, t; }" : "=r"(a) : "l"(p));
    return a;
}
#define CP16(dst, src) asm volatile("cp.async.cg.shared.global [%0], [%1], 16;" :: "r"(dst), "l"(src))
#define CP_COMMIT()    asm volatile("cp.async.commit_group;" ::: "memory")
#define CP_WAIT1()     asm volatile("cp.async.wait_group 1;" ::: "memory")
#define CP_WAIT0()     asm volatile("cp.async.wait_group 0;" ::: "memory")
#define LDSM4(r, a) \
    asm volatile("ldmatrix.sync.aligned.m8n8.x4.shared.b16 {%0,%1,%2,%3}, [%4];" \
        : "=r"((r)[0]), "=r"((r)[1]), "=r"((r)[2]), "=r"((r)[3]) : "r"(a))
#define LDSM4T(r, a) \
    asm volatile("ldmatrix.sync.aligned.m8n8.x4.trans.shared.b16 {%0,%1,%2,%3}, [%4];" \
        : "=r"((r)[0]), "=r"((r)[1]), "=r"((r)[2]), "=r"((r)[3]) : "r"(a))
__device__ __forceinline__ void mma_bf16(float* c, const uint32_t* a, uint32_t b0, uint32_t b1) {
    asm volatile("mma.sync.aligned.m16n8k16.row.col.f32.bf16.bf16.f32 "
                 "{%0,%1,%2,%3}, {%4,%5,%6,%7}, {%8,%9}, {%0,%1,%2,%3};"
                 : "+f"(c[0]), "+f"(c[1]), "+f"(c[2]), "+f"(c[3])
                 : "r"(a[0]), "r"(a[1]), "r"(a[2]), "r"(a[3]), "r"(b0), "r"(b1));
}
// split two floats into packed bf16 hi pair + lo (residual) pair
__device__ __forceinline__ void split_pack(float x, float y, uint32_t& hi, uint32_t& lo) {
    __nv_bfloat16 hx = __float2bfloat16(x), hy = __float2bfloat16(y);
    __nv_bfloat16 lx = __float2bfloat16(x - __bfloat162float(hx));
    __nv_bfloat16 ly = __float2bfloat16(y - __bfloat162float(hy));
    hi = ((uint32_t)__bfloat16_as_ushort(hy) << 16) | __bfloat16_as_ushort(hx);
    lo = ((uint32_t)__bfloat16_as_ushort(ly) << 16) | __bfloat16_as_ushort(lx);
}

// ---------------- rope / gram / fold ----------------
__global__ void rope_kernel() {
    int s = blockIdx.x, d = threadIdx.x;
    int j = d & 31;
    double invf = exp(-log(10000.0) * (double)j / 32.0);
    double ang  = (double)s * invf;
    g_rope[s*HDIM + d] = (d < 32) ? (float)cos(ang) : (float)sin(ang);
}
__global__ void gram_kernel() {
    int d = blockIdx.x, e = threadIdx.x;
    double acc = 0.0;
    for (int s = 0; s < TSEQ; s++)
        acc += (double)g_rope[s*HDIM + d] * (double)g_rope[s*HDIM + e];
    g_M[d*HDIM + e] = (float)acc;
}
__global__ __launch_bounds__(256) void fold_kernel(const float* __restrict__ Wv) {
    __shared__ float Ms[HDIM*HDIM];
    __shared__ float wrow[DMODEL];
    int i = blockIdx.x;
    for (int t = threadIdx.x; t < HDIM*HDIM; t += blockDim.x) Ms[t] = g_M[t];
    for (int t = threadIdx.x; t < DMODEL;    t += blockDim.x) wrow[t] = Wv[(size_t)i*DMODEL + t];
    __syncthreads();
    for (int c = threadIdx.x; c < DMODEL; c += blockDim.x) {
        int h = c >> 6, e = c & 63;
        float acc = 0.f;
        #pragma unroll 8
        for (int d = 0; d < HDIM; d++) acc = fmaf(wrow[h*64 + d], Ms[d*64 + e], acc);
        g_Wvp[(size_t)i*DMODEL + c] = acc;
    }
}

// ---------------- hi/lo bf16 split of x ----------------
__global__ __launch_bounds__(256) void split_kernel(const float* __restrict__ src,
                                                    __nv_bfloat16* __restrict__ hi,
                                                    __nv_bfloat16* __restrict__ lo, int n4) {
    int i = blockIdx.x*blockDim.x + threadIdx.x;
    if (i >= n4) return;
    float4 v = ((const float4*)src)[i];
    uint32_t h0, l0, h1, l1;
    split_pack(v.x, v.y, h0, l0);
    split_pack(v.z, v.w, h1, l1);
    ((uint2*)hi)[i] = make_uint2(h0, h1);
    ((uint2*)lo)[i] = make_uint2(l0, l1);
}

// ---------------- transpose + split: W[K][N] -> T[N][K] hi/lo bf16 ----------------
__global__ void tsplit_kernel(const float* __restrict__ W,
                              __nv_bfloat16* __restrict__ hi,
                              __nv_bfloat16* __restrict__ lo) {
    __shared__ float t[32][33];
    int x0 = blockIdx.x*32, y0 = blockIdx.y*32;
    int tx = threadIdx.x, ty = threadIdx.y;
    #pragma unroll
    for (int j = 0; j < 32; j += 8)
        t[ty+j][tx] = W[(size_t)(y0+ty+j)*DMODEL + x0+tx];
    __syncthreads();
    #pragma unroll
    for (int j = 0; j < 32; j += 8) {
        float v = t[tx][ty+j];
        __nv_bfloat16 h = __float2bfloat16(v);
        size_t o = (size_t)(x0+ty+j)*DMODEL + y0+tx;
        hi[o] = h;
        lo[o] = __float2bfloat16(v - __bfloat162float(h));
    }
}

// ---------------- HMMA GEMM: C(4096x1024) = A @ W^T, bf16 hi/lo x3, fp32 accum ----
// MODE 0: write split-head bf16 hi/lo [bh][t][hd] with scale. MODE 1: fp32 row-major + bias.
#define ROWB     80
#define TILEB    (128*ROWB)
#define STAGEB   (4*TILEB)
#define SMEMB    (2*STAGEB)

template<int MODE>
__global__ __launch_bounds__(256) void hgemm_tc(const __nv_bfloat16* __restrict__ Ahi,
                                                const __nv_bfloat16* __restrict__ Alo,
                                                const __nv_bfloat16* __restrict__ Bhi,
                                                const __nv_bfloat16* __restrict__ Blo,
                                                const float* __restrict__ bias,
                                                float* __restrict__ OUT,
                                                float scale,
                                                __nv_bfloat16* __restrict__ OH,
                                                __nv_bfloat16* __restrict__ OL)
{
    extern __shared__ char smem[];
    const uint32_t smem_base = smem_u32(smem);
    const int tid  = threadIdx.x;
    const int lane = tid & 31;
    const int wid  = tid >> 5;
    const int wm   = wid & 3;
    const int wn   = wid >> 2;
    const int br   = blockIdx.y, bc = blockIdx.x;

    const int lrow  = tid >> 2;
    const int chunk = tid & 3;

    const __nv_bfloat16* A0h = Ahi + (size_t)(br*128 + lrow)*DMODEL + chunk*8;
    const __nv_bfloat16* A0l = Alo + (size_t)(br*128 + lrow)*DMODEL + chunk*8;
    const __nv_bfloat16* B0h = Bhi + (size_t)(bc*128 + lrow)*DMODEL + chunk*8;
    const __nv_bfloat16* B0l = Blo + (size_t)(bc*128 + lrow)*DMODEL + chunk*8;
    const size_t rstep = (size_t)64*DMODEL;

#define ISSUE(s_, buf_) do { \
    uint32_t sb = smem_base + (buf_)*STAGEB; \
    uint32_t d0 = sb + lrow*ROWB + chunk*16; \
    size_t  go = (size_t)(s_)*32; \
    CP16(d0,                    A0h + go); \
    CP16(d0 + TILEB,            A0l + go); \
    CP16(d0 + 2*TILEB,          B0h + go); \
    CP16(d0 + 3*TILEB,          B0l + go); \
    uint32_t d1 = d0 + 64*ROWB; \
    CP16(d1,                    A0h + go + rstep); \
    CP16(d1 + TILEB,            A0l + go + rstep); \
    CP16(d1 + 2*TILEB,          B0h + go + rstep); \
    CP16(d1 + 3*TILEB,          B0l + go + rstep); \
} while (0)

    float acc[2][8][4];
    #pragma unroll
    for (int i = 0; i < 2; i++)
        #pragma unroll
        for (int j = 0; j < 8; j++)
            #pragma unroll
            for (int e = 0; e < 4; e++) acc[i][j][e] = 0.f;

    const int m0 = wm*32, n0 = wn*64;
    const int lr = lane & 15, lh = lane >> 4;

    ISSUE(0, 0); CP_COMMIT();

    for (int s = 0; s < 32; s++) {
        if (s + 1 < 32) { ISSUE(s + 1, (s + 1) & 1); CP_COMMIT(); CP_WAIT1(); }
        else            { CP_WAIT0(); }
        __syncthreads();

        const uint32_t As = smem_base + (s & 1)*STAGEB;
        const uint32_t Bs = As + 2*TILEB;
        #pragma unroll
        for (int k = 0; k < 2; k++) {
            const uint32_t koff = k*32 + lh*16;
            uint32_t ahi[2][4], axx[2][4], bq[4][4];
            #pragma unroll
            for (int mi = 0; mi < 2; mi++)
                LDSM4(ahi[mi], As + (m0 + mi*16 + lr)*ROWB + koff);
            #pragma unroll
            for (int jg = 0; jg < 4; jg++)
                LDSM4(bq[jg], Bs + (n0 + jg*16 + lr)*ROWB + koff);
            #pragma unroll
            for (int mi = 0; mi < 2; mi++)
                #pragma unroll
                for (int j = 0; j < 8; j++)
                    mma_bf16(acc[mi][j], ahi[mi], bq[j>>1][j&1], bq[j>>1][(j&1)+2]);
            #pragma unroll
            for (int mi = 0; mi < 2; mi++)
                LDSM4(axx[mi], As + TILEB + (m0 + mi*16 + lr)*ROWB + koff);
            #pragma unroll
            for (int mi = 0; mi < 2; mi++)
                #pragma unroll
                for (int j = 0; j < 8; j++)
                    mma_bf16(acc[mi][j], axx[mi], bq[j>>1][j&1], bq[j>>1][(j&1)+2]);
            #pragma unroll
            for (int jg = 0; jg < 4; jg++)
                LDSM4(bq[jg], Bs + TILEB + (n0 + jg*16 + lr)*ROWB + koff);
            #pragma unroll
            for (int mi = 0; mi < 2; mi++)
                #pragma unroll
                for (int j = 0; j < 8; j++)
                    mma_bf16(acc[mi][j], ahi[mi], bq[j>>1][j&1], bq[j>>1][(j&1)+2]);
        }
        __syncthreads();
    }
#undef ISSUE

    const int g = lane >> 2, t = lane & 3;
    #pragma unroll
    for (int mi = 0; mi < 2; mi++) {
        #pragma unroll
        for (int rr = 0; rr < 2; rr++) {
            const int row = br*128 + m0 + mi*16 + rr*8 + g;
            #pragma unroll
            for (int j = 0; j < 8; j++) {
                const int col = bc*128 + n0 + j*8 + t*2;
                float vx = acc[mi][j][rr*2 + 0];
                float vy = acc[mi][j][rr*2 + 1];
                if (MODE == 1) {
                    float2 v; v.x = vx + bias[col]; v.y = vy + bias[col + 1];
                    *(float2*)&OUT[(size_t)row*DMODEL + col] = v;
                } else {
                    uint32_t ph, pl;
                    split_pack(vx*scale, vy*scale, ph, pl);
                    int bi = row >> 11, tt = row & 2047;
                    int h = col >> 6, dd = col & 63;
                    size_t o = (((size_t)(bi*NHEADS + h))*TSEQ + tt)*HDIM + dd;
                    *(uint32_t*)&OH[o] = ph;
                    *(uint32_t*)&OL[o] = pl;
                }
            }
        }
    }
}

// ---------------- HMMA flash attention -----------------------------------------
// 128 q-rows per CTA, 8 warps x 16 rows; 64-key blocks, double-buffered cp.async.
// S = QhiKhi + QloKhi + QhiKlo ; O = PhiVhi + PloVhi + PhiVlo ; fp32 online softmax.
#define ROWF   144               /* 64 bf16 = 128B + 16B pad */
#define FQHI   0
#define FQLO   (128*ROWF)        /* 18432 */
#define FQTOT  (2*128*ROWF)      /* 36864 */
#define FKHI   0
#define FKLO   (64*ROWF)         /* 9216  */
#define FVHI   (2*64*ROWF)
#define FVLO   (3*64*ROWF)
#define FSTG   (4*64*ROWF)       /* 36864 per stage */
#define FSMEM  (FQTOT + 2*FSTG)  /* 110592 */

__global__ __launch_bounds__(256) void flash_hmma(
    const __nv_bfloat16* __restrict__ qhi, const __nv_bfloat16* __restrict__ qlo,
    const __nv_bfloat16* __restrict__ khi, const __nv_bfloat16* __restrict__ klo,
    const __nv_bfloat16* __restrict__ vhi, const __nv_bfloat16* __restrict__ vlo,
    __nv_bfloat16* __restrict__ ohi, __nv_bfloat16* __restrict__ olo)
{
    extern __shared__ char fsm[];
    const uint32_t sb = smem_u32(fsm);
    const int tid = threadIdx.x, lane = tid & 31, wid = tid >> 5;
    const int bh = blockIdx.y, q0 = blockIdx.x*128;
    const int g = lane >> 2, t = lane & 3, lr = lane & 15, lh = lane >> 4;
    const int wq = wid*16;

    const size_t base = (size_t)bh*TSEQ*HDIM;
    const __nv_bfloat16* qph = qhi + base + (size_t)q0*HDIM;
    const __nv_bfloat16* qpl = qlo + base + (size_t)q0*HDIM;
    const __nv_bfloat16* kph = khi + base;
    const __nv_bfloat16* kpl = klo + base;
    const __nv_bfloat16* vph = vhi + base;
    const __nv_bfloat16* vpl = vlo + base;

    // load Q (once)
    {
        int r = tid >> 1, c4 = (tid & 1)*4;
        #pragma unroll
        for (int u = 0; u < 4; u++) {
            CP16(sb + FQHI + r*ROWF + (c4+u)*16, qph + (size_t)r*HDIM + (c4+u)*8);
            CP16(sb + FQLO + r*ROWF + (c4+u)*16, qpl + (size_t)r*HDIM + (c4+u)*8);
        }
        CP_COMMIT();
    }

#define FISSUE(kb_, b_) do { \
    int r = tid >> 2, c2 = (tid & 3)*2; \
    uint32_t s0 = sb + FQTOT + (b_)*FSTG; \
    size_t go = (size_t)((kb_)*64 + r)*HDIM; \
    _Pragma("unroll") \
    for (int u = 0; u < 2; u++) { \
        CP16(s0 + FKHI + r*ROWF + (c2+u)*16, kph + go + (c2+u)*8); \
        CP16(s0 + FKLO + r*ROWF + (c2+u)*16, kpl + go + (c2+u)*8); \
        CP16(s0 + FVHI + r*ROWF + (c2+u)*16, vph + go + (c2+u)*8); \
        CP16(s0 + FVLO + r*ROWF + (c2+u)*16, vpl + go + (c2+u)*8); \
    } \
} while (0)

    FISSUE(0, 0); CP_COMMIT();
    CP_WAIT0(); __syncthreads();

    float oacc[8][4];
    #pragma unroll
    for (int j = 0; j < 8; j++)
        #pragma unroll
        for (int e = 0; e < 4; e++) oacc[j][e] = 0.f;
    const float NEGINF = __int_as_float(0xff800000);
    float m0 = NEGINF, m1 = NEGINF, l0 = 0.f, l1 = 0.f;

    for (int kb = 0; kb < 32; kb++) {
        if (kb + 1 < 32) { FISSUE(kb + 1, (kb + 1) & 1); CP_COMMIT(); CP_WAIT1(); }
        else             { CP_WAIT0(); }
        __syncthreads();

        const uint32_t SB = sb + FQTOT + (kb & 1)*FSTG;

        // ---- S = Q K^T (3-term) ----
        float sacc[8][4];
        #pragma unroll
        for (int j = 0; j < 8; j++)
            #pragma unroll
            for (int e = 0; e < 4; e++) sacc[j][e] = 0.f;

        #pragma unroll
        for (int kk = 0; kk < 4; kk++) {
            const uint32_t ko = kk*32 + lh*16;
            uint32_t aqh[4], aql[4];
            LDSM4(aqh, sb + FQHI + (wq + lr)*ROWF + ko);
            LDSM4(aql, sb + FQLO + (wq + lr)*ROWF + ko);
            #pragma unroll
            for (int jg = 0; jg < 4; jg++) {
                uint32_t bkh[4], bkl[4];
                LDSM4(bkh, SB + FKHI + (jg*16 + lr)*ROWF + ko);
                LDSM4(bkl, SB + FKLO + (jg*16 + lr)*ROWF + ko);
                #pragma unroll
                for (int j2 = 0; j2 < 2; j2++) {
                    float* c = sacc[jg*2 + j2];
                    mma_bf16(c, aqh, bkh[j2], bkh[j2+2]);
                    mma_bf16(c, aql, bkh[j2], bkh[j2+2]);
                    mma_bf16(c, aqh, bkl[j2], bkl[j2+2]);
                }
            }
        }

        // ---- online softmax ----
        float nm0 = NEGINF, nm1 = NEGINF;
        #pragma unroll
        for (int j = 0; j < 8; j++) {
            nm0 = fmaxf(nm0, fmaxf(sacc[j][0], sacc[j][1]));
            nm1 = fmaxf(nm1, fmaxf(sacc[j][2], sacc[j][3]));
        }
        nm0 = fmaxf(nm0, __shfl_xor_sync(0xffffffffu, nm0, 1));
        nm0 = fmaxf(nm0, __shfl_xor_sync(0xffffffffu, nm0, 2));
        nm1 = fmaxf(nm1, __shfl_xor_sync(0xffffffffu, nm1, 1));
        nm1 = fmaxf(nm1, __shfl_xor_sync(0xffffffffu, nm1, 2));
        float M0 = fmaxf(m0, nm0), M1 = fmaxf(m1, nm1);
        float c0 = __expf(m0 - M0), c1 = __expf(m1 - M1);
        m0 = M0; m1 = M1;
        float rs0 = 0.f, rs1 = 0.f;
        #pragma unroll
        for (int j = 0; j < 8; j++) {
            sacc[j][0] = __expf(sacc[j][0] - M0);
            sacc[j][1] = __expf(sacc[j][1] - M0);
            sacc[j][2] = __expf(sacc[j][2] - M1);
            sacc[j][3] = __expf(sacc[j][3] - M1);
            rs0 += sacc[j][0] + sacc[j][1];
            rs1 += sacc[j][2] + sacc[j][3];
        }
        rs0 += __shfl_xor_sync(0xffffffffu, rs0, 1);
        rs0 += __shfl_xor_sync(0xffffffffu, rs0, 2);
        rs1 += __shfl_xor_sync(0xffffffffu, rs1, 1);
        rs1 += __shfl_xor_sync(0xffffffffu, rs1, 2);
        l0 = l0*c0 + rs0;
        l1 = l1*c1 + rs1;
        #pragma unroll
        for (int j = 0; j < 8; j++) {
            oacc[j][0] *= c0; oacc[j][1] *= c0;
            oacc[j][2] *= c1; oacc[j][3] *= c1;
        }

        // ---- O += P V (3-term); P repacked from S fragments ----
        const int vrow0 = ((lane >> 3) & 1)*8 + (lane & 7);
        const int vcsub = (lane >> 4)*8;
        #pragma unroll
        for (int kk = 0; kk < 4; kk++) {
            uint32_t ah[4], al[4];
            split_pack(sacc[2*kk][0],   sacc[2*kk][1],   ah[0], al[0]);
            split_pack(sacc[2*kk][2],   sacc[2*kk][3],   ah[1], al[1]);
            split_pack(sacc[2*kk+1][0], sacc[2*kk+1][1], ah[2], al[2]);
            split_pack(sacc[2*kk+1][2], sacc[2*kk+1][3], ah[3], al[3]);
            const uint32_t vr = (kk*16 + vrow0)*ROWF;
            #pragma unroll
            for (int jj = 0; jj < 4; jj++) {
                uint32_t bvh[4], bvl[4];
                const uint32_t va = SB + vr + (jj*16 + vcsub)*2;
                LDSM4T(bvh, va + FVHI);
                LDSM4T(bvl, va + FVLO);
                #pragma unroll
                for (int j2 = 0; j2 < 2; j2++) {
                    float* o = oacc[jj*2 + j2];
                    mma_bf16(o, ah, bvh[2*j2], bvh[2*j2+1]);
                    mma_bf16(o, al, bvh[2*j2], bvh[2*j2+1]);
                    mma_bf16(o, ah, bvl[2*j2], bvl[2*j2+1]);
                }
            }
        }
        __syncthreads();
    }
#undef FISSUE

    // ---- normalize + write bf16 hi/lo to [token][dmodel] ----
    const float inv0 = 1.f / l0, inv1 = 1.f / l1;
    const int b = bh >> 4, h = bh & 15;
    const int tok0 = b*TSEQ + q0 + wq + g;
    const int tok1 = tok0 + 8;
    #pragma unroll
    for (int j = 0; j < 8; j++) {
        const int col = h*64 + j*8 + t*2;
        uint32_t ph, pl;
        split_pack(oacc[j][0]*inv0, oacc[j][1]*inv0, ph, pl);
        *(uint32_t*)&ohi[(size_t)tok0*DMODEL + col] = ph;
        *(uint32_t*)&olo[(size_t)tok0*DMODEL + col] = pl;
        split_pack(oacc[j][2]*inv1, oacc[j][3]*inv1, ph, pl);
        *(uint32_t*)&ohi[(size_t)tok1*DMODEL + col] = ph;
        *(uint32_t*)&olo[(size_t)tok1*DMODEL + col] = pl;
    }
}

// ---------------- launch ----------------
extern "C" void kernel_launch(void* const* d_in, const int* in_sizes, int n_in,
                              void* d_out, int out_size)
{
    const float* x  = (const float*)d_in[0];
    const float* Wq = (const float*)d_in[1];
    const float* Wk = (const float*)d_in[2];
    const float* Wv = (const float*)d_in[3];
    const float* Wo = (const float*)d_in[4];
    const float* bo = (const float*)d_in[5];
    float* out = (float*)d_out;

    float* wvp;
    cudaGetSymbolAddress((void**)&wvp, g_Wvp);
    __nv_bfloat16 *xhi, *xlo, *whi, *wlo, *ahi, *alo;
    __nv_bfloat16 *qhi, *qlo, *khi, *klo, *vhi, *vlo;
    cudaGetSymbolAddress((void**)&xhi, g_xhi);
    cudaGetSymbolAddress((void**)&xlo, g_xlo);
    cudaGetSymbolAddress((void**)&whi, g_whi);
    cudaGetSymbolAddress((void**)&wlo, g_wlo);
    cudaGetSymbolAddress((void**)&ahi, g_ahi);
    cudaGetSymbolAddress((void**)&alo, g_alo);
    cudaGetSymbolAddress((void**)&qhi, g_qhi);
    cudaGetSymbolAddress((void**)&qlo, g_qlo);
    cudaGetSymbolAddress((void**)&khi, g_khi);
    cudaGetSymbolAddress((void**)&klo, g_klo);
    cudaGetSymbolAddress((void**)&vhi, g_vhi);
    cudaGetSymbolAddress((void**)&vlo, g_vlo);

    const size_t WSZ = (size_t)DMODEL*DMODEL;

    rope_kernel<<<TSEQ, HDIM>>>();
    gram_kernel<<<HDIM, HDIM>>>();
    fold_kernel<<<DMODEL, 256>>>(Wv);

    split_kernel<<<(BT*DMODEL/4 + 255)/256, 256>>>(x, xhi, xlo, BT*DMODEL/4);
    dim3 tg(DMODEL/32, DMODEL/32), tb(32, 8);
    tsplit_kernel<<<tg, tb>>>(Wq,  whi + 0*WSZ, wlo + 0*WSZ);
    tsplit_kernel<<<tg, tb>>>(Wk,  whi + 1*WSZ, wlo + 1*WSZ);
    tsplit_kernel<<<tg, tb>>>(wvp, whi + 2*WSZ, wlo + 2*WSZ);
    tsplit_kernel<<<tg, tb>>>(Wo,  whi + 3*WSZ, wlo + 3*WSZ);

    cudaFuncSetAttribute(hgemm_tc<0>, cudaFuncAttributeMaxDynamicSharedMemorySize, SMEMB);
    cudaFuncSetAttribute(hgemm_tc<1>, cudaFuncAttributeMaxDynamicSharedMemorySize, SMEMB);
    cudaFuncSetAttribute(flash_hmma, cudaFuncAttributeMaxDynamicSharedMemorySize, FSMEM);

    dim3 gg(DMODEL/128, BT/128);   // (8, 32)
    hgemm_tc<0><<<gg, 256, SMEMB>>>(xhi, xlo, whi + 0*WSZ, wlo + 0*WSZ, nullptr, nullptr, 0.125f, qhi, qlo);
    hgemm_tc<0><<<gg, 256, SMEMB>>>(xhi, xlo, whi + 1*WSZ, wlo + 1*WSZ, nullptr, nullptr, 1.0f,   khi, klo);
    hgemm_tc<0><<<gg, 256, SMEMB>>>(xhi, xlo, whi + 2*WSZ, wlo + 2*WSZ, nullptr, nullptr, 1.0f,   vhi, vlo);

    flash_hmma<<<dim3(TSEQ/128, BATCH*NHEADS), 256, FSMEM>>>(qhi, qlo, khi, klo, vhi, vlo, ahi, alo);

    hgemm_tc<1><<<gg, 256, SMEMB>>>(ahi, alo, whi + 3*WSZ, wlo + 3*WSZ, bo, out, 1.0f, nullptr, nullptr);

    (void)in_sizes; (void)n_in; (void)out_size;
}

// round 6
// speedup vs baseline: 2.3840x; 1.1771x over previous
#include <cuda_runtime.h>
#include <cuda_bf16.h>
#include <math.h>
#include <stdint.h>

#define BATCH   2
#define TSEQ    2048
#define DMODEL  1024
#define NHEADS  16
#define HDIM    64
#define BT      (BATCH*TSEQ)   /* 4096 */
#define SCALE_Q 0.1803368801111137f   /* 0.125 * log2(e) */

// ---------------- scratch (static device arrays; no allocation) ----------------
__device__ float g_rope[TSEQ*HDIM];
__device__ double g_Mpart[16][HDIM*HDIM];
__device__ float g_M[HDIM*HDIM];
__device__ float g_Wvp[DMODEL*DMODEL];
__device__ __nv_bfloat16 g_xhi[(size_t)BT*DMODEL];
__device__ __nv_bfloat16 g_xlo[(size_t)BT*DMODEL];
__device__ __nv_bfloat16 g_whi[4*(size_t)DMODEL*DMODEL];   // transposed weights [N][K]
__device__ __nv_bfloat16 g_wlo[4*(size_t)DMODEL*DMODEL];
__device__ __nv_bfloat16 g_qhi[BATCH*NHEADS*TSEQ*HDIM];
__device__ __nv_bfloat16 g_qlo[BATCH*NHEADS*TSEQ*HDIM];
__device__ __nv_bfloat16 g_khi[BATCH*NHEADS*TSEQ*HDIM];
__device__ __nv_bfloat16 g_klo[BATCH*NHEADS*TSEQ*HDIM];
__device__ __nv_bfloat16 g_vhi[BATCH*NHEADS*TSEQ*HDIM];
__device__ __nv_bfloat16 g_vlo[BATCH*NHEADS*TSEQ*HDIM];
__device__ __nv_bfloat16 g_ahi[(size_t)BT*DMODEL];
__device__ __nv_bfloat16 g_alo[(size_t)BT*DMODEL];

// ---------------- PTX helpers (base ISA: cp.async / ldmatrix / mma.sync) --------
__device__ __forceinline__ uint32_t smem_u32(const void* p) {
    uint32_t a;
    asm("{ .reg .u64 t; cvta.to.shared.u64 t, %1; cvt.u32.u64 %0, t; }" : "=r"(a) : "l"(p));
    return a;
}
#define CP16(dst, src) asm volatile("cp.async.cg.shared.global [%0], [%1], 16;" :: "r"(dst), "l"(src))
#define CP_COMMIT()    asm volatile("cp.async.commit_group;" ::: "memory")
#define CP_WAIT1()     asm volatile("cp.async.wait_group 1;" ::: "memory")
#define CP_WAIT0()     asm volatile("cp.async.wait_group 0;" ::: "memory")
#define LDSM4(r, a) \
    asm volatile("ldmatrix.sync.aligned.m8n8.x4.shared.b16 {%0,%1,%2,%3}, [%4];" \
        : "=r"((r)[0]), "=r"((r)[1]), "=r"((r)[2]), "=r"((r)[3]) : "r"(a))
#define LDSM4T(r, a) \
    asm volatile("ldmatrix.sync.aligned.m8n8.x4.trans.shared.b16 {%0,%1,%2,%3}, [%4];" \
        : "=r"((r)[0]), "=r"((r)[1]), "=r"((r)[2]), "=r"((r)[3]) : "r"(a))
__device__ __forceinline__ void mma_bf16(float* c, const uint32_t* a, uint32_t b0, uint32_t b1) {
    asm volatile("mma.sync.aligned.m16n8k16.row.col.f32.bf16.bf16.f32 "
                 "{%0,%1,%2,%3}, {%4,%5,%6,%7}, {%8,%9}, {%0,%1,%2,%3};"
                 : "+f"(c[0]), "+f"(c[1]), "+f"(c[2]), "+f"(c[3])
                 : "r"(a[0]), "r"(a[1]), "r"(a[2]), "r"(a[3]), "r"(b0), "r"(b1));
}
__device__ __forceinline__ float ex2f(float x) {
    float r; asm("ex2.approx.f32 %0, %1;" : "=f"(r) : "f"(x)); return r;
}
// split two floats into packed bf16 hi pair + lo (residual) pair
__device__ __forceinline__ void split_pack(float x, float y, uint32_t& hi, uint32_t& lo) {
    __nv_bfloat16 hx = __float2bfloat16(x), hy = __float2bfloat16(y);
    __nv_bfloat16 lx = __float2bfloat16(x - __bfloat162float(hx));
    __nv_bfloat16 ly = __float2bfloat16(y - __bfloat162float(hy));
    hi = ((uint32_t)__bfloat16_as_ushort(hy) << 16) | __bfloat16_as_ushort(hx);
    lo = ((uint32_t)__bfloat16_as_ushort(ly) << 16) | __bfloat16_as_ushort(lx);
}

// ---------------- rope / gram / fold ----------------
__global__ void rope_kernel() {
    int s = blockIdx.x, d = threadIdx.x;
    int j = d & 31;
    double invf = exp(-log(10000.0) * (double)j / 32.0);
    double ang  = (double)s * invf;
    g_rope[s*HDIM + d] = (d < 32) ? (float)cos(ang) : (float)sin(ang);
}
// Gram stage 1: partial sums over 128-s chunks. grid (64, 16), block 64.
__global__ void gram1_kernel() {
    int d = blockIdx.x, c = blockIdx.y, e = threadIdx.x;
    double acc = 0.0;
    const float* rp = g_rope + c*128*HDIM;
    for (int s = 0; s < 128; s++)
        acc += (double)rp[s*HDIM + d] * (double)rp[s*HDIM + e];
    g_Mpart[c][d*HDIM + e] = acc;
}
// Gram stage 2: reduce 16 partials. grid 64, block 64.
__global__ void gram2_kernel() {
    int d = blockIdx.x, e = threadIdx.x;
    double a = 0.0;
    #pragma unroll
    for (int c = 0; c < 16; c++) a += g_Mpart[c][d*HDIM + e];
    g_M[d*HDIM + e] = (float)a;
}
__global__ __launch_bounds__(256) void fold_kernel(const float* __restrict__ Wv) {
    __shared__ float Ms[HDIM*HDIM];
    __shared__ float wrow[DMODEL];
    int i = blockIdx.x;
    for (int t = threadIdx.x; t < HDIM*HDIM; t += blockDim.x) Ms[t] = g_M[t];
    for (int t = threadIdx.x; t < DMODEL;    t += blockDim.x) wrow[t] = Wv[(size_t)i*DMODEL + t];
    __syncthreads();
    for (int c = threadIdx.x; c < DMODEL; c += blockDim.x) {
        int h = c >> 6, e = c & 63;
        float acc = 0.f;
        #pragma unroll 8
        for (int d = 0; d < HDIM; d++) acc = fmaf(wrow[h*64 + d], Ms[d*64 + e], acc);
        g_Wvp[(size_t)i*DMODEL + c] = acc;
    }
}

// ---------------- hi/lo bf16 split of x ----------------
__global__ __launch_bounds__(256) void split_kernel(const float* __restrict__ src,
                                                    __nv_bfloat16* __restrict__ hi,
                                                    __nv_bfloat16* __restrict__ lo, int n4) {
    int i = blockIdx.x*blockDim.x + threadIdx.x;
    if (i >= n4) return;
    float4 v = ((const float4*)src)[i];
    uint32_t h0, l0, h1, l1;
    split_pack(v.x, v.y, h0, l0);
    split_pack(v.z, v.w, h1, l1);
    ((uint2*)hi)[i] = make_uint2(h0, h1);
    ((uint2*)lo)[i] = make_uint2(l0, l1);
}

// ---------------- transpose + split: W[K][N] -> T[N][K] hi/lo bf16 ----------------
__global__ void tsplit_kernel(const float* __restrict__ W,
                              __nv_bfloat16* __restrict__ hi,
                              __nv_bfloat16* __restrict__ lo) {
    __shared__ float t[32][33];
    int x0 = blockIdx.x*32, y0 = blockIdx.y*32;
    int tx = threadIdx.x, ty = threadIdx.y;
    #pragma unroll
    for (int j = 0; j < 32; j += 8)
        t[ty+j][tx] = W[(size_t)(y0+ty+j)*DMODEL + x0+tx];
    __syncthreads();
    #pragma unroll
    for (int j = 0; j < 32; j += 8) {
        float v = t[tx][ty+j];
        __nv_bfloat16 h = __float2bfloat16(v);
        size_t o = (size_t)(x0+ty+j)*DMODEL + y0+tx;
        hi[o] = h;
        lo[o] = __float2bfloat16(v - __bfloat162float(h));
    }
}

// ---------------- HMMA GEMM: C = A @ W^T, bf16 hi/lo x3, fp32 accum ---------------
// MODE 0: merged QKV. blockIdx.x in [0,24): matrix m = bc>>3, col tile bc&7.
//         Writes split-head bf16 hi/lo with per-matrix scale.
// MODE 1: single GEMM (attn @ Wo), fp32 row-major + bias.
#define ROWB     80
#define TILEB    (128*ROWB)
#define STAGEB   (4*TILEB)
#define SMEMB    (2*STAGEB)

template<int MODE>
__global__ __launch_bounds__(256) void hgemm_tc(const __nv_bfloat16* __restrict__ Ahi,
                                                const __nv_bfloat16* __restrict__ Alo,
                                                const __nv_bfloat16* __restrict__ Bhi,
                                                const __nv_bfloat16* __restrict__ Blo,
                                                const float* __restrict__ bias,
                                                float* __restrict__ OUT,
                                                __nv_bfloat16* __restrict__ QH,
                                                __nv_bfloat16* __restrict__ QL,
                                                __nv_bfloat16* __restrict__ KH,
                                                __nv_bfloat16* __restrict__ KL,
                                                __nv_bfloat16* __restrict__ VH,
                                                __nv_bfloat16* __restrict__ VL)
{
    extern __shared__ char smem[];
    const uint32_t smem_base = smem_u32(smem);
    const int tid  = threadIdx.x;
    const int lane = tid & 31;
    const int wid  = tid >> 5;
    const int wm   = wid & 3;
    const int wn   = wid >> 2;
    const int br   = blockIdx.y, bc = blockIdx.x;

    const int lrow  = tid >> 2;
    const int chunk = tid & 3;

    const __nv_bfloat16* A0h = Ahi + (size_t)(br*128 + lrow)*DMODEL + chunk*8;
    const __nv_bfloat16* A0l = Alo + (size_t)(br*128 + lrow)*DMODEL + chunk*8;
    const __nv_bfloat16* B0h = Bhi + (size_t)(bc*128 + lrow)*DMODEL + chunk*8;
    const __nv_bfloat16* B0l = Blo + (size_t)(bc*128 + lrow)*DMODEL + chunk*8;
    const size_t rstep = (size_t)64*DMODEL;

#define ISSUE(s_, buf_) do { \
    uint32_t sb = smem_base + (buf_)*STAGEB; \
    uint32_t d0 = sb + lrow*ROWB + chunk*16; \
    size_t  go = (size_t)(s_)*32; \
    CP16(d0,                    A0h + go); \
    CP16(d0 + TILEB,            A0l + go); \
    CP16(d0 + 2*TILEB,          B0h + go); \
    CP16(d0 + 3*TILEB,          B0l + go); \
    uint32_t d1 = d0 + 64*ROWB; \
    CP16(d1,                    A0h + go + rstep); \
    CP16(d1 + TILEB,            A0l + go + rstep); \
    CP16(d1 + 2*TILEB,          B0h + go + rstep); \
    CP16(d1 + 3*TILEB,          B0l + go + rstep); \
} while (0)

    float acc[2][8][4];
    #pragma unroll
    for (int i = 0; i < 2; i++)
        #pragma unroll
        for (int j = 0; j < 8; j++)
            #pragma unroll
            for (int e = 0; e < 4; e++) acc[i][j][e] = 0.f;

    const int m0 = wm*32, n0 = wn*64;
    const int lr = lane & 15, lh = lane >> 4;

    ISSUE(0, 0); CP_COMMIT();

    for (int s = 0; s < 32; s++) {
        if (s + 1 < 32) { ISSUE(s + 1, (s + 1) & 1); CP_COMMIT(); CP_WAIT1(); }
        else            { CP_WAIT0(); }
        __syncthreads();

        const uint32_t As = smem_base + (s & 1)*STAGEB;
        const uint32_t Bs = As + 2*TILEB;
        #pragma unroll
        for (int k = 0; k < 2; k++) {
            const uint32_t koff = k*32 + lh*16;
            uint32_t ahi[2][4], axx[2][4], bq[4][4];
            #pragma unroll
            for (int mi = 0; mi < 2; mi++)
                LDSM4(ahi[mi], As + (m0 + mi*16 + lr)*ROWB + koff);
            #pragma unroll
            for (int jg = 0; jg < 4; jg++)
                LDSM4(bq[jg], Bs + (n0 + jg*16 + lr)*ROWB + koff);
            #pragma unroll
            for (int mi = 0; mi < 2; mi++)
                #pragma unroll
                for (int j = 0; j < 8; j++)
                    mma_bf16(acc[mi][j], ahi[mi], bq[j>>1][j&1], bq[j>>1][(j&1)+2]);
            #pragma unroll
            for (int mi = 0; mi < 2; mi++)
                LDSM4(axx[mi], As + TILEB + (m0 + mi*16 + lr)*ROWB + koff);
            #pragma unroll
            for (int mi = 0; mi < 2; mi++)
                #pragma unroll
                for (int j = 0; j < 8; j++)
                    mma_bf16(acc[mi][j], axx[mi], bq[j>>1][j&1], bq[j>>1][(j&1)+2]);
            #pragma unroll
            for (int jg = 0; jg < 4; jg++)
                LDSM4(bq[jg], Bs + TILEB + (n0 + jg*16 + lr)*ROWB + koff);
            #pragma unroll
            for (int mi = 0; mi < 2; mi++)
                #pragma unroll
                for (int j = 0; j < 8; j++)
                    mma_bf16(acc[mi][j], ahi[mi], bq[j>>1][j&1], bq[j>>1][(j&1)+2]);
        }
        __syncthreads();
    }
#undef ISSUE

    // epilogue
    __nv_bfloat16 *OH = nullptr, *OL = nullptr;
    float scale = 1.f;
    int colbase = bc*128;
    if (MODE == 0) {
        const int mm = bc >> 3;
        OH = (mm == 0) ? QH : (mm == 1) ? KH : VH;
        OL = (mm == 0) ? QL : (mm == 1) ? KL : VL;
        scale = (mm == 0) ? SCALE_Q : 1.f;
        colbase = (bc & 7)*128;
    }
    const int g = lane >> 2, t = lane & 3;
    #pragma unroll
    for (int mi = 0; mi < 2; mi++) {
        #pragma unroll
        for (int rr = 0; rr < 2; rr++) {
            const int row = br*128 + m0 + mi*16 + rr*8 + g;
            #pragma unroll
            for (int j = 0; j < 8; j++) {
                const int col = colbase + n0 + j*8 + t*2;
                float vx = acc[mi][j][rr*2 + 0];
                float vy = acc[mi][j][rr*2 + 1];
                if (MODE == 1) {
                    float2 v; v.x = vx + bias[col]; v.y = vy + bias[col + 1];
                    *(float2*)&OUT[(size_t)row*DMODEL + col] = v;
                } else {
                    uint32_t ph, pl;
                    split_pack(vx*scale, vy*scale, ph, pl);
                    int bi = row >> 11, tt = row & 2047;
                    int h = col >> 6, dd = col & 63;
                    size_t o = (((size_t)(bi*NHEADS + h))*TSEQ + tt)*HDIM + dd;
                    *(uint32_t*)&OH[o] = ph;
                    *(uint32_t*)&OL[o] = pl;
                }
            }
        }
    }
}

// ---------------- HMMA flash attention -----------------------------------------
// 128 q-rows per CTA, 8 warps x 16 rows; 64-key blocks, double-buffered cp.async.
// S = QhiKhi + QloKhi + QhiKlo (exp2 domain); O = PhiVhi + PloVhi + PhiVlo.
#define ROWF   144
#define FQHI   0
#define FQLO   (128*ROWF)
#define FQTOT  (2*128*ROWF)
#define FKHI   0
#define FKLO   (64*ROWF)
#define FVHI   (2*64*ROWF)
#define FVLO   (3*64*ROWF)
#define FSTG   (4*64*ROWF)
#define FSMEM  (FQTOT + 2*FSTG)

__global__ __launch_bounds__(256) void flash_hmma(
    const __nv_bfloat16* __restrict__ qhi, const __nv_bfloat16* __restrict__ qlo,
    const __nv_bfloat16* __restrict__ khi, const __nv_bfloat16* __restrict__ klo,
    const __nv_bfloat16* __restrict__ vhi, const __nv_bfloat16* __restrict__ vlo,
    __nv_bfloat16* __restrict__ ohi, __nv_bfloat16* __restrict__ olo)
{
    extern __shared__ char fsm[];
    const uint32_t sb = smem_u32(fsm);
    const int tid = threadIdx.x, lane = tid & 31, wid = tid >> 5;
    const int bh = blockIdx.y, q0 = blockIdx.x*128;
    const int g = lane >> 2, t = lane & 3, lr = lane & 15, lh = lane >> 4;
    const int wq = wid*16;

    const size_t base = (size_t)bh*TSEQ*HDIM;
    const __nv_bfloat16* qph = qhi + base + (size_t)q0*HDIM;
    const __nv_bfloat16* qpl = qlo + base + (size_t)q0*HDIM;
    const __nv_bfloat16* kph = khi + base;
    const __nv_bfloat16* kpl = klo + base;
    const __nv_bfloat16* vph = vhi + base;
    const __nv_bfloat16* vpl = vlo + base;

    {
        int r = tid >> 1, c4 = (tid & 1)*4;
        #pragma unroll
        for (int u = 0; u < 4; u++) {
            CP16(sb + FQHI + r*ROWF + (c4+u)*16, qph + (size_t)r*HDIM + (c4+u)*8);
            CP16(sb + FQLO + r*ROWF + (c4+u)*16, qpl + (size_t)r*HDIM + (c4+u)*8);
        }
        CP_COMMIT();
    }

#define FISSUE(kb_, b_) do { \
    int r = tid >> 2, c2 = (tid & 3)*2; \
    uint32_t s0 = sb + FQTOT + (b_)*FSTG; \
    size_t go = (size_t)((kb_)*64 + r)*HDIM; \
    _Pragma("unroll") \
    for (int u = 0; u < 2; u++) { \
        CP16(s0 + FKHI + r*ROWF + (c2+u)*16, kph + go + (c2+u)*8); \
        CP16(s0 + FKLO + r*ROWF + (c2+u)*16, kpl + go + (c2+u)*8); \
        CP16(s0 + FVHI + r*ROWF + (c2+u)*16, vph + go + (c2+u)*8); \
        CP16(s0 + FVLO + r*ROWF + (c2+u)*16, vpl + go + (c2+u)*8); \
    } \
} while (0)

    FISSUE(0, 0); CP_COMMIT();
    CP_WAIT0(); __syncthreads();

    float oacc[8][4];
    #pragma unroll
    for (int j = 0; j < 8; j++)
        #pragma unroll
        for (int e = 0; e < 4; e++) oacc[j][e] = 0.f;
    const float NEGINF = __int_as_float(0xff800000);
    float m0 = NEGINF, m1 = NEGINF, l0 = 0.f, l1 = 0.f;

    for (int kb = 0; kb < 32; kb++) {
        if (kb + 1 < 32) { FISSUE(kb + 1, (kb + 1) & 1); CP_COMMIT(); CP_WAIT1(); }
        else             { CP_WAIT0(); }
        __syncthreads();

        const uint32_t SB = sb + FQTOT + (kb & 1)*FSTG;

        // ---- S = Q K^T (3-term), already in exp2 domain ----
        float sacc[8][4];
        #pragma unroll
        for (int j = 0; j < 8; j++)
            #pragma unroll
            for (int e = 0; e < 4; e++) sacc[j][e] = 0.f;

        #pragma unroll
        for (int kk = 0; kk < 4; kk++) {
            const uint32_t ko = kk*32 + lh*16;
            uint32_t aqh[4], aql[4];
            LDSM4(aqh, sb + FQHI + (wq + lr)*ROWF + ko);
            LDSM4(aql, sb + FQLO + (wq + lr)*ROWF + ko);
            #pragma unroll
            for (int jg = 0; jg < 4; jg++) {
                uint32_t bkh[4], bkl[4];
                LDSM4(bkh, SB + FKHI + (jg*16 + lr)*ROWF + ko);
                LDSM4(bkl, SB + FKLO + (jg*16 + lr)*ROWF + ko);
                #pragma unroll
                for (int j2 = 0; j2 < 2; j2++) {
                    float* c = sacc[jg*2 + j2];
                    mma_bf16(c, aqh, bkh[j2], bkh[j2+2]);
                    mma_bf16(c, aql, bkh[j2], bkh[j2+2]);
                    mma_bf16(c, aqh, bkl[j2], bkl[j2+2]);
                }
            }
        }

        // ---- online softmax (exp2 domain) ----
        float nm0 = NEGINF, nm1 = NEGINF;
        #pragma unroll
        for (int j = 0; j < 8; j++) {
            nm0 = fmaxf(nm0, fmaxf(sacc[j][0], sacc[j][1]));
            nm1 = fmaxf(nm1, fmaxf(sacc[j][2], sacc[j][3]));
        }
        nm0 = fmaxf(nm0, __shfl_xor_sync(0xffffffffu, nm0, 1));
        nm0 = fmaxf(nm0, __shfl_xor_sync(0xffffffffu, nm0, 2));
        nm1 = fmaxf(nm1, __shfl_xor_sync(0xffffffffu, nm1, 1));
        nm1 = fmaxf(nm1, __shfl_xor_sync(0xffffffffu, nm1, 2));
        float M0 = fmaxf(m0, nm0), M1 = fmaxf(m1, nm1);
        bool changed = (M0 != m0) || (M1 != m1);
        float c0 = ex2f(m0 - M0), c1 = ex2f(m1 - M1);
        m0 = M0; m1 = M1;
        float rs0 = 0.f, rs1 = 0.f;
        #pragma unroll
        for (int j = 0; j < 8; j++) {
            sacc[j][0] = ex2f(sacc[j][0] - M0);
            sacc[j][1] = ex2f(sacc[j][1] - M0);
            sacc[j][2] = ex2f(sacc[j][2] - M1);
            sacc[j][3] = ex2f(sacc[j][3] - M1);
            rs0 += sacc[j][0] + sacc[j][1];
            rs1 += sacc[j][2] + sacc[j][3];
        }
        rs0 += __shfl_xor_sync(0xffffffffu, rs0, 1);
        rs0 += __shfl_xor_sync(0xffffffffu, rs0, 2);
        rs1 += __shfl_xor_sync(0xffffffffu, rs1, 1);
        rs1 += __shfl_xor_sync(0xffffffffu, rs1, 2);
        l0 = l0*c0 + rs0;
        l1 = l1*c1 + rs1;
        if (__any_sync(0xffffffffu, changed)) {
            #pragma unroll
            for (int j = 0; j < 8; j++) {
                oacc[j][0] *= c0; oacc[j][1] *= c0;
                oacc[j][2] *= c1; oacc[j][3] *= c1;
            }
        }

        // ---- O += P V (3-term); P repacked from S fragments ----
        const int vrow0 = ((lane >> 3) & 1)*8 + (lane & 7);
        const int vcsub = (lane >> 4)*8;
        #pragma unroll
        for (int kk = 0; kk < 4; kk++) {
            uint32_t ah[4], al[4];
            split_pack(sacc[2*kk][0],   sacc[2*kk][1],   ah[0], al[0]);
            split_pack(sacc[2*kk][2],   sacc[2*kk][3],   ah[1], al[1]);
            split_pack(sacc[2*kk+1][0], sacc[2*kk+1][1], ah[2], al[2]);
            split_pack(sacc[2*kk+1][2], sacc[2*kk+1][3], ah[3], al[3]);
            const uint32_t vr = (kk*16 + vrow0)*ROWF;
            #pragma unroll
            for (int jj = 0; jj < 4; jj++) {
                uint32_t bvh[4], bvl[4];
                const uint32_t va = SB + vr + (jj*16 + vcsub)*2;
                LDSM4T(bvh, va + FVHI);
                LDSM4T(bvl, va + FVLO);
                #pragma unroll
                for (int j2 = 0; j2 < 2; j2++) {
                    float* o = oacc[jj*2 + j2];
                    mma_bf16(o, ah, bvh[2*j2], bvh[2*j2+1]);
                    mma_bf16(o, al, bvh[2*j2], bvh[2*j2+1]);
                    mma_bf16(o, ah, bvl[2*j2], bvl[2*j2+1]);
                }
            }
        }
        __syncthreads();
    }
#undef FISSUE

    const float inv0 = 1.f / l0, inv1 = 1.f / l1;
    const int b = bh >> 4, h = bh & 15;
    const int tok0 = b*TSEQ + q0 + wq + g;
    const int tok1 = tok0 + 8;
    #pragma unroll
    for (int j = 0; j < 8; j++) {
        const int col = h*64 + j*8 + t*2;
        uint32_t ph, pl;
        split_pack(oacc[j][0]*inv0, oacc[j][1]*inv0, ph, pl);
        *(uint32_t*)&ohi[(size_t)tok0*DMODEL + col] = ph;
        *(uint32_t*)&olo[(size_t)tok0*DMODEL + col] = pl;
        split_pack(oacc[j][2]*inv1, oacc[j][3]*inv1, ph, pl);
        *(uint32_t*)&ohi[(size_t)tok1*DMODEL + col] = ph;
        *(uint32_t*)&olo[(size_t)tok1*DMODEL + col] = pl;
    }
}

// ---------------- launch ----------------
extern "C" void kernel_launch(void* const* d_in, const int* in_sizes, int n_in,
                              void* d_out, int out_size)
{
    const float* x  = (const float*)d_in[0];
    const float* Wq = (const float*)d_in[1];
    const float* Wk = (const float*)d_in[2];
    const float* Wv = (const float*)d_in[3];
    const float* Wo = (const float*)d_in[4];
    const float* bo = (const float*)d_in[5];
    float* out = (float*)d_out;

    float* wvp;
    cudaGetSymbolAddress((void**)&wvp, g_Wvp);
    __nv_bfloat16 *xhi, *xlo, *whi, *wlo, *ahi, *alo;
    __nv_bfloat16 *qhi, *qlo, *khi, *klo, *vhi, *vlo;
    cudaGetSymbolAddress((void**)&xhi, g_xhi);
    cudaGetSymbolAddress((void**)&xlo, g_xlo);
    cudaGetSymbolAddress((void**)&whi, g_whi);
    cudaGetSymbolAddress((void**)&wlo, g_wlo);
    cudaGetSymbolAddress((void**)&ahi, g_ahi);
    cudaGetSymbolAddress((void**)&alo, g_alo);
    cudaGetSymbolAddress((void**)&qhi, g_qhi);
    cudaGetSymbolAddress((void**)&qlo, g_qlo);
    cudaGetSymbolAddress((void**)&khi, g_khi);
    cudaGetSymbolAddress((void**)&klo, g_klo);
    cudaGetSymbolAddress((void**)&vhi, g_vhi);
    cudaGetSymbolAddress((void**)&vlo, g_vlo);

    const size_t WSZ = (size_t)DMODEL*DMODEL;

    rope_kernel<<<TSEQ, HDIM>>>();
    gram1_kernel<<<dim3(HDIM, 16), HDIM>>>();
    gram2_kernel<<<HDIM, HDIM>>>();
    fold_kernel<<<DMODEL, 256>>>(Wv);

    split_kernel<<<(BT*DMODEL/4 + 255)/256, 256>>>(x, xhi, xlo, BT*DMODEL/4);
    dim3 tg(DMODEL/32, DMODEL/32), tb(32, 8);
    tsplit_kernel<<<tg, tb>>>(Wq,  whi + 0*WSZ, wlo + 0*WSZ);
    tsplit_kernel<<<tg, tb>>>(Wk,  whi + 1*WSZ, wlo + 1*WSZ);
    tsplit_kernel<<<tg, tb>>>(wvp, whi + 2*WSZ, wlo + 2*WSZ);
    tsplit_kernel<<<tg, tb>>>(Wo,  whi + 3*WSZ, wlo + 3*WSZ);

    cudaFuncSetAttribute(hgemm_tc<0>, cudaFuncAttributeMaxDynamicSharedMemorySize, SMEMB);
    cudaFuncSetAttribute(hgemm_tc<1>, cudaFuncAttributeMaxDynamicSharedMemorySize, SMEMB);
    cudaFuncSetAttribute(flash_hmma, cudaFuncAttributeMaxDynamicSharedMemorySize, FSMEM);

    // merged QKV projection: grid.x = 24 (3 matrices x 8 col-tiles)
    hgemm_tc<0><<<dim3(24, BT/128), 256, SMEMB>>>(xhi, xlo, whi, wlo, nullptr, nullptr,
                                                  qhi, qlo, khi, klo, vhi, vlo);

    flash_hmma<<<dim3(TSEQ/128, BATCH*NHEADS), 256, FSMEM>>>(qhi, qlo, khi, klo, vhi, vlo, ahi, alo);

    hgemm_tc<1><<<dim3(8, BT/128), 256, SMEMB>>>(ahi, alo, whi + 3*WSZ, wlo + 3*WSZ, bo, out,
                                                 nullptr, nullptr, nullptr, nullptr, nullptr, nullptr);

    (void)in_sizes; (void)n_in; (void)out_size;
}

// round 7
// speedup vs baseline: 3.3915x; 1.4226x over previous
#include <cuda_runtime.h>
#include <cuda_fp16.h>
#include <math.h>
#include <stdint.h>

#define BATCH   2
#define TSEQ    2048
#define DMODEL  1024
#define NHEADS  16
#define HDIM    64
#define BT      (BATCH*TSEQ)   /* 4096 */
#define SCALE_Q 0.1803368801111137f   /* 0.125 * log2(e) */

// ---------------- scratch (static device arrays; no allocation) ----------------
__device__ float g_rope[TSEQ*HDIM];
__device__ double g_Mpart[16][HDIM*HDIM];
__device__ float g_M[HDIM*HDIM];
__device__ float g_Wvp[DMODEL*DMODEL];
__device__ __half g_xhi[(size_t)BT*DMODEL];
__device__ __half g_xlo[(size_t)BT*DMODEL];
__device__ __half g_wh[4*(size_t)DMODEL*DMODEL];   // transposed weights [N][K], fp16
__device__ __half g_qhi[BATCH*NHEADS*TSEQ*HDIM];
__device__ __half g_qlo[BATCH*NHEADS*TSEQ*HDIM];
__device__ __half g_kh[BATCH*NHEADS*TSEQ*HDIM];
__device__ __half g_vh[BATCH*NHEADS*TSEQ*HDIM];
__device__ __half g_ahi[(size_t)BT*DMODEL];
__device__ __half g_alo[(size_t)BT*DMODEL];

// ---------------- PTX helpers (base ISA: cp.async / ldmatrix / mma.sync) --------
__device__ __forceinline__ uint32_t smem_u32(const void* p) {
    uint32_t a;
    asm("{ .reg .u64 t; cvta.to.shared.u64 t, %1; cvt.u32.u64 %0, t; }" : "=r"(a) : "l"(p));
    return a;
}
#define CP16(dst, src) asm volatile("cp.async.cg.shared.global [%0], [%1], 16;" :: "r"(dst), "l"(src))
#define CP_COMMIT()    asm volatile("cp.async.commit_group;" ::: "memory")
#define CP_WAIT1()     asm volatile("cp.async.wait_group 1;" ::: "memory")
#define CP_WAIT0()     asm volatile("cp.async.wait_group 0;" ::: "memory")
#define LDSM4(r, a) \
    asm volatile("ldmatrix.sync.aligned.m8n8.x4.shared.b16 {%0,%1,%2,%3}, [%4];" \
        : "=r"((r)[0]), "=r"((r)[1]), "=r"((r)[2]), "=r"((r)[3]) : "r"(a))
#define LDSM4T(r, a) \
    asm volatile("ldmatrix.sync.aligned.m8n8.x4.trans.shared.b16 {%0,%1,%2,%3}, [%4];" \
        : "=r"((r)[0]), "=r"((r)[1]), "=r"((r)[2]), "=r"((r)[3]) : "r"(a))
__device__ __forceinline__ void mma_f16(float* c, const uint32_t* a, uint32_t b0, uint32_t b1) {
    asm volatile("mma.sync.aligned.m16n8k16.row.col.f32.f16.f16.f32 "
                 "{%0,%1,%2,%3}, {%4,%5,%6,%7}, {%8,%9}, {%0,%1,%2,%3};"
                 : "+f"(c[0]), "+f"(c[1]), "+f"(c[2]), "+f"(c[3])
                 : "r"(a[0]), "r"(a[1]), "r"(a[2]), "r"(a[3]), "r"(b0), "r"(b1));
}
__device__ __forceinline__ float ex2f(float x) {
    float r; asm("ex2.approx.f32 %0, %1;" : "=f"(r) : "f"(x)); return r;
}
// split two floats into packed fp16 hi pair + lo (residual) pair
__device__ __forceinline__ void split_pack(float x, float y, uint32_t& hi, uint32_t& lo) {
    __half hx = __float2half_rn(x), hy = __float2half_rn(y);
    __half lx = __float2half_rn(x - __half2float(hx));
    __half ly = __float2half_rn(y - __half2float(hy));
    hi = ((uint32_t)__half_as_ushort(hy) << 16) | __half_as_ushort(hx);
    lo = ((uint32_t)__half_as_ushort(ly) << 16) | __half_as_ushort(lx);
}
__device__ __forceinline__ uint32_t pack_h2(float x, float y) {
    return ((uint32_t)__half_as_ushort(__float2half_rn(y)) << 16) |
           __half_as_ushort(__float2half_rn(x));
}

// ---------------- rope / gram / fold ----------------
__global__ void rope_kernel() {
    int s = blockIdx.x, d = threadIdx.x;
    int j = d & 31;
    double invf = exp(-log(10000.0) * (double)j / 32.0);
    double ang  = (double)s * invf;
    g_rope[s*HDIM + d] = (d < 32) ? (float)cos(ang) : (float)sin(ang);
}
__global__ void gram1_kernel() {
    int d = blockIdx.x, c = blockIdx.y, e = threadIdx.x;
    double acc = 0.0;
    const float* rp = g_rope + c*128*HDIM;
    for (int s = 0; s < 128; s++)
        acc += (double)rp[s*HDIM + d] * (double)rp[s*HDIM + e];
    g_Mpart[c][d*HDIM + e] = acc;
}
__global__ void gram2_kernel() {
    int d = blockIdx.x, e = threadIdx.x;
    double a = 0.0;
    #pragma unroll
    for (int c = 0; c < 16; c++) a += g_Mpart[c][d*HDIM + e];
    g_M[d*HDIM + e] = (float)a;
}
__global__ __launch_bounds__(256) void fold_kernel(const float* __restrict__ Wv) {
    __shared__ float Ms[HDIM*HDIM];
    __shared__ float wrow[DMODEL];
    int i = blockIdx.x;
    for (int t = threadIdx.x; t < HDIM*HDIM; t += blockDim.x) Ms[t] = g_M[t];
    for (int t = threadIdx.x; t < DMODEL;    t += blockDim.x) wrow[t] = Wv[(size_t)i*DMODEL + t];
    __syncthreads();
    for (int c = threadIdx.x; c < DMODEL; c += blockDim.x) {
        int h = c >> 6, e = c & 63;
        float acc = 0.f;
        #pragma unroll 8
        for (int d = 0; d < HDIM; d++) acc = fmaf(wrow[h*64 + d], Ms[d*64 + e], acc);
        g_Wvp[(size_t)i*DMODEL + c] = acc;
    }
}

// ---------------- hi/lo fp16 split of x ----------------
__global__ __launch_bounds__(256) void split_kernel(const float* __restrict__ src,
                                                    __half* __restrict__ hi,
                                                    __half* __restrict__ lo, int n4) {
    int i = blockIdx.x*blockDim.x + threadIdx.x;
    if (i >= n4) return;
    float4 v = ((const float4*)src)[i];
    uint32_t h0, l0, h1, l1;
    split_pack(v.x, v.y, h0, l0);
    split_pack(v.z, v.w, h1, l1);
    ((uint2*)hi)[i] = make_uint2(h0, h1);
    ((uint2*)lo)[i] = make_uint2(l0, l1);
}

// ---------------- transpose + round: W[K][N] -> T[N][K] fp16 --------------------
__global__ void tsplit_kernel(const float* __restrict__ W, __half* __restrict__ hi) {
    __shared__ float t[32][33];
    int x0 = blockIdx.x*32, y0 = blockIdx.y*32;
    int tx = threadIdx.x, ty = threadIdx.y;
    #pragma unroll
    for (int j = 0; j < 32; j += 8)
        t[ty+j][tx] = W[(size_t)(y0+ty+j)*DMODEL + x0+tx];
    __syncthreads();
    #pragma unroll
    for (int j = 0; j < 32; j += 8)
        hi[(size_t)(x0+ty+j)*DMODEL + y0+tx] = __float2half_rn(t[tx][ty+j]);
}

// ---------------- HMMA GEMM: C = (Ahi+Alo) @ Bh^T, fp16 x2, fp32 accum -----------
// MODE 0: merged QKV. blockIdx.x in [0,24): matrix mm = bc>>3, col tile bc&7.
//         Q -> hi/lo fp16 (scaled), K/V -> single fp16, split-head layout.
// MODE 1: attn @ Wo, fp32 row-major + bias.
#define ROWB     80
#define TILEB    (128*ROWB)
#define STAGEB   (3*TILEB)
#define SMEMB    (2*STAGEB)

template<int MODE>
__global__ __launch_bounds__(256) void hgemm_tc(const __half* __restrict__ Ahi,
                                                const __half* __restrict__ Alo,
                                                const __half* __restrict__ Bh,
                                                const float* __restrict__ bias,
                                                float* __restrict__ OUT,
                                                __half* __restrict__ QH,
                                                __half* __restrict__ QL,
                                                __half* __restrict__ KH,
                                                __half* __restrict__ VH)
{
    extern __shared__ char smem[];
    const uint32_t smem_base = smem_u32(smem);
    const int tid  = threadIdx.x;
    const int lane = tid & 31;
    const int wid  = tid >> 5;
    const int wm   = wid & 3;
    const int wn   = wid >> 2;
    const int br   = blockIdx.y, bc = blockIdx.x;

    const int lrow  = tid >> 2;
    const int chunk = tid & 3;

    const __half* A0h = Ahi + (size_t)(br*128 + lrow)*DMODEL + chunk*8;
    const __half* A0l = Alo + (size_t)(br*128 + lrow)*DMODEL + chunk*8;
    const __half* B0  = Bh  + (size_t)(bc*128 + lrow)*DMODEL + chunk*8;
    const size_t rstep = (size_t)64*DMODEL;

#define ISSUE(s_, buf_) do { \
    uint32_t sb = smem_base + (buf_)*STAGEB; \
    uint32_t d0 = sb + lrow*ROWB + chunk*16; \
    size_t  go = (size_t)(s_)*32; \
    CP16(d0,           A0h + go); \
    CP16(d0 + TILEB,   A0l + go); \
    CP16(d0 + 2*TILEB, B0  + go); \
    uint32_t d1 = d0 + 64*ROWB; \
    CP16(d1,           A0h + go + rstep); \
    CP16(d1 + TILEB,   A0l + go + rstep); \
    CP16(d1 + 2*TILEB, B0  + go + rstep); \
} while (0)

    float acc[2][8][4];
    #pragma unroll
    for (int i = 0; i < 2; i++)
        #pragma unroll
        for (int j = 0; j < 8; j++)
            #pragma unroll
            for (int e = 0; e < 4; e++) acc[i][j][e] = 0.f;

    const int m0 = wm*32, n0 = wn*64;
    const int lr = lane & 15, lh = lane >> 4;

    ISSUE(0, 0); CP_COMMIT();

    for (int s = 0; s < 32; s++) {
        if (s + 1 < 32) { ISSUE(s + 1, (s + 1) & 1); CP_COMMIT(); CP_WAIT1(); }
        else            { CP_WAIT0(); }
        __syncthreads();

        const uint32_t As = smem_base + (s & 1)*STAGEB;
        const uint32_t Bs = As + 2*TILEB;
        #pragma unroll
        for (int k = 0; k < 2; k++) {
            const uint32_t koff = k*32 + lh*16;
            uint32_t ahi[2][4], alo[2][4], bq[4][4];
            #pragma unroll
            for (int mi = 0; mi < 2; mi++) {
                LDSM4(ahi[mi], As + (m0 + mi*16 + lr)*ROWB + koff);
                LDSM4(alo[mi], As + TILEB + (m0 + mi*16 + lr)*ROWB + koff);
            }
            #pragma unroll
            for (int jg = 0; jg < 4; jg++)
                LDSM4(bq[jg], Bs + (n0 + jg*16 + lr)*ROWB + koff);
            #pragma unroll
            for (int mi = 0; mi < 2; mi++)
                #pragma unroll
                for (int j = 0; j < 8; j++) {
                    mma_f16(acc[mi][j], ahi[mi], bq[j>>1][j&1], bq[j>>1][(j&1)+2]);
                    mma_f16(acc[mi][j], alo[mi], bq[j>>1][j&1], bq[j>>1][(j&1)+2]);
                }
        }
        __syncthreads();
    }
#undef ISSUE

    // epilogue
    const int g = lane >> 2, t = lane & 3;
    int colbase = bc*128;
    int mm = 0;
    if (MODE == 0) { mm = bc >> 3; colbase = (bc & 7)*128; }
    #pragma unroll
    for (int mi = 0; mi < 2; mi++) {
        #pragma unroll
        for (int rr = 0; rr < 2; rr++) {
            const int row = br*128 + m0 + mi*16 + rr*8 + g;
            #pragma unroll
            for (int j = 0; j < 8; j++) {
                const int col = colbase + n0 + j*8 + t*2;
                float vx = acc[mi][j][rr*2 + 0];
                float vy = acc[mi][j][rr*2 + 1];
                if (MODE == 1) {
                    float2 v; v.x = vx + bias[col]; v.y = vy + bias[col + 1];
                    *(float2*)&OUT[(size_t)row*DMODEL + col] = v;
                } else {
                    int bi = row >> 11, tt = row & 2047;
                    int h = col >> 6, dd = col & 63;
                    size_t o = (((size_t)(bi*NHEADS + h))*TSEQ + tt)*HDIM + dd;
                    if (mm == 0) {
                        uint32_t ph, pl;
                        split_pack(vx*SCALE_Q, vy*SCALE_Q, ph, pl);
                        *(uint32_t*)&QH[o] = ph;
                        *(uint32_t*)&QL[o] = pl;
                    } else {
                        __half* P = (mm == 1) ? KH : VH;
                        *(uint32_t*)&P[o] = pack_h2(vx, vy);
                    }
                }
            }
        }
    }
}

// ---------------- HMMA flash attention -----------------------------------------
// 128 q-rows per CTA, 8 warps x 16 rows; 64-key blocks, double-buffered cp.async.
// S = (Qhi+Qlo) K^T (exp2 domain); O = (Phi+Plo) V ; fp32 online softmax.
#define ROWF   144
#define FQHI   0
#define FQLO   (128*ROWF)
#define FQTOT  (2*128*ROWF)      /* 36864 */
#define FKH    0
#define FVH    (64*ROWF)
#define FSTG   (2*64*ROWF)       /* 18432 */
#define FSMEM  (FQTOT + 2*FSTG)  /* 73728 */

__global__ __launch_bounds__(256, 2) void flash_hmma(
    const __half* __restrict__ qhi, const __half* __restrict__ qlo,
    const __half* __restrict__ kh,  const __half* __restrict__ vh,
    __half* __restrict__ ohi, __half* __restrict__ olo)
{
    extern __shared__ char fsm[];
    const uint32_t sb = smem_u32(fsm);
    const int tid = threadIdx.x, lane = tid & 31, wid = tid >> 5;
    const int bh = blockIdx.y, q0 = blockIdx.x*128;
    const int g = lane >> 2, t = lane & 3, lr = lane & 15, lh = lane >> 4;
    const int wq = wid*16;

    const size_t base = (size_t)bh*TSEQ*HDIM;
    const __half* qph = qhi + base + (size_t)q0*HDIM;
    const __half* qpl = qlo + base + (size_t)q0*HDIM;
    const __half* kp  = kh  + base;
    const __half* vp  = vh  + base;

    {
        int r = tid >> 1, c4 = (tid & 1)*4;
        #pragma unroll
        for (int u = 0; u < 4; u++) {
            CP16(sb + FQHI + r*ROWF + (c4+u)*16, qph + (size_t)r*HDIM + (c4+u)*8);
            CP16(sb + FQLO + r*ROWF + (c4+u)*16, qpl + (size_t)r*HDIM + (c4+u)*8);
        }
        CP_COMMIT();
    }

#define FISSUE(kb_, b_) do { \
    int r = tid >> 2, c2 = (tid & 3)*2; \
    uint32_t s0 = sb + FQTOT + (b_)*FSTG; \
    size_t go = (size_t)((kb_)*64 + r)*HDIM; \
    _Pragma("unroll") \
    for (int u = 0; u < 2; u++) { \
        CP16(s0 + FKH + r*ROWF + (c2+u)*16, kp + go + (c2+u)*8); \
        CP16(s0 + FVH + r*ROWF + (c2+u)*16, vp + go + (c2+u)*8); \
    } \
} while (0)

    FISSUE(0, 0); CP_COMMIT();
    CP_WAIT0(); __syncthreads();

    float oacc[8][4];
    #pragma unroll
    for (int j = 0; j < 8; j++)
        #pragma unroll
        for (int e = 0; e < 4; e++) oacc[j][e] = 0.f;
    const float NEGINF = __int_as_float(0xff800000);
    float m0 = NEGINF, m1 = NEGINF, l0 = 0.f, l1 = 0.f;

    for (int kb = 0; kb < 32; kb++) {
        if (kb + 1 < 32) { FISSUE(kb + 1, (kb + 1) & 1); CP_COMMIT(); CP_WAIT1(); }
        else             { CP_WAIT0(); }
        __syncthreads();

        const uint32_t SB = sb + FQTOT + (kb & 1)*FSTG;

        // ---- S = Q K^T (2-term), exp2 domain ----
        float sacc[8][4];
        #pragma unroll
        for (int j = 0; j < 8; j++)
            #pragma unroll
            for (int e = 0; e < 4; e++) sacc[j][e] = 0.f;

        #pragma unroll
        for (int kk = 0; kk < 4; kk++) {
            const uint32_t ko = kk*32 + lh*16;
            uint32_t aqh[4], aql[4];
            LDSM4(aqh, sb + FQHI + (wq + lr)*ROWF + ko);
            LDSM4(aql, sb + FQLO + (wq + lr)*ROWF + ko);
            #pragma unroll
            for (int jg = 0; jg < 4; jg++) {
                uint32_t bkh[4];
                LDSM4(bkh, SB + FKH + (jg*16 + lr)*ROWF + ko);
                #pragma unroll
                for (int j2 = 0; j2 < 2; j2++) {
                    float* c = sacc[jg*2 + j2];
                    mma_f16(c, aqh, bkh[j2], bkh[j2+2]);
                    mma_f16(c, aql, bkh[j2], bkh[j2+2]);
                }
            }
        }

        // ---- online softmax (exp2 domain) ----
        float nm0 = NEGINF, nm1 = NEGINF;
        #pragma unroll
        for (int j = 0; j < 8; j++) {
            nm0 = fmaxf(nm0, fmaxf(sacc[j][0], sacc[j][1]));
            nm1 = fmaxf(nm1, fmaxf(sacc[j][2], sacc[j][3]));
        }
        nm0 = fmaxf(nm0, __shfl_xor_sync(0xffffffffu, nm0, 1));
        nm0 = fmaxf(nm0, __shfl_xor_sync(0xffffffffu, nm0, 2));
        nm1 = fmaxf(nm1, __shfl_xor_sync(0xffffffffu, nm1, 1));
        nm1 = fmaxf(nm1, __shfl_xor_sync(0xffffffffu, nm1, 2));
        float M0 = fmaxf(m0, nm0), M1 = fmaxf(m1, nm1);
        bool changed = (M0 != m0) || (M1 != m1);
        float c0 = ex2f(m0 - M0), c1 = ex2f(m1 - M1);
        m0 = M0; m1 = M1;
        float rs0 = 0.f, rs1 = 0.f;
        #pragma unroll
        for (int j = 0; j < 8; j++) {
            sacc[j][0] = ex2f(sacc[j][0] - M0);
            sacc[j][1] = ex2f(sacc[j][1] - M0);
            sacc[j][2] = ex2f(sacc[j][2] - M1);
            sacc[j][3] = ex2f(sacc[j][3] - M1);
            rs0 += sacc[j][0] + sacc[j][1];
            rs1 += sacc[j][2] + sacc[j][3];
        }
        rs0 += __shfl_xor_sync(0xffffffffu, rs0, 1);
        rs0 += __shfl_xor_sync(0xffffffffu, rs0, 2);
        rs1 += __shfl_xor_sync(0xffffffffu, rs1, 1);
        rs1 += __shfl_xor_sync(0xffffffffu, rs1, 2);
        l0 = l0*c0 + rs0;
        l1 = l1*c1 + rs1;
        if (__any_sync(0xffffffffu, changed)) {
            #pragma unroll
            for (int j = 0; j < 8; j++) {
                oacc[j][0] *= c0; oacc[j][1] *= c0;
                oacc[j][2] *= c1; oacc[j][3] *= c1;
            }
        }

        // ---- O += P V (2-term); P repacked from S fragments ----
        const int vrow0 = ((lane >> 3) & 1)*8 + (lane & 7);
        const int vcsub = (lane >> 4)*8;
        #pragma unroll
        for (int kk = 0; kk < 4; kk++) {
            uint32_t ah[4], al[4];
            split_pack(sacc[2*kk][0],   sacc[2*kk][1],   ah[0], al[0]);
            split_pack(sacc[2*kk][2],   sacc[2*kk][3],   ah[1], al[1]);
            split_pack(sacc[2*kk+1][0], sacc[2*kk+1][1], ah[2], al[2]);
            split_pack(sacc[2*kk+1][2], sacc[2*kk+1][3], ah[3], al[3]);
            const uint32_t vr = (kk*16 + vrow0)*ROWF;
            #pragma unroll
            for (int jj = 0; jj < 4; jj++) {
                uint32_t bvh[4];
                LDSM4T(bvh, SB + FVH + vr + (jj*16 + vcsub)*2);
                #pragma unroll
                for (int j2 = 0; j2 < 2; j2++) {
                    float* o = oacc[jj*2 + j2];
                    mma_f16(o, ah, bvh[2*j2], bvh[2*j2+1]);
                    mma_f16(o, al, bvh[2*j2], bvh[2*j2+1]);
                }
            }
        }
        __syncthreads();
    }
#undef FISSUE

    const float inv0 = 1.f / l0, inv1 = 1.f / l1;
    const int b = bh >> 4, h = bh & 15;
    const int tok0 = b*TSEQ + q0 + wq + g;
    const int tok1 = tok0 + 8;
    #pragma unroll
    for (int j = 0; j < 8; j++) {
        const int col = h*64 + j*8 + t*2;
        uint32_t ph, pl;
        split_pack(oacc[j][0]*inv0, oacc[j][1]*inv0, ph, pl);
        *(uint32_t*)&ohi[(size_t)tok0*DMODEL + col] = ph;
        *(uint32_t*)&olo[(size_t)tok0*DMODEL + col] = pl;
        split_pack(oacc[j][2]*inv1, oacc[j][3]*inv1, ph, pl);
        *(uint32_t*)&ohi[(size_t)tok1*DMODEL + col] = ph;
        *(uint32_t*)&olo[(size_t)tok1*DMODEL + col] = pl;
    }
}

// ---------------- launch ----------------
extern "C" void kernel_launch(void* const* d_in, const int* in_sizes, int n_in,
                              void* d_out, int out_size)
{
    const float* x  = (const float*)d_in[0];
    const float* Wq = (const float*)d_in[1];
    const float* Wk = (const float*)d_in[2];
    const float* Wv = (const float*)d_in[3];
    const float* Wo = (const float*)d_in[4];
    const float* bo = (const float*)d_in[5];
    float* out = (float*)d_out;

    float* wvp;
    cudaGetSymbolAddress((void**)&wvp, g_Wvp);
    __half *xhi, *xlo, *wh, *ahi, *alo, *qhi, *qlo, *kh, *vh;
    cudaGetSymbolAddress((void**)&xhi, g_xhi);
    cudaGetSymbolAddress((void**)&xlo, g_xlo);
    cudaGetSymbolAddress((void**)&wh,  g_wh);
    cudaGetSymbolAddress((void**)&ahi, g_ahi);
    cudaGetSymbolAddress((void**)&alo, g_alo);
    cudaGetSymbolAddress((void**)&qhi, g_qhi);
    cudaGetSymbolAddress((void**)&qlo, g_qlo);
    cudaGetSymbolAddress((void**)&kh,  g_kh);
    cudaGetSymbolAddress((void**)&vh,  g_vh);

    const size_t WSZ = (size_t)DMODEL*DMODEL;

    rope_kernel<<<TSEQ, HDIM>>>();
    gram1_kernel<<<dim3(HDIM, 16), HDIM>>>();
    gram2_kernel<<<HDIM, HDIM>>>();
    fold_kernel<<<DMODEL, 256>>>(Wv);

    split_kernel<<<(BT*DMODEL/4 + 255)/256, 256>>>(x, xhi, xlo, BT*DMODEL/4);
    dim3 tg(DMODEL/32, DMODEL/32), tb(32, 8);
    tsplit_kernel<<<tg, tb>>>(Wq,  wh + 0*WSZ);
    tsplit_kernel<<<tg, tb>>>(Wk,  wh + 1*WSZ);
    tsplit_kernel<<<tg, tb>>>(wvp, wh + 2*WSZ);
    tsplit_kernel<<<tg, tb>>>(Wo,  wh + 3*WSZ);

    cudaFuncSetAttribute(hgemm_tc<0>, cudaFuncAttributeMaxDynamicSharedMemorySize, SMEMB);
    cudaFuncSetAttribute(hgemm_tc<1>, cudaFuncAttributeMaxDynamicSharedMemorySize, SMEMB);
    cudaFuncSetAttribute(flash_hmma, cudaFuncAttributeMaxDynamicSharedMemorySize, FSMEM);

    // merged QKV projection: grid.x = 24 (3 matrices x 8 col-tiles)
    hgemm_tc<0><<<dim3(24, BT/128), 256, SMEMB>>>(xhi, xlo, wh, nullptr, nullptr,
                                                  qhi, qlo, kh, vh);

    flash_hmma<<<dim3(TSEQ/128, BATCH*NHEADS), 256, FSMEM>>>(qhi, qlo, kh, vh, ahi, alo);

    hgemm_tc<1><<<dim3(8, BT/128), 256, SMEMB>>>(ahi, alo, wh + 3*WSZ, bo, out,
                                                 nullptr, nullptr, nullptr, nullptr);

    (void)in_sizes; (void)n_in; (void)out_size;
}

// round 9
// speedup vs baseline: 3.4382x; 1.0138x over previous
#include <cuda_runtime.h>
#include <cuda_fp16.h>
#include <math.h>
#include <stdint.h>

#define BATCH   2
#define TSEQ    2048
#define DMODEL  1024
#define NHEADS  16
#define HDIM    64
#define BT      (BATCH*TSEQ)   /* 4096 */
#define SCALE_Q 0.1803368801111137f   /* 0.125 * log2(e) */

// ---------------- scratch (static device arrays; no allocation) ----------------
__device__ float g_rope[TSEQ*HDIM];
__device__ double g_Mpart[16][HDIM*HDIM];
__device__ float g_M[HDIM*HDIM];
__device__ __half g_xhi[(size_t)BT*DMODEL];
__device__ __half g_xlo[(size_t)BT*DMODEL];
__device__ __half g_wh[4*(size_t)DMODEL*DMODEL];   // transposed weights [N][K], fp16
__device__ __half g_qhi[BATCH*NHEADS*TSEQ*HDIM];
__device__ __half g_qlo[BATCH*NHEADS*TSEQ*HDIM];
__device__ __half g_kh[BATCH*NHEADS*TSEQ*HDIM];
__device__ __half g_vh[BATCH*NHEADS*TSEQ*HDIM];
__device__ __half g_ahi[(size_t)BT*DMODEL];
__device__ __half g_alo[(size_t)BT*DMODEL];

// ---------------- PTX helpers (base ISA: cp.async / ldmatrix / mma.sync) --------
__device__ __forceinline__ uint32_t smem_u32(const void* p) {
    uint32_t a;
    asm("{ .reg .u64 t; cvta.to.shared.u64 t, %1; cvt.u32.u64 %0, t; }" : "=r"(a) : "l"(p));
    return a;
}
#define CP16(dst, src) asm volatile("cp.async.cg.shared.global [%0], [%1], 16;" :: "r"(dst), "l"(src))
#define CP_COMMIT()    asm volatile("cp.async.commit_group;" ::: "memory")
#define CP_WAIT1()     asm volatile("cp.async.wait_group 1;" ::: "memory")
#define CP_WAIT0()     asm volatile("cp.async.wait_group 0;" ::: "memory")
#define LDSM4(r, a) \
    asm volatile("ldmatrix.sync.aligned.m8n8.x4.shared.b16 {%0,%1,%2,%3}, [%4];" \
        : "=r"((r)[0]), "=r"((r)[1]), "=r"((r)[2]), "=r"((r)[3]) : "r"(a))
#define LDSM4T(r, a) \
    asm volatile("ldmatrix.sync.aligned.m8n8.x4.trans.shared.b16 {%0,%1,%2,%3}, [%4];" \
        : "=r"((r)[0]), "=r"((r)[1]), "=r"((r)[2]), "=r"((r)[3]) : "r"(a))
__device__ __forceinline__ void mma_f16(float* c, const uint32_t* a, uint32_t b0, uint32_t b1) {
    asm volatile("mma.sync.aligned.m16n8k16.row.col.f32.f16.f16.f32 "
                 "{%0,%1,%2,%3}, {%4,%5,%6,%7}, {%8,%9}, {%0,%1,%2,%3};"
                 : "+f"(c[0]), "+f"(c[1]), "+f"(c[2]), "+f"(c[3])
                 : "r"(a[0]), "r"(a[1]), "r"(a[2]), "r"(a[3]), "r"(b0), "r"(b1));
}
__device__ __forceinline__ float ex2f(float x) {
    float r; asm("ex2.approx.f32 %0, %1;" : "=f"(r) : "f"(x)); return r;
}
// split two floats into packed fp16 hi pair + lo (residual) pair, f16x2 cvt
__device__ __forceinline__ void split_pack(float x, float y, uint32_t& hi, uint32_t& lo) {
    __half2 h = __floats2half2_rn(x, y);
    float2 hf = __half22float2(h);
    __half2 l = __floats2half2_rn(x - hf.x, y - hf.y);
    hi = *(uint32_t*)&h;
    lo = *(uint32_t*)&l;
}
__device__ __forceinline__ uint32_t pack_h2(float x, float y) {
    __half2 h = __floats2half2_rn(x, y);
    return *(uint32_t*)&h;
}

// ---------------- rope / gram ----------------
__global__ void rope_kernel() {
    int s = blockIdx.x, d = threadIdx.x;
    int j = d & 31;
    double invf = exp(-log(10000.0) * (double)j / 32.0);
    double ang  = (double)s * invf;
    g_rope[s*HDIM + d] = (d < 32) ? (float)cos(ang) : (float)sin(ang);
}
__global__ void gram1_kernel() {
    int d = blockIdx.x, c = blockIdx.y, e = threadIdx.x;
    double acc = 0.0;
    const float* rp = g_rope + c*128*HDIM;
    for (int s = 0; s < 128; s++)
        acc += (double)rp[s*HDIM + d] * (double)rp[s*HDIM + e];
    g_Mpart[c][d*HDIM + e] = acc;
}
__global__ void gram2_kernel() {
    int d = blockIdx.x, e = threadIdx.x;
    double a = 0.0;
    #pragma unroll
    for (int c = 0; c < 16; c++) a += g_Mpart[c][d*HDIM + e];
    g_M[d*HDIM + e] = (float)a;
}

// ---------------- fused fold+transpose+fp16: wh[2] = (Wv @ blockdiag(M))^T -------
// out[n][k] = sum_d Wv[k][ (n>>6)*64 + d ] * M[d][ n&63 ],  fp16.
__global__ __launch_bounds__(256) void wvfold_kernel(const float* __restrict__ Wv,
                                                     __half* __restrict__ whv) {
    __shared__ float Wt[32][65];   // [k_local][d]
    __shared__ float Mt[64][33];   // [d][e_local]
    const int n0 = blockIdx.x*32, k0 = blockIdx.y*32;
    const int h0 = n0 >> 6;
    const int e0 = n0 & 63;        // 0 or 32 (32-tile never crosses a head)
    const int tid = threadIdx.x;
    for (int i = tid; i < 32*64; i += 256) {
        int r = i >> 6, c = i & 63;
        Wt[r][c] = Wv[(size_t)(k0 + r)*DMODEL + h0*64 + c];
    }
    for (int i = tid; i < 64*32; i += 256) {
        int d = i >> 5, e = i & 31;
        Mt[d][e] = g_M[d*HDIM + e0 + e];
    }
    __syncthreads();
    const int kl = tid & 31, nl0 = tid >> 5;
    #pragma unroll
    for (int u = 0; u < 4; u++) {
        int nl = nl0 + u*8;
        float acc = 0.f;
        #pragma unroll
        for (int d = 0; d < 64; d++) acc = fmaf(Wt[kl][d], Mt[d][nl], acc);
        whv[(size_t)(n0 + nl)*DMODEL + k0 + kl] = __float2half_rn(acc);
    }
}

// ---------------- hi/lo fp16 split of x ----------------
__global__ __launch_bounds__(256) void split_kernel(const float* __restrict__ src,
                                                    __half* __restrict__ hi,
                                                    __half* __restrict__ lo, int n4) {
    int i = blockIdx.x*blockDim.x + threadIdx.x;
    if (i >= n4) return;
    float4 v = ((const float4*)src)[i];
    uint32_t h0, l0, h1, l1;
    split_pack(v.x, v.y, h0, l0);
    split_pack(v.z, v.w, h1, l1);
    ((uint2*)hi)[i] = make_uint2(h0, h1);
    ((uint2*)lo)[i] = make_uint2(l0, l1);
}

// ---------------- batched transpose+round: {Wq,Wk,Wo} -> wh slots {0,1,3} --------
__global__ void tsplit3_kernel(const float* __restrict__ Wq,
                               const float* __restrict__ Wk,
                               const float* __restrict__ Wo,
                               __half* __restrict__ wh) {
    const int z = blockIdx.z;
    const float* W = (z == 0) ? Wq : (z == 1) ? Wk : Wo;
    __half* out = wh + (size_t)((z == 2) ? 3 : z)*DMODEL*DMODEL;
    __shared__ float t[32][33];
    int x0 = blockIdx.x*32, y0 = blockIdx.y*32;
    int tx = threadIdx.x, ty = threadIdx.y;
    #pragma unroll
    for (int j = 0; j < 32; j += 8)
        t[ty+j][tx] = W[(size_t)(y0+ty+j)*DMODEL + x0+tx];
    __syncthreads();
    #pragma unroll
    for (int j = 0; j < 32; j += 8)
        out[(size_t)(x0+ty+j)*DMODEL + y0+tx] = __float2half_rn(t[tx][ty+j]);
}

// ---------------- HMMA GEMM: C = (Ahi+Alo) @ Bh^T, fp16 x2, fp32 accum -----------
#define ROWB     80
#define TILEB    (128*ROWB)
#define STAGEB   (3*TILEB)
#define SMEMB    (2*STAGEB)

template<int MODE>
__global__ __launch_bounds__(256) void hgemm_tc(const __half* __restrict__ Ahi,
                                                const __half* __restrict__ Alo,
                                                const __half* __restrict__ Bh,
                                                const float* __restrict__ bias,
                                                float* __restrict__ OUT,
                                                __half* __restrict__ QH,
                                                __half* __restrict__ QL,
                                                __half* __restrict__ KH,
                                                __half* __restrict__ VH)
{
    extern __shared__ char smem[];
    const uint32_t smem_base = smem_u32(smem);
    const int tid  = threadIdx.x;
    const int lane = tid & 31;
    const int wid  = tid >> 5;
    const int wm   = wid & 3;
    const int wn   = wid >> 2;
    const int br   = blockIdx.y, bc = blockIdx.x;

    const int lrow  = tid >> 2;
    const int chunk = tid & 3;

    const __half* A0h = Ahi + (size_t)(br*128 + lrow)*DMODEL + chunk*8;
    const __half* A0l = Alo + (size_t)(br*128 + lrow)*DMODEL + chunk*8;
    const __half* B0  = Bh  + (size_t)(bc*128 + lrow)*DMODEL + chunk*8;
    const size_t rstep = (size_t)64*DMODEL;

#define ISSUE(s_, buf_) do { \
    uint32_t sb = smem_base + (buf_)*STAGEB; \
    uint32_t d0 = sb + lrow*ROWB + chunk*16; \
    size_t  go = (size_t)(s_)*32; \
    CP16(d0,           A0h + go); \
    CP16(d0 + TILEB,   A0l + go); \
    CP16(d0 + 2*TILEB, B0  + go); \
    uint32_t d1 = d0 + 64*ROWB; \
    CP16(d1,           A0h + go + rstep); \
    CP16(d1 + TILEB,   A0l + go + rstep); \
    CP16(d1 + 2*TILEB, B0  + go + rstep); \
} while (0)

    float acc[2][8][4];
    #pragma unroll
    for (int i = 0; i < 2; i++)
        #pragma unroll
        for (int j = 0; j < 8; j++)
            #pragma unroll
            for (int e = 0; e < 4; e++) acc[i][j][e] = 0.f;

    const int m0 = wm*32, n0 = wn*64;
    const int lr = lane & 15, lh = lane >> 4;

    ISSUE(0, 0); CP_COMMIT();

    for (int s = 0; s < 32; s++) {
        if (s + 1 < 32) { ISSUE(s + 1, (s + 1) & 1); CP_COMMIT(); CP_WAIT1(); }
        else            { CP_WAIT0(); }
        __syncthreads();

        const uint32_t As = smem_base + (s & 1)*STAGEB;
        const uint32_t Bs = As + 2*TILEB;
        #pragma unroll
        for (int k = 0; k < 2; k++) {
            const uint32_t koff = k*32 + lh*16;
            uint32_t ahi[2][4], alo[2][4], bq[4][4];
            #pragma unroll
            for (int mi = 0; mi < 2; mi++) {
                LDSM4(ahi[mi], As + (m0 + mi*16 + lr)*ROWB + koff);
                LDSM4(alo[mi], As + TILEB + (m0 + mi*16 + lr)*ROWB + koff);
            }
            #pragma unroll
            for (int jg = 0; jg < 4; jg++)
                LDSM4(bq[jg], Bs + (n0 + jg*16 + lr)*ROWB + koff);
            #pragma unroll
            for (int mi = 0; mi < 2; mi++)
                #pragma unroll
                for (int j = 0; j < 8; j++) {
                    mma_f16(acc[mi][j], ahi[mi], bq[j>>1][j&1], bq[j>>1][(j&1)+2]);
                    mma_f16(acc[mi][j], alo[mi], bq[j>>1][j&1], bq[j>>1][(j&1)+2]);
                }
        }
        __syncthreads();
    }
#undef ISSUE

    // epilogue
    const int g = lane >> 2, t = lane & 3;
    int colbase = bc*128;
    int mm = 0;
    if (MODE == 0) { mm = bc >> 3; colbase = (bc & 7)*128; }
    #pragma unroll
    for (int mi = 0; mi < 2; mi++) {
        #pragma unroll
        for (int rr = 0; rr < 2; rr++) {
            const int row = br*128 + m0 + mi*16 + rr*8 + g;
            #pragma unroll
            for (int j = 0; j < 8; j++) {
                const int col = colbase + n0 + j*8 + t*2;
                float vx = acc[mi][j][rr*2 + 0];
                float vy = acc[mi][j][rr*2 + 1];
                if (MODE == 1) {
                    float2 v; v.x = vx + bias[col]; v.y = vy + bias[col + 1];
                    *(float2*)&OUT[(size_t)row*DMODEL + col] = v;
                } else {
                    int bi = row >> 11, tt = row & 2047;
                    int h = col >> 6, dd = col & 63;
                    size_t o = (((size_t)(bi*NHEADS + h))*TSEQ + tt)*HDIM + dd;
                    if (mm == 0) {
                        uint32_t ph, pl;
                        split_pack(vx*SCALE_Q, vy*SCALE_Q, ph, pl);
                        *(uint32_t*)&QH[o] = ph;
                        *(uint32_t*)&QL[o] = pl;
                    } else {
                        __half* P = (mm == 1) ? KH : VH;
                        *(uint32_t*)&P[o] = pack_h2(vx, vy);
                    }
                }
            }
        }
    }
}

// ---------------- HMMA flash attention -----------------------------------------
#define ROWF   144
#define FQHI   0
#define FQLO   (128*ROWF)
#define FQTOT  (2*128*ROWF)      /* 36864 */
#define FKH    0
#define FVH    (64*ROWF)
#define FSTG   (2*64*ROWF)       /* 18432 */
#define FSMEM  (FQTOT + 2*FSTG)  /* 73728 */

__global__ __launch_bounds__(256, 2) void flash_hmma(
    const __half* __restrict__ qhi, const __half* __restrict__ qlo,
    const __half* __restrict__ kh,  const __half* __restrict__ vh,
    __half* __restrict__ ohi, __half* __restrict__ olo)
{
    extern __shared__ char fsm[];
    const uint32_t sb = smem_u32(fsm);
    const int tid = threadIdx.x, lane = tid & 31, wid = tid >> 5;
    const int bh = blockIdx.y, q0 = blockIdx.x*128;
    const int g = lane >> 2, t = lane & 3, lr = lane & 15, lh = lane >> 4;
    const int wq = wid*16;

    const size_t base = (size_t)bh*TSEQ*HDIM;
    const __half* qph = qhi + base + (size_t)q0*HDIM;
    const __half* qpl = qlo + base + (size_t)q0*HDIM;
    const __half* kp  = kh  + base;
    const __half* vp  = vh  + base;

    {
        int r = tid >> 1, c4 = (tid & 1)*4;
        #pragma unroll
        for (int u = 0; u < 4; u++) {
            CP16(sb + FQHI + r*ROWF + (c4+u)*16, qph + (size_t)r*HDIM + (c4+u)*8);
            CP16(sb + FQLO + r*ROWF + (c4+u)*16, qpl + (size_t)r*HDIM + (c4+u)*8);
        }
        CP_COMMIT();
    }

#define FISSUE(kb_, b_) do { \
    int r = tid >> 2, c2 = (tid & 3)*2; \
    uint32_t s0 = sb + FQTOT + (b_)*FSTG; \
    size_t go = (size_t)((kb_)*64 + r)*HDIM; \
    _Pragma("unroll") \
    for (int u = 0; u < 2; u++) { \
        CP16(s0 + FKH + r*ROWF + (c2+u)*16, kp + go + (c2+u)*8); \
        CP16(s0 + FVH + r*ROWF + (c2+u)*16, vp + go + (c2+u)*8); \
    } \
} while (0)

    FISSUE(0, 0); CP_COMMIT();
    CP_WAIT0(); __syncthreads();

    float oacc[8][4];
    #pragma unroll
    for (int j = 0; j < 8; j++)
        #pragma unroll
        for (int e = 0; e < 4; e++) oacc[j][e] = 0.f;
    const float NEGINF = __int_as_float(0xff800000);
    float m0 = NEGINF, m1 = NEGINF, l0 = 0.f, l1 = 0.f;

    for (int kb = 0; kb < 32; kb++) {
        if (kb + 1 < 32) { FISSUE(kb + 1, (kb + 1) & 1); CP_COMMIT(); CP_WAIT1(); }
        else             { CP_WAIT0(); }
        __syncthreads();

        const uint32_t SB = sb + FQTOT + (kb & 1)*FSTG;

        // ---- S = Q K^T (2-term), exp2 domain ----
        float sacc[8][4];
        #pragma unroll
        for (int j = 0; j < 8; j++)
            #pragma unroll
            for (int e = 0; e < 4; e++) sacc[j][e] = 0.f;

        #pragma unroll
        for (int kk = 0; kk < 4; kk++) {
            const uint32_t ko = kk*32 + lh*16;
            uint32_t aqh[4], aql[4];
            LDSM4(aqh, sb + FQHI + (wq + lr)*ROWF + ko);
            LDSM4(aql, sb + FQLO + (wq + lr)*ROWF + ko);
            #pragma unroll
            for (int jg = 0; jg < 4; jg++) {
                uint32_t bkh[4];
                LDSM4(bkh, SB + FKH + (jg*16 + lr)*ROWF + ko);
                #pragma unroll
                for (int j2 = 0; j2 < 2; j2++) {
                    float* c = sacc[jg*2 + j2];
                    mma_f16(c, aqh, bkh[j2], bkh[j2+2]);
                    mma_f16(c, aql, bkh[j2], bkh[j2+2]);
                }
            }
        }

        // ---- online softmax (exp2 domain) ----
        float nm0 = NEGINF, nm1 = NEGINF;
        #pragma unroll
        for (int j = 0; j < 8; j++) {
            nm0 = fmaxf(nm0, fmaxf(sacc[j][0], sacc[j][1]));
            nm1 = fmaxf(nm1, fmaxf(sacc[j][2], sacc[j][3]));
        }
        nm0 = fmaxf(nm0, __shfl_xor_sync(0xffffffffu, nm0, 1));
        nm0 = fmaxf(nm0, __shfl_xor_sync(0xffffffffu, nm0, 2));
        nm1 = fmaxf(nm1, __shfl_xor_sync(0xffffffffu, nm1, 1));
        nm1 = fmaxf(nm1, __shfl_xor_sync(0xffffffffu, nm1, 2));
        float M0 = fmaxf(m0, nm0), M1 = fmaxf(m1, nm1);
        bool changed = (M0 != m0) || (M1 != m1);
        float c0 = ex2f(m0 - M0), c1 = ex2f(m1 - M1);
        m0 = M0; m1 = M1;
        float rs0 = 0.f, rs1 = 0.f;
        #pragma unroll
        for (int j = 0; j < 8; j++) {
            sacc[j][0] = ex2f(sacc[j][0] - M0);
            sacc[j][1] = ex2f(sacc[j][1] - M0);
            sacc[j][2] = ex2f(sacc[j][2] - M1);
            sacc[j][3] = ex2f(sacc[j][3] - M1);
            rs0 += sacc[j][0] + sacc[j][1];
            rs1 += sacc[j][2] + sacc[j][3];
        }
        rs0 += __shfl_xor_sync(0xffffffffu, rs0, 1);
        rs0 += __shfl_xor_sync(0xffffffffu, rs0, 2);
        rs1 += __shfl_xor_sync(0xffffffffu, rs1, 1);
        rs1 += __shfl_xor_sync(0xffffffffu, rs1, 2);
        l0 = l0*c0 + rs0;
        l1 = l1*c1 + rs1;
        if (__any_sync(0xffffffffu, changed)) {
            #pragma unroll
            for (int j = 0; j < 8; j++) {
                oacc[j][0] *= c0; oacc[j][1] *= c0;
                oacc[j][2] *= c1; oacc[j][3] *= c1;
            }
        }

        // ---- O += P V (2-term); P repacked from S fragments ----
        const int vrow0 = ((lane >> 3) & 1)*8 + (lane & 7);
        const int vcsub = (lane >> 4)*8;
        #pragma unroll
        for (int kk = 0; kk < 4; kk++) {
            uint32_t ah[4], al[4];
            split_pack(sacc[2*kk][0],   sacc[2*kk][1],   ah[0], al[0]);
            split_pack(sacc[2*kk][2],   sacc[2*kk][3],   ah[1], al[1]);
            split_pack(sacc[2*kk+1][0], sacc[2*kk+1][1], ah[2], al[2]);
            split_pack(sacc[2*kk+1][2], sacc[2*kk+1][3], ah[3], al[3]);
            const uint32_t vr = (kk*16 + vrow0)*ROWF;
            #pragma unroll
            for (int jj = 0; jj < 4; jj++) {
                uint32_t bvh[4];
                LDSM4T(bvh, SB + FVH + vr + (jj*16 + vcsub)*2);
                #pragma unroll
                for (int j2 = 0; j2 < 2; j2++) {
                    float* o = oacc[jj*2 + j2];
                    mma_f16(o, ah, bvh[2*j2], bvh[2*j2+1]);
                    mma_f16(o, al, bvh[2*j2], bvh[2*j2+1]);
                }
            }
        }
        __syncthreads();
    }
#undef FISSUE

    const float inv0 = 1.f / l0, inv1 = 1.f / l1;
    const int b = bh >> 4, h = bh & 15;
    const int tok0 = b*TSEQ + q0 + wq + g;
    const int tok1 = tok0 + 8;
    #pragma unroll
    for (int j = 0; j < 8; j++) {
        const int col = h*64 + j*8 + t*2;
        uint32_t ph, pl;
        split_pack(oacc[j][0]*inv0, oacc[j][1]*inv0, ph, pl);
        *(uint32_t*)&ohi[(size_t)tok0*DMODEL + col] = ph;
        *(uint32_t*)&olo[(size_t)tok0*DMODEL + col] = pl;
        split_pack(oacc[j][2]*inv1, oacc[j][3]*inv1, ph, pl);
        *(uint32_t*)&ohi[(size_t)tok1*DMODEL + col] = ph;
        *(uint32_t*)&olo[(size_t)tok1*DMODEL + col] = pl;
    }
}

// ---------------- launch ----------------
extern "C" void kernel_launch(void* const* d_in, const int* in_sizes, int n_in,
                              void* d_out, int out_size)
{
    const float* x  = (const float*)d_in[0];
    const float* Wq = (const float*)d_in[1];
    const float* Wk = (const float*)d_in[2];
    const float* Wv = (const float*)d_in[3];
    const float* Wo = (const float*)d_in[4];
    const float* bo = (const float*)d_in[5];
    float* out = (float*)d_out;

    __half *xhi, *xlo, *wh, *ahi, *alo, *qhi, *qlo, *kh, *vh;
    cudaGetSymbolAddress((void**)&xhi, g_xhi);
    cudaGetSymbolAddress((void**)&xlo, g_xlo);
    cudaGetSymbolAddress((void**)&wh,  g_wh);
    cudaGetSymbolAddress((void**)&ahi, g_ahi);
    cudaGetSymbolAddress((void**)&alo, g_alo);
    cudaGetSymbolAddress((void**)&qhi, g_qhi);
    cudaGetSymbolAddress((void**)&qlo, g_qlo);
    cudaGetSymbolAddress((void**)&kh,  g_kh);
    cudaGetSymbolAddress((void**)&vh,  g_vh);

    const size_t WSZ = (size_t)DMODEL*DMODEL;

    // independent prep first (no rope dependency)
    split_kernel<<<(BT*DMODEL/4 + 255)/256, 256>>>(x, xhi, xlo, BT*DMODEL/4);
    tsplit3_kernel<<<dim3(32, 32, 3), dim3(32, 8)>>>(Wq, Wk, Wo, wh);

    // rope -> gram -> folded V weight (fp16 transposed, direct)
    rope_kernel<<<TSEQ, HDIM>>>();
    gram1_kernel<<<dim3(HDIM, 16), HDIM>>>();
    gram2_kernel<<<HDIM, HDIM>>>();
    wvfold_kernel<<<dim3(32, 32), 256>>>(Wv, wh + 2*WSZ);

    cudaFuncSetAttribute(hgemm_tc<0>, cudaFuncAttributeMaxDynamicSharedMemorySize, SMEMB);
    cudaFuncSetAttribute(hgemm_tc<1>, cudaFuncAttributeMaxDynamicSharedMemorySize, SMEMB);
    cudaFuncSetAttribute(flash_hmma, cudaFuncAttributeMaxDynamicSharedMemorySize, FSMEM);

    // merged QKV projection: grid.x = 24 (3 matrices x 8 col-tiles)
    hgemm_tc<0><<<dim3(24, BT/128), 256, SMEMB>>>(xhi, xlo, wh, nullptr, nullptr,
                                                  qhi, qlo, kh, vh);

    flash_hmma<<<dim3(TSEQ/128, BATCH*NHEADS), 256, FSMEM>>>(qhi, qlo, kh, vh, ahi, alo);

    hgemm_tc<1><<<dim3(8, BT/128), 256, SMEMB>>>(ahi, alo, wh + 3*WSZ, bo, out,
                                                 nullptr, nullptr, nullptr, nullptr);

    (void)in_sizes; (void)n_in; (void)out_size;
}

// round 11
// speedup vs baseline: 3.7639x; 1.0947x over previous
#include <cuda_runtime.h>
#include <cuda_fp16.h>
#include <math.h>
#include <stdint.h>

#define BATCH   2
#define TSEQ    2048
#define DMODEL  1024
#define NHEADS  16
#define HDIM    64
#define BT      (BATCH*TSEQ)   /* 4096 */
#define SCALE_Q 0.1803368801111137f   /* 0.125 * log2(e) */

// ---------------- scratch (static device arrays; no allocation) ----------------
__device__ float g_rope[TSEQ*HDIM];
__device__ double g_invf[32];
__device__ float g_MpartF[16][HDIM*HDIM];
__device__ float g_M[HDIM*HDIM];
__device__ __half g_xhi[(size_t)BT*DMODEL];
__device__ __half g_xlo[(size_t)BT*DMODEL];
__device__ __half g_wh[4*(size_t)DMODEL*DMODEL];   // transposed weights [N][K], fp16
__device__ __half g_qhi[BATCH*NHEADS*TSEQ*HDIM];
__device__ __half g_qlo[BATCH*NHEADS*TSEQ*HDIM];
__device__ __half g_kh[BATCH*NHEADS*TSEQ*HDIM];
__device__ __half g_vh[BATCH*NHEADS*TSEQ*HDIM];
__device__ __half g_ahi[(size_t)BT*DMODEL];
__device__ __half g_alo[(size_t)BT*DMODEL];

// ---------------- PTX helpers (base ISA: cp.async / ldmatrix / mma.sync) --------
__device__ __forceinline__ uint32_t smem_u32(const void* p) {
    uint32_t a;
    asm("{ .reg .u64 t; cvta.to.shared.u64 t, %1; cvt.u32.u64 %0, t; }" : "=r"(a) : "l"(p));
    return a;
}
#define CP16(dst, src) asm volatile("cp.async.cg.shared.global [%0], [%1], 16;" :: "r"(dst), "l"(src))
#define CP_COMMIT()    asm volatile("cp.async.commit_group;" ::: "memory")
#define CP_WAIT1()     asm volatile("cp.async.wait_group 1;" ::: "memory")
#define CP_WAIT0()     asm volatile("cp.async.wait_group 0;" ::: "memory")
#define LDSM4(r, a) \
    asm volatile("ldmatrix.sync.aligned.m8n8.x4.shared.b16 {%0,%1,%2,%3}, [%4];" \
        : "=r"((r)[0]), "=r"((r)[1]), "=r"((r)[2]), "=r"((r)[3]) : "r"(a))
#define LDSM4T(r, a) \
    asm volatile("ldmatrix.sync.aligned.m8n8.x4.trans.shared.b16 {%0,%1,%2,%3}, [%4];" \
        : "=r"((r)[0]), "=r"((r)[1]), "=r"((r)[2]), "=r"((r)[3]) : "r"(a))
__device__ __forceinline__ void mma_f16(float* c, const uint32_t* a, uint32_t b0, uint32_t b1) {
    asm volatile("mma.sync.aligned.m16n8k16.row.col.f32.f16.f16.f32 "
                 "{%0,%1,%2,%3}, {%4,%5,%6,%7}, {%8,%9}, {%0,%1,%2,%3};"
                 : "+f"(c[0]), "+f"(c[1]), "+f"(c[2]), "+f"(c[3])
                 : "r"(a[0]), "r"(a[1]), "r"(a[2]), "r"(a[3]), "r"(b0), "r"(b1));
}
__device__ __forceinline__ float ex2f(float x) {
    float r; asm("ex2.approx.f32 %0, %1;" : "=f"(r) : "f"(x)); return r;
}
// split two floats into packed fp16 hi pair + lo (residual) pair, f16x2 cvt
__device__ __forceinline__ void split_pack(float x, float y, uint32_t& hi, uint32_t& lo) {
    __half2 h = __floats2half2_rn(x, y);
    float2 hf = __half22float2(h);
    __half2 l = __floats2half2_rn(x - hf.x, y - hf.y);
    hi = *(uint32_t*)&h;
    lo = *(uint32_t*)&l;
}
__device__ __forceinline__ uint32_t pack_h2(float x, float y) {
    __half2 h = __floats2half2_rn(x, y);
    return *(uint32_t*)&h;
}

// ---------------- rope / gram ----------------
__global__ void invf_kernel() {
    int j = threadIdx.x;
    g_invf[j] = exp(-log(10000.0) * (double)j / 32.0);
}
__global__ void rope_kernel() {
    int s = blockIdx.x, d = threadIdx.x;
    double ang = (double)s * g_invf[d & 31];
    g_rope[s*HDIM + d] = (d < 32) ? (float)cos(ang) : (float)sin(ang);
}
// Gram partials, fp32: 16 blocks x 256 threads; each block one 128-row chunk.
__global__ __launch_bounds__(256) void gram1_kernel() {
    __shared__ float R[128][68];
    const int c = blockIdx.x, tid = threadIdx.x;
    const float* rp = g_rope + (size_t)c*128*HDIM;
    for (int i = tid; i < 128*16; i += 256) {
        int r = i >> 4, q = i & 15;
        *(float4*)&R[r][q*4] = *(const float4*)(rp + r*HDIM + q*4);
    }
    __syncthreads();
    const int d0 = (tid & 15)*4, e0 = (tid >> 4)*4;
    float acc[4][4] = {};
    #pragma unroll 4
    for (int s = 0; s < 128; s++) {
        float4 a = *(const float4*)&R[s][d0];
        float4 b = *(const float4*)&R[s][e0];
        acc[0][0] = fmaf(a.x, b.x, acc[0][0]); acc[0][1] = fmaf(a.x, b.y, acc[0][1]);
        acc[0][2] = fmaf(a.x, b.z, acc[0][2]); acc[0][3] = fmaf(a.x, b.w, acc[0][3]);
        acc[1][0] = fmaf(a.y, b.x, acc[1][0]); acc[1][1] = fmaf(a.y, b.y, acc[1][1]);
        acc[1][2] = fmaf(a.y, b.z, acc[1][2]); acc[1][3] = fmaf(a.y, b.w, acc[1][3]);
        acc[2][0] = fmaf(a.z, b.x, acc[2][0]); acc[2][1] = fmaf(a.z, b.y, acc[2][1]);
        acc[2][2] = fmaf(a.z, b.z, acc[2][2]); acc[2][3] = fmaf(a.z, b.w, acc[2][3]);
        acc[3][0] = fmaf(a.w, b.x, acc[3][0]); acc[3][1] = fmaf(a.w, b.y, acc[3][1]);
        acc[3][2] = fmaf(a.w, b.z, acc[3][2]); acc[3][3] = fmaf(a.w, b.w, acc[3][3]);
    }
    #pragma unroll
    for (int i = 0; i < 4; i++)
        #pragma unroll
        for (int j = 0; j < 4; j++)
            g_MpartF[c][(d0 + i)*HDIM + e0 + j] = acc[i][j];
}
__global__ void gram2_kernel() {
    int d = blockIdx.x, e = threadIdx.x;
    float a = 0.f;
    #pragma unroll
    for (int c = 0; c < 16; c++) a += g_MpartF[c][d*HDIM + e];
    g_M[d*HDIM + e] = a;
}

// ---------------- fused fold+transpose+fp16: wh[2] = (Wv @ blockdiag(M))^T -------
__global__ __launch_bounds__(256) void wvfold_kernel(const float* __restrict__ Wv,
                                                     __half* __restrict__ whv) {
    __shared__ float Wt[32][65];   // [k_local][d]
    __shared__ float Mt[64][33];   // [d][e_local]
    const int n0 = blockIdx.x*32, k0 = blockIdx.y*32;
    const int h0 = n0 >> 6;
    const int e0 = n0 & 63;
    const int tid = threadIdx.x;
    for (int i = tid; i < 32*64; i += 256) {
        int r = i >> 6, c = i & 63;
        Wt[r][c] = Wv[(size_t)(k0 + r)*DMODEL + h0*64 + c];
    }
    for (int i = tid; i < 64*32; i += 256) {
        int d = i >> 5, e = i & 31;
        Mt[d][e] = g_M[d*HDIM + e0 + e];
    }
    __syncthreads();
    const int kl = tid & 31, nl0 = tid >> 5;
    #pragma unroll
    for (int u = 0; u < 4; u++) {
        int nl = nl0 + u*8;
        float acc = 0.f;
        #pragma unroll
        for (int d = 0; d < 64; d++) acc = fmaf(Wt[kl][d], Mt[d][nl], acc);
        whv[(size_t)(n0 + nl)*DMODEL + k0 + kl] = __float2half_rn(acc);
    }
}

// ---------------- hi/lo fp16 split of x ----------------
__global__ __launch_bounds__(256) void split_kernel(const float* __restrict__ src,
                                                    __half* __restrict__ hi,
                                                    __half* __restrict__ lo, int n4) {
    int i = blockIdx.x*blockDim.x + threadIdx.x;
    if (i >= n4) return;
    float4 v = ((const float4*)src)[i];
    uint32_t h0, l0, h1, l1;
    split_pack(v.x, v.y, h0, l0);
    split_pack(v.z, v.w, h1, l1);
    ((uint2*)hi)[i] = make_uint2(h0, h1);
    ((uint2*)lo)[i] = make_uint2(l0, l1);
}

// ---------------- batched transpose+round: {Wq,Wk,Wo} -> wh slots {0,1,3} --------
__global__ void tsplit3_kernel(const float* __restrict__ Wq,
                               const float* __restrict__ Wk,
                               const float* __restrict__ Wo,
                               __half* __restrict__ wh) {
    const int z = blockIdx.z;
    const float* W = (z == 0) ? Wq : (z == 1) ? Wk : Wo;
    __half* out = wh + (size_t)((z == 2) ? 3 : z)*DMODEL*DMODEL;
    __shared__ float t[32][33];
    int x0 = blockIdx.x*32, y0 = blockIdx.y*32;
    int tx = threadIdx.x, ty = threadIdx.y;
    #pragma unroll
    for (int j = 0; j < 32; j += 8)
        t[ty+j][tx] = W[(size_t)(y0+ty+j)*DMODEL + x0+tx];
    __syncthreads();
    #pragma unroll
    for (int j = 0; j < 32; j += 8)
        out[(size_t)(x0+ty+j)*DMODEL + y0+tx] = __float2half_rn(t[tx][ty+j]);
}

// ---------------- HMMA GEMM: C = (Ahi+Alo) @ Bh^T, fp16 x2, fp32 accum -----------
#define ROWB     80
#define TILEB    (128*ROWB)
#define STAGEB   (3*TILEB)
#define SMEMB    (2*STAGEB)

template<int MODE>
__global__ __launch_bounds__(256) void hgemm_tc(const __half* __restrict__ Ahi,
                                                const __half* __restrict__ Alo,
                                                const __half* __restrict__ Bh,
                                                const float* __restrict__ bias,
                                                float* __restrict__ OUT,
                                                __half* __restrict__ QH,
                                                __half* __restrict__ QL,
                                                __half* __restrict__ KH,
                                                __half* __restrict__ VH)
{
    extern __shared__ char smem[];
    const uint32_t smem_base = smem_u32(smem);
    const int tid  = threadIdx.x;
    const int lane = tid & 31;
    const int wid  = tid >> 5;
    const int wm   = wid & 3;
    const int wn   = wid >> 2;
    const int br   = blockIdx.y, bc = blockIdx.x;

    const int lrow  = tid >> 2;
    const int chunk = tid & 3;

    const __half* A0h = Ahi + (size_t)(br*128 + lrow)*DMODEL + chunk*8;
    const __half* A0l = Alo + (size_t)(br*128 + lrow)*DMODEL + chunk*8;
    const __half* B0  = Bh  + (size_t)(bc*128 + lrow)*DMODEL + chunk*8;
    const size_t rstep = (size_t)64*DMODEL;

#define ISSUE(s_, buf_) do { \
    uint32_t sb = smem_base + (buf_)*STAGEB; \
    uint32_t d0 = sb + lrow*ROWB + chunk*16; \
    size_t  go = (size_t)(s_)*32; \
    CP16(d0,           A0h + go); \
    CP16(d0 + TILEB,   A0l + go); \
    CP16(d0 + 2*TILEB, B0  + go); \
    uint32_t d1 = d0 + 64*ROWB; \
    CP16(d1,           A0h + go + rstep); \
    CP16(d1 + TILEB,   A0l + go + rstep); \
    CP16(d1 + 2*TILEB, B0  + go + rstep); \
} while (0)

    float acc[2][8][4];
    #pragma unroll
    for (int i = 0; i < 2; i++)
        #pragma unroll
        for (int j = 0; j < 8; j++)
            #pragma unroll
            for (int e = 0; e < 4; e++) acc[i][j][e] = 0.f;

    const int m0 = wm*32, n0 = wn*64;
    const int lr = lane & 15, lh = lane >> 4;

    ISSUE(0, 0); CP_COMMIT();

    for (int s = 0; s < 32; s++) {
        if (s + 1 < 32) { ISSUE(s + 1, (s + 1) & 1); CP_COMMIT(); CP_WAIT1(); }
        else            { CP_WAIT0(); }
        __syncthreads();

        const uint32_t As = smem_base + (s & 1)*STAGEB;
        const uint32_t Bs = As + 2*TILEB;
        #pragma unroll
        for (int k = 0; k < 2; k++) {
            const uint32_t koff = k*32 + lh*16;
            uint32_t ahi[2][4], alo[2][4], bq[4][4];
            #pragma unroll
            for (int mi = 0; mi < 2; mi++) {
                LDSM4(ahi[mi], As + (m0 + mi*16 + lr)*ROWB + koff);
                LDSM4(alo[mi], As + TILEB + (m0 + mi*16 + lr)*ROWB + koff);
            }
            #pragma unroll
            for (int jg = 0; jg < 4; jg++)
                LDSM4(bq[jg], Bs + (n0 + jg*16 + lr)*ROWB + koff);
            #pragma unroll
            for (int mi = 0; mi < 2; mi++)
                #pragma unroll
                for (int j = 0; j < 8; j++) {
                    mma_f16(acc[mi][j], ahi[mi], bq[j>>1][j&1], bq[j>>1][(j&1)+2]);
                    mma_f16(acc[mi][j], alo[mi], bq[j>>1][j&1], bq[j>>1][(j&1)+2]);
                }
        }
        __syncthreads();
    }
#undef ISSUE

    // epilogue
    const int g = lane >> 2, t = lane & 3;
    int colbase = bc*128;
    int mm = 0;
    if (MODE == 0) { mm = bc >> 3; colbase = (bc & 7)*128; }
    #pragma unroll
    for (int mi = 0; mi < 2; mi++) {
        #pragma unroll
        for (int rr = 0; rr < 2; rr++) {
            const int row = br*128 + m0 + mi*16 + rr*8 + g;
            #pragma unroll
            for (int j = 0; j < 8; j++) {
                const int col = colbase + n0 + j*8 + t*2;
                float vx = acc[mi][j][rr*2 + 0];
                float vy = acc[mi][j][rr*2 + 1];
                if (MODE == 1) {
                    float2 v; v.x = vx + bias[col]; v.y = vy + bias[col + 1];
                    *(float2*)&OUT[(size_t)row*DMODEL + col] = v;
                } else {
                    int bi = row >> 11, tt = row & 2047;
                    int h = col >> 6, dd = col & 63;
                    size_t o = (((size_t)(bi*NHEADS + h))*TSEQ + tt)*HDIM + dd;
                    if (mm == 0) {
                        uint32_t ph, pl;
                        split_pack(vx*SCALE_Q, vy*SCALE_Q, ph, pl);
                        *(uint32_t*)&QH[o] = ph;
                        *(uint32_t*)&QL[o] = pl;
                    } else {
                        __half* P = (mm == 1) ? KH : VH;
                        *(uint32_t*)&P[o] = pack_h2(vx, vy);
                    }
                }
            }
        }
    }
}

// ---------------- HMMA flash attention -----------------------------------------
#define ROWF   144
#define FQHI   0
#define FQLO   (128*ROWF)
#define FQTOT  (2*128*ROWF)      /* 36864 */
#define FKH    0
#define FVH    (64*ROWF)
#define FSTG   (2*64*ROWF)       /* 18432 */
#define FSMEM  (FQTOT + 2*FSTG)  /* 73728 */

__global__ __launch_bounds__(256, 2) void flash_hmma(
    const __half* __restrict__ qhi, const __half* __restrict__ qlo,
    const __half* __restrict__ kh,  const __half* __restrict__ vh,
    __half* __restrict__ ohi, __half* __restrict__ olo)
{
    extern __shared__ char fsm[];
    const uint32_t sb = smem_u32(fsm);
    const int tid = threadIdx.x, lane = tid & 31, wid = tid >> 5;
    const int bh = blockIdx.y, q0 = blockIdx.x*128;
    const int g = lane >> 2, t = lane & 3, lr = lane & 15, lh = lane >> 4;
    const int wq = wid*16;

    const size_t base = (size_t)bh*TSEQ*HDIM;
    const __half* qph = qhi + base + (size_t)q0*HDIM;
    const __half* qpl = qlo + base + (size_t)q0*HDIM;
    const __half* kp  = kh  + base;
    const __half* vp  = vh  + base;

    {
        int r = tid >> 1, c4 = (tid & 1)*4;
        #pragma unroll
        for (int u = 0; u < 4; u++) {
            CP16(sb + FQHI + r*ROWF + (c4+u)*16, qph + (size_t)r*HDIM + (c4+u)*8);
            CP16(sb + FQLO + r*ROWF + (c4+u)*16, qpl + (size_t)r*HDIM + (c4+u)*8);
        }
        CP_COMMIT();
    }

#define FISSUE(kb_, b_) do { \
    int r = tid >> 2, c2 = (tid & 3)*2; \
    uint32_t s0 = sb + FQTOT + (b_)*FSTG; \
    size_t go = (size_t)((kb_)*64 + r)*HDIM; \
    _Pragma("unroll") \
    for (int u = 0; u < 2; u++) { \
        CP16(s0 + FKH + r*ROWF + (c2+u)*16, kp + go + (c2+u)*8); \
        CP16(s0 + FVH + r*ROWF + (c2+u)*16, vp + go + (c2+u)*8); \
    } \
} while (0)

    FISSUE(0, 0); CP_COMMIT();
    CP_WAIT0(); __syncthreads();

    float oacc[8][4];
    #pragma unroll
    for (int j = 0; j < 8; j++)
        #pragma unroll
        for (int e = 0; e < 4; e++) oacc[j][e] = 0.f;
    const float NEGINF = __int_as_float(0xff800000);
    float m0 = NEGINF, m1 = NEGINF, l0 = 0.f, l1 = 0.f;

    for (int kb = 0; kb < 32; kb++) {
        if (kb + 1 < 32) { FISSUE(kb + 1, (kb + 1) & 1); CP_COMMIT(); CP_WAIT1(); }
        else             { CP_WAIT0(); }
        __syncthreads();

        const uint32_t SB = sb + FQTOT + (kb & 1)*FSTG;

        // ---- S = Q K^T (2-term), exp2 domain ----
        float sacc[8][4];
        #pragma unroll
        for (int j = 0; j < 8; j++)
            #pragma unroll
            for (int e = 0; e < 4; e++) sacc[j][e] = 0.f;

        #pragma unroll
        for (int kk = 0; kk < 4; kk++) {
            const uint32_t ko = kk*32 + lh*16;
            uint32_t aqh[4], aql[4];
            LDSM4(aqh, sb + FQHI + (wq + lr)*ROWF + ko);
            LDSM4(aql, sb + FQLO + (wq + lr)*ROWF + ko);
            #pragma unroll
            for (int jg = 0; jg < 4; jg++) {
                uint32_t bkh[4];
                LDSM4(bkh, SB + FKH + (jg*16 + lr)*ROWF + ko);
                #pragma unroll
                for (int j2 = 0; j2 < 2; j2++) {
                    float* c = sacc[jg*2 + j2];
                    mma_f16(c, aqh, bkh[j2], bkh[j2+2]);
                    mma_f16(c, aql, bkh[j2], bkh[j2+2]);
                }
            }
        }

        // ---- online softmax (exp2 domain) ----
        float nm0 = NEGINF, nm1 = NEGINF;
        #pragma unroll
        for (int j = 0; j < 8; j++) {
            nm0 = fmaxf(nm0, fmaxf(sacc[j][0], sacc[j][1]));
            nm1 = fmaxf(nm1, fmaxf(sacc[j][2], sacc[j][3]));
        }
        nm0 = fmaxf(nm0, __shfl_xor_sync(0xffffffffu, nm0, 1));
        nm0 = fmaxf(nm0, __shfl_xor_sync(0xffffffffu, nm0, 2));
        nm1 = fmaxf(nm1, __shfl_xor_sync(0xffffffffu, nm1, 1));
        nm1 = fmaxf(nm1, __shfl_xor_sync(0xffffffffu, nm1, 2));
        float M0 = fmaxf(m0, nm0), M1 = fmaxf(m1, nm1);
        bool changed = (M0 != m0) || (M1 != m1);
        float c0 = ex2f(m0 - M0), c1 = ex2f(m1 - M1);
        m0 = M0; m1 = M1;
        float rs0 = 0.f, rs1 = 0.f;
        #pragma unroll
        for (int j = 0; j < 8; j++) {
            sacc[j][0] = ex2f(sacc[j][0] - M0);
            sacc[j][1] = ex2f(sacc[j][1] - M0);
            sacc[j][2] = ex2f(sacc[j][2] - M1);
            sacc[j][3] = ex2f(sacc[j][3] - M1);
            rs0 += sacc[j][0] + sacc[j][1];
            rs1 += sacc[j][2] + sacc[j][3];
        }
        rs0 += __shfl_xor_sync(0xffffffffu, rs0, 1);
        rs0 += __shfl_xor_sync(0xffffffffu, rs0, 2);
        rs1 += __shfl_xor_sync(0xffffffffu, rs1, 1);
        rs1 += __shfl_xor_sync(0xffffffffu, rs1, 2);
        l0 = l0*c0 + rs0;
        l1 = l1*c1 + rs1;
        if (__any_sync(0xffffffffu, changed)) {
            #pragma unroll
            for (int j = 0; j < 8; j++) {
                oacc[j][0] *= c0; oacc[j][1] *= c0;
                oacc[j][2] *= c1; oacc[j][3] *= c1;
            }
        }

        // ---- O += P V (2-term); P repacked from S fragments ----
        const int vrow0 = ((lane >> 3) & 1)*8 + (lane & 7);
        const int vcsub = (lane >> 4)*8;
        #pragma unroll
        for (int kk = 0; kk < 4; kk++) {
            uint32_t ah[4], al[4];
            split_pack(sacc[2*kk][0],   sacc[2*kk][1],   ah[0], al[0]);
            split_pack(sacc[2*kk][2],   sacc[2*kk][3],   ah[1], al[1]);
            split_pack(sacc[2*kk+1][0], sacc[2*kk+1][1], ah[2], al[2]);
            split_pack(sacc[2*kk+1][2], sacc[2*kk+1][3], ah[3], al[3]);
            const uint32_t vr = (kk*16 + vrow0)*ROWF;
            #pragma unroll
            for (int jj = 0; jj < 4; jj++) {
                uint32_t bvh[4];
                LDSM4T(bvh, SB + FVH + vr + (jj*16 + vcsub)*2);
                #pragma unroll
                for (int j2 = 0; j2 < 2; j2++) {
                    float* o = oacc[jj*2 + j2];
                    mma_f16(o, ah, bvh[2*j2], bvh[2*j2+1]);
                    mma_f16(o, al, bvh[2*j2], bvh[2*j2+1]);
                }
            }
        }
        __syncthreads();
    }
#undef FISSUE

    const float inv0 = 1.f / l0, inv1 = 1.f / l1;
    const int b = bh >> 4, h = bh & 15;
    const int tok0 = b*TSEQ + q0 + wq + g;
    const int tok1 = tok0 + 8;
    #pragma unroll
    for (int j = 0; j < 8; j++) {
        const int col = h*64 + j*8 + t*2;
        uint32_t ph, pl;
        split_pack(oacc[j][0]*inv0, oacc[j][1]*inv0, ph, pl);
        *(uint32_t*)&ohi[(size_t)tok0*DMODEL + col] = ph;
        *(uint32_t*)&olo[(size_t)tok0*DMODEL + col] = pl;
        split_pack(oacc[j][2]*inv1, oacc[j][3]*inv1, ph, pl);
        *(uint32_t*)&ohi[(size_t)tok1*DMODEL + col] = ph;
        *(uint32_t*)&olo[(size_t)tok1*DMODEL + col] = pl;
    }
}

// ---------------- launch ----------------
extern "C" void kernel_launch(void* const* d_in, const int* in_sizes, int n_in,
                              void* d_out, int out_size)
{
    const float* x  = (const float*)d_in[0];
    const float* Wq = (const float*)d_in[1];
    const float* Wk = (const float*)d_in[2];
    const float* Wv = (const float*)d_in[3];
    const float* Wo = (const float*)d_in[4];
    const float* bo = (const float*)d_in[5];
    float* out = (float*)d_out;

    __half *xhi, *xlo, *wh, *ahi, *alo, *qhi, *qlo, *kh, *vh;
    cudaGetSymbolAddress((void**)&xhi, g_xhi);
    cudaGetSymbolAddress((void**)&xlo, g_xlo);
    cudaGetSymbolAddress((void**)&wh,  g_wh);
    cudaGetSymbolAddress((void**)&ahi, g_ahi);
    cudaGetSymbolAddress((void**)&alo, g_alo);
    cudaGetSymbolAddress((void**)&qhi, g_qhi);
    cudaGetSymbolAddress((void**)&qlo, g_qlo);
    cudaGetSymbolAddress((void**)&kh,  g_kh);
    cudaGetSymbolAddress((void**)&vh,  g_vh);

    const size_t WSZ = (size_t)DMODEL*DMODEL;

    // rope chain (serial) interleaved with independent prep
    invf_kernel<<<1, 32>>>();
    rope_kernel<<<TSEQ, HDIM>>>();
    split_kernel<<<(BT*DMODEL/4 + 255)/256, 256>>>(x, xhi, xlo, BT*DMODEL/4);
    gram1_kernel<<<16, 256>>>();
    gram2_kernel<<<HDIM, HDIM>>>();
    tsplit3_kernel<<<dim3(32, 32, 3), dim3(32, 8)>>>(Wq, Wk, Wo, wh);
    wvfold_kernel<<<dim3(32, 32), 256>>>(Wv, wh + 2*WSZ);

    cudaFuncSetAttribute(hgemm_tc<0>, cudaFuncAttributeMaxDynamicSharedMemorySize, SMEMB);
    cudaFuncSetAttribute(hgemm_tc<1>, cudaFuncAttributeMaxDynamicSharedMemorySize, SMEMB);
    cudaFuncSetAttribute(flash_hmma, cudaFuncAttributeMaxDynamicSharedMemorySize, FSMEM);

    // merged QKV projection: grid.x = 24 (3 matrices x 8 col-tiles)
    hgemm_tc<0><<<dim3(24, BT/128), 256, SMEMB>>>(xhi, xlo, wh, nullptr, nullptr,
                                                  qhi, qlo, kh, vh);

    flash_hmma<<<dim3(TSEQ/128, BATCH*NHEADS), 256, FSMEM>>>(qhi, qlo, kh, vh, ahi, alo);

    hgemm_tc<1><<<dim3(8, BT/128), 256, SMEMB>>>(ahi, alo, wh + 3*WSZ, bo, out,
                                                 nullptr, nullptr, nullptr, nullptr);

    (void)in_sizes; (void)n_in; (void)out_size;
}

// round 12
// speedup vs baseline: 4.0579x; 1.0781x over previous
#include <cuda_runtime.h>
#include <cuda_fp16.h>
#include <math.h>
#include <stdint.h>

#define BATCH   2
#define TSEQ    2048
#define DMODEL  1024
#define NHEADS  16
#define HDIM    64
#define BT      (BATCH*TSEQ)   /* 4096 */
#define SCALE_Q 0.1803368801111137f   /* 0.125 * log2(e) */

// ---------------- scratch (static device arrays; no allocation) ----------------
__device__ float g_rope[TSEQ*HDIM];
__device__ double g_invf[32];
__device__ float g_MpartF[64][HDIM*HDIM];
__device__ float g_M[HDIM*HDIM];
__device__ __half g_xhi[(size_t)BT*DMODEL];
__device__ __half g_xlo[(size_t)BT*DMODEL];
__device__ __half g_wh[4*(size_t)DMODEL*DMODEL];   // transposed weights [N][K], fp16
__device__ __half g_qhi[BATCH*NHEADS*TSEQ*HDIM];
__device__ __half g_qlo[BATCH*NHEADS*TSEQ*HDIM];
__device__ __half g_kh[BATCH*NHEADS*TSEQ*HDIM];
__device__ __half g_vh[BATCH*NHEADS*TSEQ*HDIM];
__device__ __half g_ahi[(size_t)BT*DMODEL];
__device__ __half g_alo[(size_t)BT*DMODEL];

// ---------------- PTX helpers (base ISA: cp.async / ldmatrix / mma.sync) --------
__device__ __forceinline__ uint32_t smem_u32(const void* p) {
    uint32_t a;
    asm("{ .reg .u64 t; cvta.to.shared.u64 t, %1; cvt.u32.u64 %0, t; }" : "=r"(a) : "l"(p));
    return a;
}
#define CP16(dst, src) asm volatile("cp.async.cg.shared.global [%0], [%1], 16;" :: "r"(dst), "l"(src))
#define CP_COMMIT()    asm volatile("cp.async.commit_group;" ::: "memory")
#define CP_WAIT1()     asm volatile("cp.async.wait_group 1;" ::: "memory")
#define CP_WAIT0()     asm volatile("cp.async.wait_group 0;" ::: "memory")
#define LDSM4(r, a) \
    asm volatile("ldmatrix.sync.aligned.m8n8.x4.shared.b16 {%0,%1,%2,%3}, [%4];" \
        : "=r"((r)[0]), "=r"((r)[1]), "=r"((r)[2]), "=r"((r)[3]) : "r"(a))
#define LDSM4T(r, a) \
    asm volatile("ldmatrix.sync.aligned.m8n8.x4.trans.shared.b16 {%0,%1,%2,%3}, [%4];" \
        : "=r"((r)[0]), "=r"((r)[1]), "=r"((r)[2]), "=r"((r)[3]) : "r"(a))
__device__ __forceinline__ void mma_f16(float* c, const uint32_t* a, uint32_t b0, uint32_t b1) {
    asm volatile("mma.sync.aligned.m16n8k16.row.col.f32.f16.f16.f32 "
                 "{%0,%1,%2,%3}, {%4,%5,%6,%7}, {%8,%9}, {%0,%1,%2,%3};"
                 : "+f"(c[0]), "+f"(c[1]), "+f"(c[2]), "+f"(c[3])
                 : "r"(a[0]), "r"(a[1]), "r"(a[2]), "r"(a[3]), "r"(b0), "r"(b1));
}
__device__ __forceinline__ float ex2f(float x) {
    float r; asm("ex2.approx.f32 %0, %1;" : "=f"(r) : "f"(x)); return r;
}
// split two floats into packed fp16 hi pair + lo (residual) pair, f16x2 cvt
__device__ __forceinline__ void split_pack(float x, float y, uint32_t& hi, uint32_t& lo) {
    __half2 h = __floats2half2_rn(x, y);
    float2 hf = __half22float2(h);
    __half2 l = __floats2half2_rn(x - hf.x, y - hf.y);
    hi = *(uint32_t*)&h;
    lo = *(uint32_t*)&l;
}
__device__ __forceinline__ uint32_t pack_h2(float x, float y) {
    __half2 h = __floats2half2_rn(x, y);
    return *(uint32_t*)&h;
}

// ---------------- rope / gram ----------------
__global__ void invf_kernel() {
    int j = threadIdx.x;
    g_invf[j] = exp(-log(10000.0) * (double)j / 32.0);
}
__global__ void rope_kernel() {
    int s = blockIdx.x, d = threadIdx.x;
    double ang = (double)s * g_invf[d & 31];
    g_rope[s*HDIM + d] = (d < 32) ? (float)cos(ang) : (float)sin(ang);
}
// Gram partials, fp32: 64 blocks x 256 threads; each block one 32-row chunk.
__global__ __launch_bounds__(256) void gram1_kernel() {
    __shared__ float R[32][68];
    const int c = blockIdx.x, tid = threadIdx.x;
    const float* rp = g_rope + (size_t)c*32*HDIM;
    for (int i = tid; i < 32*16; i += 256) {
        int r = i >> 4, q = i & 15;
        *(float4*)&R[r][q*4] = *(const float4*)(rp + r*HDIM + q*4);
    }
    __syncthreads();
    const int d0 = (tid & 15)*4, e0 = (tid >> 4)*4;
    float acc[4][4] = {};
    #pragma unroll 4
    for (int s = 0; s < 32; s++) {
        float4 a = *(const float4*)&R[s][d0];
        float4 b = *(const float4*)&R[s][e0];
        acc[0][0] = fmaf(a.x, b.x, acc[0][0]); acc[0][1] = fmaf(a.x, b.y, acc[0][1]);
        acc[0][2] = fmaf(a.x, b.z, acc[0][2]); acc[0][3] = fmaf(a.x, b.w, acc[0][3]);
        acc[1][0] = fmaf(a.y, b.x, acc[1][0]); acc[1][1] = fmaf(a.y, b.y, acc[1][1]);
        acc[1][2] = fmaf(a.y, b.z, acc[1][2]); acc[1][3] = fmaf(a.y, b.w, acc[1][3]);
        acc[2][0] = fmaf(a.z, b.x, acc[2][0]); acc[2][1] = fmaf(a.z, b.y, acc[2][1]);
        acc[2][2] = fmaf(a.z, b.z, acc[2][2]); acc[2][3] = fmaf(a.z, b.w, acc[2][3]);
        acc[3][0] = fmaf(a.w, b.x, acc[3][0]); acc[3][1] = fmaf(a.w, b.y, acc[3][1]);
        acc[3][2] = fmaf(a.w, b.z, acc[3][2]); acc[3][3] = fmaf(a.w, b.w, acc[3][3]);
    }
    #pragma unroll
    for (int i = 0; i < 4; i++)
        #pragma unroll
        for (int j = 0; j < 4; j++)
            g_MpartF[c][(d0 + i)*HDIM + e0 + j] = acc[i][j];
}
__global__ void gram2_kernel() {
    int d = blockIdx.x, e = threadIdx.x;
    float a = 0.f;
    #pragma unroll
    for (int c = 0; c < 64; c++) a += g_MpartF[c][d*HDIM + e];
    g_M[d*HDIM + e] = a;
}

// ---------------- fused fold+transpose+fp16: wh[2] = (Wv @ blockdiag(M))^T -------
__global__ __launch_bounds__(256) void wvfold_kernel(const float* __restrict__ Wv,
                                                     __half* __restrict__ whv) {
    __shared__ float Wt[32][65];   // [k_local][d]
    __shared__ float Mt[64][33];   // [d][e_local]
    const int n0 = blockIdx.x*32, k0 = blockIdx.y*32;
    const int h0 = n0 >> 6;
    const int e0 = n0 & 63;
    const int tid = threadIdx.x;
    for (int i = tid; i < 32*64; i += 256) {
        int r = i >> 6, c = i & 63;
        Wt[r][c] = Wv[(size_t)(k0 + r)*DMODEL + h0*64 + c];
    }
    for (int i = tid; i < 64*32; i += 256) {
        int d = i >> 5, e = i & 31;
        Mt[d][e] = g_M[d*HDIM + e0 + e];
    }
    __syncthreads();
    const int kl = tid & 31, nl0 = tid >> 5;
    #pragma unroll
    for (int u = 0; u < 4; u++) {
        int nl = nl0 + u*8;
        float acc = 0.f;
        #pragma unroll
        for (int d = 0; d < 64; d++) acc = fmaf(Wt[kl][d], Mt[d][nl], acc);
        whv[(size_t)(n0 + nl)*DMODEL + k0 + kl] = __float2half_rn(acc);
    }
}

// ---------------- hi/lo fp16 split of x ----------------
__global__ __launch_bounds__(256) void split_kernel(const float* __restrict__ src,
                                                    __half* __restrict__ hi,
                                                    __half* __restrict__ lo, int n4) {
    int i = blockIdx.x*blockDim.x + threadIdx.x;
    if (i >= n4) return;
    float4 v = ((const float4*)src)[i];
    uint32_t h0, l0, h1, l1;
    split_pack(v.x, v.y, h0, l0);
    split_pack(v.z, v.w, h1, l1);
    ((uint2*)hi)[i] = make_uint2(h0, h1);
    ((uint2*)lo)[i] = make_uint2(l0, l1);
}

// ---------------- batched transpose+round: {Wq,Wk,Wo} -> wh slots {0,1,3} --------
__global__ void tsplit3_kernel(const float* __restrict__ Wq,
                               const float* __restrict__ Wk,
                               const float* __restrict__ Wo,
                               __half* __restrict__ wh) {
    const int z = blockIdx.z;
    const float* W = (z == 0) ? Wq : (z == 1) ? Wk : Wo;
    __half* out = wh + (size_t)((z == 2) ? 3 : z)*DMODEL*DMODEL;
    __shared__ float t[32][33];
    int x0 = blockIdx.x*32, y0 = blockIdx.y*32;
    int tx = threadIdx.x, ty = threadIdx.y;
    #pragma unroll
    for (int j = 0; j < 32; j += 8)
        t[ty+j][tx] = W[(size_t)(y0+ty+j)*DMODEL + x0+tx];
    __syncthreads();
    #pragma unroll
    for (int j = 0; j < 32; j += 8)
        out[(size_t)(x0+ty+j)*DMODEL + y0+tx] = __float2half_rn(t[tx][ty+j]);
}

// ---------------- HMMA GEMM: C = (Ahi+Alo) @ Bh^T, fp16 x2, fp32 accum -----------
#define ROWB     80
#define TILEB    (128*ROWB)
#define STAGEB   (3*TILEB)
#define SMEMB    (2*STAGEB)

template<int MODE>
__global__ __launch_bounds__(256) void hgemm_tc(const __half* __restrict__ Ahi,
                                                const __half* __restrict__ Alo,
                                                const __half* __restrict__ Bh,
                                                const float* __restrict__ bias,
                                                float* __restrict__ OUT,
                                                __half* __restrict__ QH,
                                                __half* __restrict__ QL,
                                                __half* __restrict__ KH,
                                                __half* __restrict__ VH)
{
    extern __shared__ char smem[];
    const uint32_t smem_base = smem_u32(smem);
    const int tid  = threadIdx.x;
    const int lane = tid & 31;
    const int wid  = tid >> 5;
    const int wm   = wid & 3;
    const int wn   = wid >> 2;
    const int br   = blockIdx.y, bc = blockIdx.x;

    const int lrow  = tid >> 2;
    const int chunk = tid & 3;

    const __half* A0h = Ahi + (size_t)(br*128 + lrow)*DMODEL + chunk*8;
    const __half* A0l = Alo + (size_t)(br*128 + lrow)*DMODEL + chunk*8;
    const __half* B0  = Bh  + (size_t)(bc*128 + lrow)*DMODEL + chunk*8;
    const size_t rstep = (size_t)64*DMODEL;

#define ISSUE(s_, buf_) do { \
    uint32_t sb = smem_base + (buf_)*STAGEB; \
    uint32_t d0 = sb + lrow*ROWB + chunk*16; \
    size_t  go = (size_t)(s_)*32; \
    CP16(d0,           A0h + go); \
    CP16(d0 + TILEB,   A0l + go); \
    CP16(d0 + 2*TILEB, B0  + go); \
    uint32_t d1 = d0 + 64*ROWB; \
    CP16(d1,           A0h + go + rstep); \
    CP16(d1 + TILEB,   A0l + go + rstep); \
    CP16(d1 + 2*TILEB, B0  + go + rstep); \
} while (0)

    float acc[2][8][4];
    #pragma unroll
    for (int i = 0; i < 2; i++)
        #pragma unroll
        for (int j = 0; j < 8; j++)
            #pragma unroll
            for (int e = 0; e < 4; e++) acc[i][j][e] = 0.f;

    const int m0 = wm*32, n0 = wn*64;
    const int lr = lane & 15, lh = lane >> 4;

    ISSUE(0, 0); CP_COMMIT();

    for (int s = 0; s < 32; s++) {
        if (s + 1 < 32) { ISSUE(s + 1, (s + 1) & 1); CP_COMMIT(); CP_WAIT1(); }
        else            { CP_WAIT0(); }
        __syncthreads();

        const uint32_t As = smem_base + (s & 1)*STAGEB;
        const uint32_t Bs = As + 2*TILEB;
        #pragma unroll
        for (int k = 0; k < 2; k++) {
            const uint32_t koff = k*32 + lh*16;
            uint32_t ahi[2][4], alo[2][4], bq[4][4];
            #pragma unroll
            for (int mi = 0; mi < 2; mi++) {
                LDSM4(ahi[mi], As + (m0 + mi*16 + lr)*ROWB + koff);
                LDSM4(alo[mi], As + TILEB + (m0 + mi*16 + lr)*ROWB + koff);
            }
            #pragma unroll
            for (int jg = 0; jg < 4; jg++)
                LDSM4(bq[jg], Bs + (n0 + jg*16 + lr)*ROWB + koff);
            #pragma unroll
            for (int mi = 0; mi < 2; mi++)
                #pragma unroll
                for (int j = 0; j < 8; j++) {
                    mma_f16(acc[mi][j], ahi[mi], bq[j>>1][j&1], bq[j>>1][(j&1)+2]);
                    mma_f16(acc[mi][j], alo[mi], bq[j>>1][j&1], bq[j>>1][(j&1)+2]);
                }
        }
        __syncthreads();
    }
#undef ISSUE

    // epilogue
    const int g = lane >> 2, t = lane & 3;
    int colbase = bc*128;
    int mm = 0;
    if (MODE == 0) { mm = bc >> 3; colbase = (bc & 7)*128; }
    #pragma unroll
    for (int mi = 0; mi < 2; mi++) {
        #pragma unroll
        for (int rr = 0; rr < 2; rr++) {
            const int row = br*128 + m0 + mi*16 + rr*8 + g;
            #pragma unroll
            for (int j = 0; j < 8; j++) {
                const int col = colbase + n0 + j*8 + t*2;
                float vx = acc[mi][j][rr*2 + 0];
                float vy = acc[mi][j][rr*2 + 1];
                if (MODE == 1) {
                    float2 v; v.x = vx + bias[col]; v.y = vy + bias[col + 1];
                    *(float2*)&OUT[(size_t)row*DMODEL + col] = v;
                } else {
                    int bi = row >> 11, tt = row & 2047;
                    int h = col >> 6, dd = col & 63;
                    size_t o = (((size_t)(bi*NHEADS + h))*TSEQ + tt)*HDIM + dd;
                    if (mm == 0) {
                        uint32_t ph, pl;
                        split_pack(vx*SCALE_Q, vy*SCALE_Q, ph, pl);
                        *(uint32_t*)&QH[o] = ph;
                        *(uint32_t*)&QL[o] = pl;
                    } else {
                        __half* P = (mm == 1) ? KH : VH;
                        *(uint32_t*)&P[o] = pack_h2(vx, vy);
                    }
                }
            }
        }
    }
}

// ---------------- HMMA flash attention -----------------------------------------
// S = (Qhi+Qlo) K^T (exp2 domain); O = Phi V (P hi-only); fp32 online softmax.
#define ROWF   144
#define FQHI   0
#define FQLO   (128*ROWF)
#define FQTOT  (2*128*ROWF)      /* 36864 */
#define FKH    0
#define FVH    (64*ROWF)
#define FSTG   (2*64*ROWF)       /* 18432 */
#define FSMEM  (FQTOT + 2*FSTG)  /* 73728 */

__global__ __launch_bounds__(256, 2) void flash_hmma(
    const __half* __restrict__ qhi, const __half* __restrict__ qlo,
    const __half* __restrict__ kh,  const __half* __restrict__ vh,
    __half* __restrict__ ohi, __half* __restrict__ olo)
{
    extern __shared__ char fsm[];
    const uint32_t sb = smem_u32(fsm);
    const int tid = threadIdx.x, lane = tid & 31, wid = tid >> 5;
    const int bh = blockIdx.y, q0 = blockIdx.x*128;
    const int g = lane >> 2, t = lane & 3, lr = lane & 15, lh = lane >> 4;
    const int wq = wid*16;

    const size_t base = (size_t)bh*TSEQ*HDIM;
    const __half* qph = qhi + base + (size_t)q0*HDIM;
    const __half* qpl = qlo + base + (size_t)q0*HDIM;
    const __half* kp  = kh  + base;
    const __half* vp  = vh  + base;

    {
        int r = tid >> 1, c4 = (tid & 1)*4;
        #pragma unroll
        for (int u = 0; u < 4; u++) {
            CP16(sb + FQHI + r*ROWF + (c4+u)*16, qph + (size_t)r*HDIM + (c4+u)*8);
            CP16(sb + FQLO + r*ROWF + (c4+u)*16, qpl + (size_t)r*HDIM + (c4+u)*8);
        }
        CP_COMMIT();
    }

#define FISSUE(kb_, b_) do { \
    int r = tid >> 2, c2 = (tid & 3)*2; \
    uint32_t s0 = sb + FQTOT + (b_)*FSTG; \
    size_t go = (size_t)((kb_)*64 + r)*HDIM; \
    _Pragma("unroll") \
    for (int u = 0; u < 2; u++) { \
        CP16(s0 + FKH + r*ROWF + (c2+u)*16, kp + go + (c2+u)*8); \
        CP16(s0 + FVH + r*ROWF + (c2+u)*16, vp + go + (c2+u)*8); \
    } \
} while (0)

    FISSUE(0, 0); CP_COMMIT();
    CP_WAIT0(); __syncthreads();

    float oacc[8][4];
    #pragma unroll
    for (int j = 0; j < 8; j++)
        #pragma unroll
        for (int e = 0; e < 4; e++) oacc[j][e] = 0.f;
    const float NEGINF = __int_as_float(0xff800000);
    float m0 = NEGINF, m1 = NEGINF, l0 = 0.f, l1 = 0.f;

    for (int kb = 0; kb < 32; kb++) {
        if (kb + 1 < 32) { FISSUE(kb + 1, (kb + 1) & 1); CP_COMMIT(); CP_WAIT1(); }
        else             { CP_WAIT0(); }
        __syncthreads();

        const uint32_t SB = sb + FQTOT + (kb & 1)*FSTG;

        // ---- S = Q K^T (2-term), exp2 domain ----
        float sacc[8][4];
        #pragma unroll
        for (int j = 0; j < 8; j++)
            #pragma unroll
            for (int e = 0; e < 4; e++) sacc[j][e] = 0.f;

        #pragma unroll
        for (int kk = 0; kk < 4; kk++) {
            const uint32_t ko = kk*32 + lh*16;
            uint32_t aqh[4], aql[4];
            LDSM4(aqh, sb + FQHI + (wq + lr)*ROWF + ko);
            LDSM4(aql, sb + FQLO + (wq + lr)*ROWF + ko);
            #pragma unroll
            for (int jg = 0; jg < 4; jg++) {
                uint32_t bkh[4];
                LDSM4(bkh, SB + FKH + (jg*16 + lr)*ROWF + ko);
                #pragma unroll
                for (int j2 = 0; j2 < 2; j2++) {
                    float* c = sacc[jg*2 + j2];
                    mma_f16(c, aqh, bkh[j2], bkh[j2+2]);
                    mma_f16(c, aql, bkh[j2], bkh[j2+2]);
                }
            }
        }

        // ---- online softmax (exp2 domain) ----
        float nm0 = NEGINF, nm1 = NEGINF;
        #pragma unroll
        for (int j = 0; j < 8; j++) {
            nm0 = fmaxf(nm0, fmaxf(sacc[j][0], sacc[j][1]));
            nm1 = fmaxf(nm1, fmaxf(sacc[j][2], sacc[j][3]));
        }
        nm0 = fmaxf(nm0, __shfl_xor_sync(0xffffffffu, nm0, 1));
        nm0 = fmaxf(nm0, __shfl_xor_sync(0xffffffffu, nm0, 2));
        nm1 = fmaxf(nm1, __shfl_xor_sync(0xffffffffu, nm1, 1));
        nm1 = fmaxf(nm1, __shfl_xor_sync(0xffffffffu, nm1, 2));
        float M0 = fmaxf(m0, nm0), M1 = fmaxf(m1, nm1);
        bool changed = (M0 != m0) || (M1 != m1);
        float c0 = ex2f(m0 - M0), c1 = ex2f(m1 - M1);
        m0 = M0; m1 = M1;
        float rs0 = 0.f, rs1 = 0.f;
        #pragma unroll
        for (int j = 0; j < 8; j++) {
            sacc[j][0] = ex2f(sacc[j][0] - M0);
            sacc[j][1] = ex2f(sacc[j][1] - M0);
            sacc[j][2] = ex2f(sacc[j][2] - M1);
            sacc[j][3] = ex2f(sacc[j][3] - M1);
            rs0 += sacc[j][0] + sacc[j][1];
            rs1 += sacc[j][2] + sacc[j][3];
        }
        rs0 += __shfl_xor_sync(0xffffffffu, rs0, 1);
        rs0 += __shfl_xor_sync(0xffffffffu, rs0, 2);
        rs1 += __shfl_xor_sync(0xffffffffu, rs1, 1);
        rs1 += __shfl_xor_sync(0xffffffffu, rs1, 2);
        l0 = l0*c0 + rs0;
        l1 = l1*c1 + rs1;
        if (__any_sync(0xffffffffu, changed)) {
            #pragma unroll
            for (int j = 0; j < 8; j++) {
                oacc[j][0] *= c0; oacc[j][1] *= c0;
                oacc[j][2] *= c1; oacc[j][3] *= c1;
            }
        }

        // ---- O += Phi V (1-term); P repacked hi-only from S fragments ----
        const int vrow0 = ((lane >> 3) & 1)*8 + (lane & 7);
        const int vcsub = (lane >> 4)*8;
        #pragma unroll
        for (int kk = 0; kk < 4; kk++) {
            uint32_t ah[4];
            ah[0] = pack_h2(sacc[2*kk][0],   sacc[2*kk][1]);
            ah[1] = pack_h2(sacc[2*kk][2],   sacc[2*kk][3]);
            ah[2] = pack_h2(sacc[2*kk+1][0], sacc[2*kk+1][1]);
            ah[3] = pack_h2(sacc[2*kk+1][2], sacc[2*kk+1][3]);
            const uint32_t vr = (kk*16 + vrow0)*ROWF;
            #pragma unroll
            for (int jj = 0; jj < 4; jj++) {
                uint32_t bvh[4];
                LDSM4T(bvh, SB + FVH + vr + (jj*16 + vcsub)*2);
                #pragma unroll
                for (int j2 = 0; j2 < 2; j2++) {
                    float* o = oacc[jj*2 + j2];
                    mma_f16(o, ah, bvh[2*j2], bvh[2*j2+1]);
                }
            }
        }
        __syncthreads();
    }
#undef FISSUE

    const float inv0 = 1.f / l0, inv1 = 1.f / l1;
    const int b = bh >> 4, h = bh & 15;
    const int tok0 = b*TSEQ + q0 + wq + g;
    const int tok1 = tok0 + 8;
    #pragma unroll
    for (int j = 0; j < 8; j++) {
        const int col = h*64 + j*8 + t*2;
        uint32_t ph, pl;
        split_pack(oacc[j][0]*inv0, oacc[j][1]*inv0, ph, pl);
        *(uint32_t*)&ohi[(size_t)tok0*DMODEL + col] = ph;
        *(uint32_t*)&olo[(size_t)tok0*DMODEL + col] = pl;
        split_pack(oacc[j][2]*inv1, oacc[j][3]*inv1, ph, pl);
        *(uint32_t*)&ohi[(size_t)tok1*DMODEL + col] = ph;
        *(uint32_t*)&olo[(size_t)tok1*DMODEL + col] = pl;
    }
}

// ---------------- launch ----------------
extern "C" void kernel_launch(void* const* d_in, const int* in_sizes, int n_in,
                              void* d_out, int out_size)
{
    const float* x  = (const float*)d_in[0];
    const float* Wq = (const float*)d_in[1];
    const float* Wk = (const float*)d_in[2];
    const float* Wv = (const float*)d_in[3];
    const float* Wo = (const float*)d_in[4];
    const float* bo = (const float*)d_in[5];
    float* out = (float*)d_out;

    __half *xhi, *xlo, *wh, *ahi, *alo, *qhi, *qlo, *kh, *vh;
    cudaGetSymbolAddress((void**)&xhi, g_xhi);
    cudaGetSymbolAddress((void**)&xlo, g_xlo);
    cudaGetSymbolAddress((void**)&wh,  g_wh);
    cudaGetSymbolAddress((void**)&ahi, g_ahi);
    cudaGetSymbolAddress((void**)&alo, g_alo);
    cudaGetSymbolAddress((void**)&qhi, g_qhi);
    cudaGetSymbolAddress((void**)&qlo, g_qlo);
    cudaGetSymbolAddress((void**)&kh,  g_kh);
    cudaGetSymbolAddress((void**)&vh,  g_vh);

    const size_t WSZ = (size_t)DMODEL*DMODEL;

    invf_kernel<<<1, 32>>>();
    rope_kernel<<<TSEQ, HDIM>>>();
    split_kernel<<<(BT*DMODEL/4 + 255)/256, 256>>>(x, xhi, xlo, BT*DMODEL/4);
    gram1_kernel<<<64, 256>>>();
    gram2_kernel<<<HDIM, HDIM>>>();
    tsplit3_kernel<<<dim3(32, 32, 3), dim3(32, 8)>>>(Wq, Wk, Wo, wh);
    wvfold_kernel<<<dim3(32, 32), 256>>>(Wv, wh + 2*WSZ);

    cudaFuncSetAttribute(hgemm_tc<0>, cudaFuncAttributeMaxDynamicSharedMemorySize, SMEMB);
    cudaFuncSetAttribute(hgemm_tc<1>, cudaFuncAttributeMaxDynamicSharedMemorySize, SMEMB);
    cudaFuncSetAttribute(flash_hmma, cudaFuncAttributeMaxDynamicSharedMemorySize, FSMEM);

    // merged QKV projection: grid.x = 24 (3 matrices x 8 col-tiles)
    hgemm_tc<0><<<dim3(24, BT/128), 256, SMEMB>>>(xhi, xlo, wh, nullptr, nullptr,
                                                  qhi, qlo, kh, vh);

    flash_hmma<<<dim3(TSEQ/128, BATCH*NHEADS), 256, FSMEM>>>(qhi, qlo, kh, vh, ahi, alo);

    hgemm_tc<1><<<dim3(8, BT/128), 256, SMEMB>>>(ahi, alo, wh + 3*WSZ, bo, out,
                                                 nullptr, nullptr, nullptr, nullptr);

    (void)in_sizes; (void)n_in; (void)out_size;
}

// round 13
// speedup vs baseline: 4.3217x; 1.0650x over previous
#include <cuda_runtime.h>
#include <cuda_fp16.h>
#include <math.h>
#include <stdint.h>

#define BATCH   2
#define TSEQ    2048
#define DMODEL  1024
#define NHEADS  16
#define HDIM    64
#define BT      (BATCH*TSEQ)   /* 4096 */
#define SCALE_Q 0.1803368801111137f   /* 0.125 * log2(e) */

// ---------------- scratch (static device arrays; no allocation) ----------------
__device__ float g_rope[TSEQ*HDIM];
__device__ double g_invf[32];
__device__ float g_MpartF[64][HDIM*HDIM];
__device__ float g_M[HDIM*HDIM];
__device__ __half g_xhi[(size_t)BT*DMODEL];
__device__ __half g_xlo[(size_t)BT*DMODEL];
__device__ __half g_wh[4*(size_t)DMODEL*DMODEL];   // transposed weights [N][K], fp16
__device__ __half g_qh[BATCH*NHEADS*TSEQ*HDIM];
__device__ __half g_kh[BATCH*NHEADS*TSEQ*HDIM];
__device__ __half g_vh[BATCH*NHEADS*TSEQ*HDIM];
__device__ __half g_ahi[(size_t)BT*DMODEL];
__device__ __half g_alo[(size_t)BT*DMODEL];

// ---------------- PTX helpers (base ISA: cp.async / ldmatrix / mma.sync) --------
__device__ __forceinline__ uint32_t smem_u32(const void* p) {
    uint32_t a;
    asm("{ .reg .u64 t; cvta.to.shared.u64 t, %1; cvt.u32.u64 %0, t; }" : "=r"(a) : "l"(p));
    return a;
}
#define CP16(dst, src) asm volatile("cp.async.cg.shared.global [%0], [%1], 16;" :: "r"(dst), "l"(src))
#define CP_COMMIT()    asm volatile("cp.async.commit_group;" ::: "memory")
#define CP_WAIT1()     asm volatile("cp.async.wait_group 1;" ::: "memory")
#define CP_WAIT0()     asm volatile("cp.async.wait_group 0;" ::: "memory")
#define LDSM4(r, a) \
    asm volatile("ldmatrix.sync.aligned.m8n8.x4.shared.b16 {%0,%1,%2,%3}, [%4];" \
        : "=r"((r)[0]), "=r"((r)[1]), "=r"((r)[2]), "=r"((r)[3]) : "r"(a))
#define LDSM4T(r, a) \
    asm volatile("ldmatrix.sync.aligned.m8n8.x4.trans.shared.b16 {%0,%1,%2,%3}, [%4];" \
        : "=r"((r)[0]), "=r"((r)[1]), "=r"((r)[2]), "=r"((r)[3]) : "r"(a))
__device__ __forceinline__ void mma_f16(float* c, const uint32_t* a, uint32_t b0, uint32_t b1) {
    asm volatile("mma.sync.aligned.m16n8k16.row.col.f32.f16.f16.f32 "
                 "{%0,%1,%2,%3}, {%4,%5,%6,%7}, {%8,%9}, {%0,%1,%2,%3};"
                 : "+f"(c[0]), "+f"(c[1]), "+f"(c[2]), "+f"(c[3])
                 : "r"(a[0]), "r"(a[1]), "r"(a[2]), "r"(a[3]), "r"(b0), "r"(b1));
}
__device__ __forceinline__ float ex2f(float x) {
    float r; asm("ex2.approx.f32 %0, %1;" : "=f"(r) : "f"(x)); return r;
}
// split two floats into packed fp16 hi pair + lo (residual) pair, f16x2 cvt
__device__ __forceinline__ void split_pack(float x, float y, uint32_t& hi, uint32_t& lo) {
    __half2 h = __floats2half2_rn(x, y);
    float2 hf = __half22float2(h);
    __half2 l = __floats2half2_rn(x - hf.x, y - hf.y);
    hi = *(uint32_t*)&h;
    lo = *(uint32_t*)&l;
}
__device__ __forceinline__ uint32_t pack_h2(float x, float y) {
    __half2 h = __floats2half2_rn(x, y);
    return *(uint32_t*)&h;
}

// ---------------- rope / gram ----------------
__global__ void invf_kernel() {
    int j = threadIdx.x;
    g_invf[j] = exp(-log(10000.0) * (double)j / 32.0);
}
__global__ void rope_kernel() {
    int s = blockIdx.x, d = threadIdx.x;
    double ang = (double)s * g_invf[d & 31];
    g_rope[s*HDIM + d] = (d < 32) ? (float)cos(ang) : (float)sin(ang);
}
// Gram partials, fp32: 64 blocks x 256 threads; each block one 32-row chunk.
__global__ __launch_bounds__(256) void gram1_kernel() {
    __shared__ float R[32][68];
    const int c = blockIdx.x, tid = threadIdx.x;
    const float* rp = g_rope + (size_t)c*32*HDIM;
    for (int i = tid; i < 32*16; i += 256) {
        int r = i >> 4, q = i & 15;
        *(float4*)&R[r][q*4] = *(const float4*)(rp + r*HDIM + q*4);
    }
    __syncthreads();
    const int d0 = (tid & 15)*4, e0 = (tid >> 4)*4;
    float acc[4][4] = {};
    #pragma unroll 4
    for (int s = 0; s < 32; s++) {
        float4 a = *(const float4*)&R[s][d0];
        float4 b = *(const float4*)&R[s][e0];
        acc[0][0] = fmaf(a.x, b.x, acc[0][0]); acc[0][1] = fmaf(a.x, b.y, acc[0][1]);
        acc[0][2] = fmaf(a.x, b.z, acc[0][2]); acc[0][3] = fmaf(a.x, b.w, acc[0][3]);
        acc[1][0] = fmaf(a.y, b.x, acc[1][0]); acc[1][1] = fmaf(a.y, b.y, acc[1][1]);
        acc[1][2] = fmaf(a.y, b.z, acc[1][2]); acc[1][3] = fmaf(a.y, b.w, acc[1][3]);
        acc[2][0] = fmaf(a.z, b.x, acc[2][0]); acc[2][1] = fmaf(a.z, b.y, acc[2][1]);
        acc[2][2] = fmaf(a.z, b.z, acc[2][2]); acc[2][3] = fmaf(a.z, b.w, acc[2][3]);
        acc[3][0] = fmaf(a.w, b.x, acc[3][0]); acc[3][1] = fmaf(a.w, b.y, acc[3][1]);
        acc[3][2] = fmaf(a.w, b.z, acc[3][2]); acc[3][3] = fmaf(a.w, b.w, acc[3][3]);
    }
    #pragma unroll
    for (int i = 0; i < 4; i++)
        #pragma unroll
        for (int j = 0; j < 4; j++)
            g_MpartF[c][(d0 + i)*HDIM + e0 + j] = acc[i][j];
}
__global__ void gram2_kernel() {
    int d = blockIdx.x, e = threadIdx.x;
    float a = 0.f;
    #pragma unroll
    for (int c = 0; c < 64; c++) a += g_MpartF[c][d*HDIM + e];
    g_M[d*HDIM + e] = a;
}

// ---------------- fused fold+transpose+fp16: wh[2] = (Wv @ blockdiag(M))^T -------
__global__ __launch_bounds__(256) void wvfold_kernel(const float* __restrict__ Wv,
                                                     __half* __restrict__ whv) {
    __shared__ float Wt[32][65];   // [k_local][d]
    __shared__ float Mt[64][33];   // [d][e_local]
    const int n0 = blockIdx.x*32, k0 = blockIdx.y*32;
    const int h0 = n0 >> 6;
    const int e0 = n0 & 63;
    const int tid = threadIdx.x;
    for (int i = tid; i < 32*64; i += 256) {
        int r = i >> 6, c = i & 63;
        Wt[r][c] = Wv[(size_t)(k0 + r)*DMODEL + h0*64 + c];
    }
    for (int i = tid; i < 64*32; i += 256) {
        int d = i >> 5, e = i & 31;
        Mt[d][e] = g_M[d*HDIM + e0 + e];
    }
    __syncthreads();
    const int kl = tid & 31, nl0 = tid >> 5;
    #pragma unroll
    for (int u = 0; u < 4; u++) {
        int nl = nl0 + u*8;
        float acc = 0.f;
        #pragma unroll
        for (int d = 0; d < 64; d++) acc = fmaf(Wt[kl][d], Mt[d][nl], acc);
        whv[(size_t)(n0 + nl)*DMODEL + k0 + kl] = __float2half_rn(acc);
    }
}

// ---------------- hi/lo fp16 split of x ----------------
__global__ __launch_bounds__(256) void split_kernel(const float* __restrict__ src,
                                                    __half* __restrict__ hi,
                                                    __half* __restrict__ lo, int n4) {
    int i = blockIdx.x*blockDim.x + threadIdx.x;
    if (i >= n4) return;
    float4 v = ((const float4*)src)[i];
    uint32_t h0, l0, h1, l1;
    split_pack(v.x, v.y, h0, l0);
    split_pack(v.z, v.w, h1, l1);
    ((uint2*)hi)[i] = make_uint2(h0, h1);
    ((uint2*)lo)[i] = make_uint2(l0, l1);
}

// ---------------- batched transpose+round: {Wq,Wk,Wo} -> wh slots {0,1,3} --------
__global__ void tsplit3_kernel(const float* __restrict__ Wq,
                               const float* __restrict__ Wk,
                               const float* __restrict__ Wo,
                               __half* __restrict__ wh) {
    const int z = blockIdx.z;
    const float* W = (z == 0) ? Wq : (z == 1) ? Wk : Wo;
    __half* out = wh + (size_t)((z == 2) ? 3 : z)*DMODEL*DMODEL;
    __shared__ float t[32][33];
    int x0 = blockIdx.x*32, y0 = blockIdx.y*32;
    int tx = threadIdx.x, ty = threadIdx.y;
    #pragma unroll
    for (int j = 0; j < 32; j += 8)
        t[ty+j][tx] = W[(size_t)(y0+ty+j)*DMODEL + x0+tx];
    __syncthreads();
    #pragma unroll
    for (int j = 0; j < 32; j += 8)
        out[(size_t)(x0+ty+j)*DMODEL + y0+tx] = __float2half_rn(t[tx][ty+j]);
}

// ---------------- HMMA GEMM: C = (Ahi+Alo) @ Bh^T, fp16 x2, fp32 accum -----------
#define ROWB     80
#define TILEB    (128*ROWB)
#define STAGEB   (3*TILEB)
#define SMEMB    (2*STAGEB)

template<int MODE>
__global__ __launch_bounds__(256) void hgemm_tc(const __half* __restrict__ Ahi,
                                                const __half* __restrict__ Alo,
                                                const __half* __restrict__ Bh,
                                                const float* __restrict__ bias,
                                                float* __restrict__ OUT,
                                                __half* __restrict__ QH,
                                                __half* __restrict__ KH,
                                                __half* __restrict__ VH)
{
    extern __shared__ char smem[];
    const uint32_t smem_base = smem_u32(smem);
    const int tid  = threadIdx.x;
    const int lane = tid & 31;
    const int wid  = tid >> 5;
    const int wm   = wid & 3;
    const int wn   = wid >> 2;
    const int br   = blockIdx.y, bc = blockIdx.x;

    const int lrow  = tid >> 2;
    const int chunk = tid & 3;

    const __half* A0h = Ahi + (size_t)(br*128 + lrow)*DMODEL + chunk*8;
    const __half* A0l = Alo + (size_t)(br*128 + lrow)*DMODEL + chunk*8;
    const __half* B0  = Bh  + (size_t)(bc*128 + lrow)*DMODEL + chunk*8;
    const size_t rstep = (size_t)64*DMODEL;

#define ISSUE(s_, buf_) do { \
    uint32_t sb = smem_base + (buf_)*STAGEB; \
    uint32_t d0 = sb + lrow*ROWB + chunk*16; \
    size_t  go = (size_t)(s_)*32; \
    CP16(d0,           A0h + go); \
    CP16(d0 + TILEB,   A0l + go); \
    CP16(d0 + 2*TILEB, B0  + go); \
    uint32_t d1 = d0 + 64*ROWB; \
    CP16(d1,           A0h + go + rstep); \
    CP16(d1 + TILEB,   A0l + go + rstep); \
    CP16(d1 + 2*TILEB, B0  + go + rstep); \
} while (0)

    float acc[2][8][4];
    #pragma unroll
    for (int i = 0; i < 2; i++)
        #pragma unroll
        for (int j = 0; j < 8; j++)
            #pragma unroll
            for (int e = 0; e < 4; e++) acc[i][j][e] = 0.f;

    const int m0 = wm*32, n0 = wn*64;
    const int lr = lane & 15, lh = lane >> 4;

    ISSUE(0, 0); CP_COMMIT();

    for (int s = 0; s < 32; s++) {
        if (s + 1 < 32) { ISSUE(s + 1, (s + 1) & 1); CP_COMMIT(); CP_WAIT1(); }
        else            { CP_WAIT0(); }
        __syncthreads();

        const uint32_t As = smem_base + (s & 1)*STAGEB;
        const uint32_t Bs = As + 2*TILEB;
        #pragma unroll
        for (int k = 0; k < 2; k++) {
            const uint32_t koff = k*32 + lh*16;
            uint32_t ahi[2][4], alo[2][4], bq[4][4];
            #pragma unroll
            for (int mi = 0; mi < 2; mi++) {
                LDSM4(ahi[mi], As + (m0 + mi*16 + lr)*ROWB + koff);
                LDSM4(alo[mi], As + TILEB + (m0 + mi*16 + lr)*ROWB + koff);
            }
            #pragma unroll
            for (int jg = 0; jg < 4; jg++)
                LDSM4(bq[jg], Bs + (n0 + jg*16 + lr)*ROWB + koff);
            #pragma unroll
            for (int mi = 0; mi < 2; mi++)
                #pragma unroll
                for (int j = 0; j < 8; j++) {
                    mma_f16(acc[mi][j], ahi[mi], bq[j>>1][j&1], bq[j>>1][(j&1)+2]);
                    mma_f16(acc[mi][j], alo[mi], bq[j>>1][j&1], bq[j>>1][(j&1)+2]);
                }
        }
        __syncthreads();
    }
#undef ISSUE

    // epilogue
    const int g = lane >> 2, t = lane & 3;
    int colbase = bc*128;
    int mm = 0;
    if (MODE == 0) { mm = bc >> 3; colbase = (bc & 7)*128; }
    #pragma unroll
    for (int mi = 0; mi < 2; mi++) {
        #pragma unroll
        for (int rr = 0; rr < 2; rr++) {
            const int row = br*128 + m0 + mi*16 + rr*8 + g;
            #pragma unroll
            for (int j = 0; j < 8; j++) {
                const int col = colbase + n0 + j*8 + t*2;
                float vx = acc[mi][j][rr*2 + 0];
                float vy = acc[mi][j][rr*2 + 1];
                if (MODE == 1) {
                    float2 v; v.x = vx + bias[col]; v.y = vy + bias[col + 1];
                    *(float2*)&OUT[(size_t)row*DMODEL + col] = v;
                } else {
                    int bi = row >> 11, tt = row & 2047;
                    int h = col >> 6, dd = col & 63;
                    size_t o = (((size_t)(bi*NHEADS + h))*TSEQ + tt)*HDIM + dd;
                    __half* P = (mm == 0) ? QH : (mm == 1) ? KH : VH;
                    float sc = (mm == 0) ? SCALE_Q : 1.f;
                    *(uint32_t*)&P[o] = pack_h2(vx*sc, vy*sc);
                }
            }
        }
    }
}

// ---------------- HMMA flash attention -----------------------------------------
// S = Qh K^T (exp2 domain, both fp16 hi-only); O = Phi V; fp32 online softmax.
#define ROWF   144
#define FQH    0
#define FQTOT  (128*ROWF)        /* 18432 */
#define FKH    0
#define FVH    (64*ROWF)
#define FSTG   (2*64*ROWF)       /* 18432 */
#define FSMEM  (FQTOT + 2*FSTG)  /* 55296 */

__global__ __launch_bounds__(256, 2) void flash_hmma(
    const __half* __restrict__ qh,
    const __half* __restrict__ kh,  const __half* __restrict__ vh,
    __half* __restrict__ ohi, __half* __restrict__ olo)
{
    extern __shared__ char fsm[];
    const uint32_t sb = smem_u32(fsm);
    const int tid = threadIdx.x, lane = tid & 31, wid = tid >> 5;
    const int bh = blockIdx.y, q0 = blockIdx.x*128;
    const int g = lane >> 2, t = lane & 3, lr = lane & 15, lh = lane >> 4;
    const int wq = wid*16;

    const size_t base = (size_t)bh*TSEQ*HDIM;
    const __half* qp = qh + base + (size_t)q0*HDIM;
    const __half* kp = kh + base;
    const __half* vp = vh + base;

    {
        int r = tid >> 1, c4 = (tid & 1)*4;
        #pragma unroll
        for (int u = 0; u < 4; u++)
            CP16(sb + FQH + r*ROWF + (c4+u)*16, qp + (size_t)r*HDIM + (c4+u)*8);
        CP_COMMIT();
    }

#define FISSUE(kb_, b_) do { \
    int r = tid >> 2, c2 = (tid & 3)*2; \
    uint32_t s0 = sb + FQTOT + (b_)*FSTG; \
    size_t go = (size_t)((kb_)*64 + r)*HDIM; \
    _Pragma("unroll") \
    for (int u = 0; u < 2; u++) { \
        CP16(s0 + FKH + r*ROWF + (c2+u)*16, kp + go + (c2+u)*8); \
        CP16(s0 + FVH + r*ROWF + (c2+u)*16, vp + go + (c2+u)*8); \
    } \
} while (0)

    FISSUE(0, 0); CP_COMMIT();
    CP_WAIT0(); __syncthreads();

    float oacc[8][4];
    #pragma unroll
    for (int j = 0; j < 8; j++)
        #pragma unroll
        for (int e = 0; e < 4; e++) oacc[j][e] = 0.f;
    const float NEGINF = __int_as_float(0xff800000);
    float m0 = NEGINF, m1 = NEGINF, l0 = 0.f, l1 = 0.f;

    for (int kb = 0; kb < 32; kb++) {
        if (kb + 1 < 32) { FISSUE(kb + 1, (kb + 1) & 1); CP_COMMIT(); CP_WAIT1(); }
        else             { CP_WAIT0(); }
        __syncthreads();

        const uint32_t SB = sb + FQTOT + (kb & 1)*FSTG;

        // ---- S = Q K^T (1-term), exp2 domain ----
        float sacc[8][4];
        #pragma unroll
        for (int j = 0; j < 8; j++)
            #pragma unroll
            for (int e = 0; e < 4; e++) sacc[j][e] = 0.f;

        #pragma unroll
        for (int kk = 0; kk < 4; kk++) {
            const uint32_t ko = kk*32 + lh*16;
            uint32_t aq[4];
            LDSM4(aq, sb + FQH + (wq + lr)*ROWF + ko);
            #pragma unroll
            for (int jg = 0; jg < 4; jg++) {
                uint32_t bkh[4];
                LDSM4(bkh, SB + FKH + (jg*16 + lr)*ROWF + ko);
                #pragma unroll
                for (int j2 = 0; j2 < 2; j2++)
                    mma_f16(sacc[jg*2 + j2], aq, bkh[j2], bkh[j2+2]);
            }
        }

        // ---- online softmax (exp2 domain) ----
        float nm0 = NEGINF, nm1 = NEGINF;
        #pragma unroll
        for (int j = 0; j < 8; j++) {
            nm0 = fmaxf(nm0, fmaxf(sacc[j][0], sacc[j][1]));
            nm1 = fmaxf(nm1, fmaxf(sacc[j][2], sacc[j][3]));
        }
        nm0 = fmaxf(nm0, __shfl_xor_sync(0xffffffffu, nm0, 1));
        nm0 = fmaxf(nm0, __shfl_xor_sync(0xffffffffu, nm0, 2));
        nm1 = fmaxf(nm1, __shfl_xor_sync(0xffffffffu, nm1, 1));
        nm1 = fmaxf(nm1, __shfl_xor_sync(0xffffffffu, nm1, 2));
        float M0 = fmaxf(m0, nm0), M1 = fmaxf(m1, nm1);
        bool changed = (M0 != m0) || (M1 != m1);
        float c0 = ex2f(m0 - M0), c1 = ex2f(m1 - M1);
        m0 = M0; m1 = M1;
        float rs0 = 0.f, rs1 = 0.f;
        #pragma unroll
        for (int j = 0; j < 8; j++) {
            sacc[j][0] = ex2f(sacc[j][0] - M0);
            sacc[j][1] = ex2f(sacc[j][1] - M0);
            sacc[j][2] = ex2f(sacc[j][2] - M1);
            sacc[j][3] = ex2f(sacc[j][3] - M1);
            rs0 += sacc[j][0] + sacc[j][1];
            rs1 += sacc[j][2] + sacc[j][3];
        }
        rs0 += __shfl_xor_sync(0xffffffffu, rs0, 1);
        rs0 += __shfl_xor_sync(0xffffffffu, rs0, 2);
        rs1 += __shfl_xor_sync(0xffffffffu, rs1, 1);
        rs1 += __shfl_xor_sync(0xffffffffu, rs1, 2);
        l0 = l0*c0 + rs0;
        l1 = l1*c1 + rs1;
        if (__any_sync(0xffffffffu, changed)) {
            #pragma unroll
            for (int j = 0; j < 8; j++) {
                oacc[j][0] *= c0; oacc[j][1] *= c0;
                oacc[j][2] *= c1; oacc[j][3] *= c1;
            }
        }

        // ---- O += Phi V (1-term); P repacked hi-only from S fragments ----
        const int vrow0 = ((lane >> 3) & 1)*8 + (lane & 7);
        const int vcsub = (lane >> 4)*8;
        #pragma unroll
        for (int kk = 0; kk < 4; kk++) {
            uint32_t ah[4];
            ah[0] = pack_h2(sacc[2*kk][0],   sacc[2*kk][1]);
            ah[1] = pack_h2(sacc[2*kk][2],   sacc[2*kk][3]);
            ah[2] = pack_h2(sacc[2*kk+1][0], sacc[2*kk+1][1]);
            ah[3] = pack_h2(sacc[2*kk+1][2], sacc[2*kk+1][3]);
            const uint32_t vr = (kk*16 + vrow0)*ROWF;
            #pragma unroll
            for (int jj = 0; jj < 4; jj++) {
                uint32_t bvh[4];
                LDSM4T(bvh, SB + FVH + vr + (jj*16 + vcsub)*2);
                #pragma unroll
                for (int j2 = 0; j2 < 2; j2++)
                    mma_f16(oacc[jj*2 + j2], ah, bvh[2*j2], bvh[2*j2+1]);
            }
        }
        __syncthreads();
    }
#undef FISSUE

    const float inv0 = 1.f / l0, inv1 = 1.f / l1;
    const int b = bh >> 4, h = bh & 15;
    const int tok0 = b*TSEQ + q0 + wq + g;
    const int tok1 = tok0 + 8;
    #pragma unroll
    for (int j = 0; j < 8; j++) {
        const int col = h*64 + j*8 + t*2;
        uint32_t ph, pl;
        split_pack(oacc[j][0]*inv0, oacc[j][1]*inv0, ph, pl);
        *(uint32_t*)&ohi[(size_t)tok0*DMODEL + col] = ph;
        *(uint32_t*)&olo[(size_t)tok0*DMODEL + col] = pl;
        split_pack(oacc[j][2]*inv1, oacc[j][3]*inv1, ph, pl);
        *(uint32_t*)&ohi[(size_t)tok1*DMODEL + col] = ph;
        *(uint32_t*)&olo[(size_t)tok1*DMODEL + col] = pl;
    }
}

// ---------------- launch ----------------
extern "C" void kernel_launch(void* const* d_in, const int* in_sizes, int n_in,
                              void* d_out, int out_size)
{
    const float* x  = (const float*)d_in[0];
    const float* Wq = (const float*)d_in[1];
    const float* Wk = (const float*)d_in[2];
    const float* Wv = (const float*)d_in[3];
    const float* Wo = (const float*)d_in[4];
    const float* bo = (const float*)d_in[5];
    float* out = (float*)d_out;

    __half *xhi, *xlo, *wh, *ahi, *alo, *qh, *kh, *vh;
    cudaGetSymbolAddress((void**)&xhi, g_xhi);
    cudaGetSymbolAddress((void**)&xlo, g_xlo);
    cudaGetSymbolAddress((void**)&wh,  g_wh);
    cudaGetSymbolAddress((void**)&ahi, g_ahi);
    cudaGetSymbolAddress((void**)&alo, g_alo);
    cudaGetSymbolAddress((void**)&qh,  g_qh);
    cudaGetSymbolAddress((void**)&kh,  g_kh);
    cudaGetSymbolAddress((void**)&vh,  g_vh);

    const size_t WSZ = (size_t)DMODEL*DMODEL;

    invf_kernel<<<1, 32>>>();
    rope_kernel<<<TSEQ, HDIM>>>();
    split_kernel<<<(BT*DMODEL/4 + 255)/256, 256>>>(x, xhi, xlo, BT*DMODEL/4);
    gram1_kernel<<<64, 256>>>();
    gram2_kernel<<<HDIM, HDIM>>>();
    tsplit3_kernel<<<dim3(32, 32, 3), dim3(32, 8)>>>(Wq, Wk, Wo, wh);
    wvfold_kernel<<<dim3(32, 32), 256>>>(Wv, wh + 2*WSZ);

    cudaFuncSetAttribute(hgemm_tc<0>, cudaFuncAttributeMaxDynamicSharedMemorySize, SMEMB);
    cudaFuncSetAttribute(hgemm_tc<1>, cudaFuncAttributeMaxDynamicSharedMemorySize, SMEMB);
    cudaFuncSetAttribute(flash_hmma, cudaFuncAttributeMaxDynamicSharedMemorySize, FSMEM);

    // merged QKV projection: grid.x = 24 (3 matrices x 8 col-tiles)
    hgemm_tc<0><<<dim3(24, BT/128), 256, SMEMB>>>(xhi, xlo, wh, nullptr, nullptr,
                                                  qh, kh, vh);

    flash_hmma<<<dim3(TSEQ/128, BATCH*NHEADS), 256, FSMEM>>>(qh, kh, vh, ahi, alo);

    hgemm_tc<1><<<dim3(8, BT/128), 256, SMEMB>>>(ahi, alo, wh + 3*WSZ, bo, out,
                                                 nullptr, nullptr, nullptr);

    (void)in_sizes; (void)n_in; (void)out_size;
}